// round 1
// baseline (speedup 1.0000x reference)
#include <cuda_runtime.h>
#include <math.h>

#define B_    2
#define H_    256
#define W_    256
#define C_    192
#define L_    (H_*W_)         // 65536
#define M_    (B_*L_)         // 131072
#define HID_  768
#define NH    6
#define HD    32
#define WS    8
#define SHIFT 4
#define NWIN  (B_*(H_/WS)*(W_/WS))  // 2048
#define RED_  24

// ---------------- scratch (device globals; no allocations) ----------------
__device__ float g_xn [M_*C_];
__device__ float g_qkv[M_*3*C_];
__device__ float g_ao [M_*C_];
__device__ float g_x1 [M_*C_];
__device__ float g_x1n[M_*C_];
__device__ float g_hb [(size_t)M_*HID_];
__device__ float g_y1 [M_*RED_];
__device__ float g_y2 [M_*RED_];
__device__ float g_y  [M_*C_];
__device__ float g_pool[B_*C_];
__device__ float g_s  [B_*C_];

// ---------------- LayerNorm: one warp per token (C=192 = 32*6) -------------
__global__ __launch_bounds__(256) void ln_kernel(const float* __restrict__ x,
                                                 const float* __restrict__ g,
                                                 const float* __restrict__ b,
                                                 float* __restrict__ out) {
    int token = blockIdx.x * 8 + (threadIdx.x >> 5);
    int lane  = threadIdx.x & 31;
    const float* p = x + (size_t)token * C_;
    float v[6];
    float s = 0.f;
    #pragma unroll
    for (int j = 0; j < 6; j++) { v[j] = p[lane + 32*j]; s += v[j]; }
    #pragma unroll
    for (int o = 16; o > 0; o >>= 1) s += __shfl_xor_sync(0xffffffffu, s, o);
    float mean = s * (1.f / C_);
    float q = 0.f;
    #pragma unroll
    for (int j = 0; j < 6; j++) { float d = v[j] - mean; q += d * d; }
    #pragma unroll
    for (int o = 16; o > 0; o >>= 1) q += __shfl_xor_sync(0xffffffffu, q, o);
    float rstd = rsqrtf(q * (1.f / C_) + 1e-5f);
    float* po = out + (size_t)token * C_;
    #pragma unroll
    for (int j = 0; j < 6; j++) {
        int c = lane + 32*j;
        po[c] = (v[j] - mean) * rstd * g[c] + b[c];
    }
}

// ---------------- Generic GEMM: out = epi(A[M,K] @ W[N,K]^T + bias) --------
// EPI: 0 none, 1 +res, 2 exact GELU, 3 LeakyReLU(0.2)
template<int EPI>
__global__ __launch_bounds__(256) void gemm_kernel(const float* __restrict__ A,
                                                   const float* __restrict__ Wt,
                                                   const float* __restrict__ bias,
                                                   const float* __restrict__ res,
                                                   float* __restrict__ out,
                                                   int M, int N, int K) {
    __shared__ float As[8][132];
    __shared__ float Bs[8][68];
    int tid = threadIdx.x;
    int m0 = blockIdx.y * 128;
    int n0 = blockIdx.x * 64;
    int lm = tid >> 1;          // 0..127
    int lk = (tid & 1) * 4;     // 0 or 4
    int my = (tid >> 4) * 8;    // 0..120
    int nx = (tid & 15) * 4;    // 0..60
    float acc[8][4];
    #pragma unroll
    for (int i = 0; i < 8; i++)
        #pragma unroll
        for (int j = 0; j < 4; j++) acc[i][j] = 0.f;

    for (int k0 = 0; k0 < K; k0 += 8) {
        float4 av = *(const float4*)(A + (size_t)(m0 + lm) * K + k0 + lk);
        As[lk+0][lm] = av.x; As[lk+1][lm] = av.y;
        As[lk+2][lm] = av.z; As[lk+3][lm] = av.w;
        #pragma unroll
        for (int i = 0; i < 2; i++) {
            int e = tid + i * 256;
            int bk = e & 7, bn = e >> 3;
            float v = 0.f;
            if (n0 + bn < N) v = Wt[(size_t)(n0 + bn) * K + k0 + bk];
            Bs[bk][bn] = v;
        }
        __syncthreads();
        #pragma unroll
        for (int k = 0; k < 8; k++) {
            float4 a0 = *(const float4*)&As[k][my];
            float4 a1 = *(const float4*)&As[k][my + 4];
            float4 bv = *(const float4*)&Bs[k][nx];
            float a[8] = {a0.x, a0.y, a0.z, a0.w, a1.x, a1.y, a1.z, a1.w};
            float bb[4] = {bv.x, bv.y, bv.z, bv.w};
            #pragma unroll
            for (int i = 0; i < 8; i++)
                #pragma unroll
                for (int j = 0; j < 4; j++) acc[i][j] += a[i] * bb[j];
        }
        __syncthreads();
    }
    #pragma unroll
    for (int i = 0; i < 8; i++) {
        int m = m0 + my + i;
        #pragma unroll
        for (int j = 0; j < 4; j++) {
            int n = n0 + nx + j;
            if (n < N) {
                float c = acc[i][j] + bias[n];
                if (EPI == 1) c += res[(size_t)m * N + n];
                if (EPI == 2) c = 0.5f * c * (1.f + erff(c * 0.70710678118654752f));
                if (EPI == 3) c = (c >= 0.f) ? c : 0.2f * c;
                out[(size_t)m * N + n] = c;
            }
        }
    }
}

// ---------------- Windowed attention, one block per window ----------------
__global__ __launch_bounds__(256) void attn_kernel(const float* __restrict__ qkv,
                                                   const float* __restrict__ rpb,
                                                   float* __restrict__ ao) {
    __shared__ int   gidx[64];
    __shared__ int   rid [64];
    __shared__ float qs[64][33];
    __shared__ float ks[64][33];
    __shared__ float vs[64][36];
    __shared__ float Sm[64][65];

    int tid = threadIdx.x;
    int wid = blockIdx.x;
    int b   = wid >> 10;            // 1024 windows per batch
    int wib = wid & 1023;
    int wh  = wib >> 5;
    int ww  = wib & 31;

    if (tid < 64) {
        int ih = tid >> 3, iw = tid & 7;
        int h = wh * 8 + ih, w = ww * 8 + iw;
        int hs = (h + SHIFT) & (H_ - 1);
        int ws2 = (w + SHIFT) & (W_ - 1);
        gidx[tid] = b * L_ + hs * W_ + ws2;
        int rh = (h < H_ - WS) ? 0 : ((h < H_ - SHIFT) ? 1 : 2);
        int rw = (w < W_ - WS) ? 0 : ((w < W_ - SHIFT) ? 1 : 2);
        rid[tid] = rh * 3 + rw;
    }
    __syncthreads();

    const float SCALE = 0.17677669529663687f;  // 1/sqrt(32)
    int i  = tid >> 2;              // score row
    int jb = (tid & 3) * 16;        // score col base
    int ihi = i >> 3, iwi = i & 7;
    int r_out = tid >> 2;           // out row
    int db    = (tid & 3) * 8;      // out d base

    for (int h = 0; h < NH; h++) {
        // load q,k,v for this head (gathered)
        for (int e = tid; e < 6144; e += 256) {
            int mat = e >> 11;           // 0:q 1:k 2:v
            int rem = e & 2047;
            int t = rem >> 5, d = rem & 31;
            float v = qkv[(size_t)gidx[t] * (3*C_) + mat * C_ + h * HD + d];
            if (mat == 0)      qs[t][d] = v * SCALE;
            else if (mat == 1) ks[t][d] = v;
            else               vs[t][d] = v;
        }
        __syncthreads();

        // scores + bias + mask (each thread: row i, 16 cols)
        float qrow[32];
        #pragma unroll
        for (int kk = 0; kk < 32; kk++) qrow[kk] = qs[i][kk];
        int ridi = rid[i];
        float ex[16];
        float mx = -1e30f;
        #pragma unroll
        for (int jj = 0; jj < 16; jj++) {
            int j = jb + jj;
            float s = 0.f;
            #pragma unroll
            for (int kk = 0; kk < 32; kk++) s += qrow[kk] * ks[j][kk];
            int jh = j >> 3, jw = j & 7;
            int rel = (ihi - jh + 7) * 15 + (iwi - jw + 7);
            s += rpb[rel * NH + h];
            if (ridi != rid[j]) s -= 100.f;
            ex[jj] = s;
            mx = fmaxf(mx, s);
        }
        // quad reduction (4 threads per row)
        mx = fmaxf(mx, __shfl_xor_sync(0xffffffffu, mx, 1));
        mx = fmaxf(mx, __shfl_xor_sync(0xffffffffu, mx, 2));
        float sum = 0.f;
        #pragma unroll
        for (int jj = 0; jj < 16; jj++) { ex[jj] = expf(ex[jj] - mx); sum += ex[jj]; }
        sum += __shfl_xor_sync(0xffffffffu, sum, 1);
        sum += __shfl_xor_sync(0xffffffffu, sum, 2);
        float inv = 1.f / sum;
        #pragma unroll
        for (int jj = 0; jj < 16; jj++) Sm[i][jb + jj] = ex[jj] * inv;
        __syncthreads();

        // out = S @ V : thread handles (r_out, d in [db, db+8))
        float oacc[8];
        #pragma unroll
        for (int d = 0; d < 8; d++) oacc[d] = 0.f;
        for (int m = 0; m < 64; m++) {
            float sv = Sm[r_out][m];
            float4 v0 = *(const float4*)&vs[m][db];
            float4 v1 = *(const float4*)&vs[m][db + 4];
            oacc[0] += sv * v0.x; oacc[1] += sv * v0.y;
            oacc[2] += sv * v0.z; oacc[3] += sv * v0.w;
            oacc[4] += sv * v1.x; oacc[5] += sv * v1.y;
            oacc[6] += sv * v1.z; oacc[7] += sv * v1.w;
        }
        float* po = ao + (size_t)gidx[r_out] * C_ + h * HD + db;
        #pragma unroll
        for (int d = 0; d < 8; d++) po[d] = oacc[d];
        __syncthreads();
    }
}

// ---------------- 3x3 conv on r=24 channels, NHWC, pad 1 -------------------
__global__ __launch_bounds__(64) void conv3_kernel(const float* __restrict__ yin,
                                                   const float* __restrict__ w,
                                                   const float* __restrict__ bias,
                                                   float* __restrict__ yout) {
    __shared__ float patch[100][RED_];       // 10x10 spatial x 24 ch
    __shared__ float wts[RED_ * RED_ * 9];   // [ic*9+kk][oc]
    int tid = threadIdx.x;
    int b = blockIdx.z;
    int th0 = blockIdx.y * 8, tw0 = blockIdx.x * 8;

    for (int d = tid; d < RED_ * RED_ * 9; d += 64) {
        int oc = d % RED_;
        int t2 = d / RED_;
        int kk = t2 % 9;
        int ic = t2 / 9;
        wts[d] = w[(oc * RED_ + ic) * 9 + kk];
    }
    for (int d = tid; d < 100 * RED_; d += 64) {
        int ic = d % RED_;
        int pos = d / RED_;
        int ph = pos / 10, pw = pos % 10;
        int hh = th0 + ph - 1, ww = tw0 + pw - 1;
        float v = 0.f;
        if (hh >= 0 && hh < H_ && ww >= 0 && ww < W_)
            v = yin[((size_t)b * L_ + hh * W_ + ww) * RED_ + ic];
        patch[pos][ic] = v;
    }
    __syncthreads();

    int py = tid >> 3, px = tid & 7;
    float acc[RED_];
    #pragma unroll
    for (int oc = 0; oc < RED_; oc++) acc[oc] = __ldg(bias + oc);
    for (int ic = 0; ic < RED_; ic++) {
        #pragma unroll
        for (int kk = 0; kk < 9; kk++) {
            int kh = kk / 3, kw = kk % 3;
            float pv = patch[(py + kh) * 10 + (px + kw)][ic];
            const float4* wp = (const float4*)&wts[(ic * 9 + kk) * RED_];
            #pragma unroll
            for (int o4 = 0; o4 < 6; o4++) {
                float4 wv = wp[o4];
                acc[o4*4+0] += wv.x * pv; acc[o4*4+1] += wv.y * pv;
                acc[o4*4+2] += wv.z * pv; acc[o4*4+3] += wv.w * pv;
            }
        }
    }
    float* po = yout + ((size_t)b * L_ + (th0 + py) * W_ + (tw0 + px)) * RED_;
    #pragma unroll
    for (int oc = 0; oc < RED_; oc++) po[oc] = acc[oc];
}

// ---------------- pool / SE / final ---------------------------------------
__global__ void zero_pool_kernel(float* pool) {
    if (threadIdx.x < B_ * C_) pool[threadIdx.x] = 0.f;
}

__global__ __launch_bounds__(192) void pool_kernel(const float* __restrict__ y,
                                                   float* __restrict__ pool) {
    int base = blockIdx.x * 128;          // 128 tokens per block
    int b = base >> 16;                   // 65536 tokens per batch
    int c = threadIdx.x;
    float acc = 0.f;
    for (int i = 0; i < 128; i++)
        acc += y[(size_t)(base + i) * C_ + c];
    atomicAdd(&pool[b * C_ + c], acc);
}

__global__ __launch_bounds__(192) void se_kernel(const float* __restrict__ pool,
                                                 const float* __restrict__ fc1,
                                                 const float* __restrict__ fc2,
                                                 float* __restrict__ sbuf) {
    __shared__ float t[RED_];
    int tid = threadIdx.x;
    const float inv = 1.f / (float)L_;
    for (int b = 0; b < B_; b++) {
        if (tid < RED_) {
            float s = 0.f;
            for (int c = 0; c < C_; c++)
                s += pool[b * C_ + c] * inv * fc1[tid * C_ + c];
            t[tid] = fmaxf(s, 0.f);
        }
        __syncthreads();
        float s = 0.f;
        #pragma unroll
        for (int j = 0; j < RED_; j++) s += t[j] * fc2[tid * RED_ + j];
        sbuf[b * C_ + tid] = 1.f / (1.f + expf(-s));
        __syncthreads();
    }
}

__global__ __launch_bounds__(256) void final_kernel(const float* __restrict__ y,
                                                    const float* __restrict__ sbuf,
                                                    float* __restrict__ out) {
    size_t i = (size_t)blockIdx.x * 256 + threadIdx.x;
    if (i >= (size_t)M_ * C_) return;
    int c = (int)(i % C_);
    int b = (int)(i / ((size_t)L_ * C_));
    out[i] += y[i] * sbuf[b * C_ + c];
}

// ---------------- launch ---------------------------------------------------
extern "C" void kernel_launch(void* const* d_in, const int* in_sizes, int n_in,
                              void* d_out, int out_size) {
    const float* x      = (const float*)d_in[0];
    const float* n1g    = (const float*)d_in[1];
    const float* n1b    = (const float*)d_in[2];
    const float* qkvw   = (const float*)d_in[3];
    const float* qkvb   = (const float*)d_in[4];
    const float* rpb    = (const float*)d_in[5];
    const float* projw  = (const float*)d_in[6];
    const float* projb  = (const float*)d_in[7];
    const float* n2g    = (const float*)d_in[8];
    const float* n2b    = (const float*)d_in[9];
    const float* fc1w   = (const float*)d_in[10];
    const float* fc1b   = (const float*)d_in[11];
    const float* fc2w   = (const float*)d_in[12];
    const float* fc2b   = (const float*)d_in[13];
    const float* c1w    = (const float*)d_in[14];
    const float* c1b    = (const float*)d_in[15];
    const float* c2w    = (const float*)d_in[16];
    const float* c2b    = (const float*)d_in[17];
    const float* c3w    = (const float*)d_in[18];
    const float* c3b    = (const float*)d_in[19];
    const float* sfc1   = (const float*)d_in[20];
    const float* sfc2   = (const float*)d_in[21];
    float* out = (float*)d_out;

    float *xn, *qkv, *ao, *x1, *x1n, *hb, *y1, *y2, *y, *pool, *sbuf;
    cudaGetSymbolAddress((void**)&xn,   g_xn);
    cudaGetSymbolAddress((void**)&qkv,  g_qkv);
    cudaGetSymbolAddress((void**)&ao,   g_ao);
    cudaGetSymbolAddress((void**)&x1,   g_x1);
    cudaGetSymbolAddress((void**)&x1n,  g_x1n);
    cudaGetSymbolAddress((void**)&hb,   g_hb);
    cudaGetSymbolAddress((void**)&y1,   g_y1);
    cudaGetSymbolAddress((void**)&y2,   g_y2);
    cudaGetSymbolAddress((void**)&y,    g_y);
    cudaGetSymbolAddress((void**)&pool, g_pool);
    cudaGetSymbolAddress((void**)&sbuf, g_s);

    // 1) LN1
    ln_kernel<<<M_/8, 256>>>(x, n1g, n1b, xn);
    // 2) QKV GEMM (131072 x 576 x 192)
    gemm_kernel<0><<<dim3(9, M_/128), 256>>>(xn, qkvw, qkvb, nullptr, qkv, M_, 3*C_, C_);
    // 3) attention (gathered shifted windows; output scattered back)
    attn_kernel<<<NWIN, 256>>>(qkv, rpb, ao);
    // 4) proj + residual -> x1
    gemm_kernel<1><<<dim3(3, M_/128), 256>>>(ao, projw, projb, x, x1, M_, C_, C_);
    // 5) LN2
    ln_kernel<<<M_/8, 256>>>(x1, n2g, n2b, x1n);
    // 6) fc1 + GELU
    gemm_kernel<2><<<dim3(12, M_/128), 256>>>(x1n, fc1w, fc1b, nullptr, hb, M_, HID_, C_);
    // 7) fc2 + residual -> out (x2)
    gemm_kernel<1><<<dim3(3, M_/128), 256>>>(hb, fc2w, fc2b, x1, out, M_, C_, HID_);
    // 8) LCE conv1x1 C->24
    gemm_kernel<0><<<dim3(1, M_/128), 256>>>(xn, c1w, c1b, nullptr, y1, M_, RED_, C_);
    // 9) LCE conv3x3 24->24
    conv3_kernel<<<dim3(W_/8, H_/8, B_), 64>>>(y1, c2w, c2b, y2);
    // 10) LCE conv1x1 24->192 + LeakyReLU -> y
    gemm_kernel<3><<<dim3(3, M_/128), 256>>>(y2, c3w, c3b, nullptr, y, M_, C_, RED_);
    // 11) global avg pool
    zero_pool_kernel<<<1, 384>>>(pool);
    pool_kernel<<<M_/128, 192>>>(y, pool);
    // 12) SE gate
    se_kernel<<<1, 192>>>(pool, sfc1, sfc2, sbuf);
    // 13) out += y * s
    final_kernel<<<(M_*C_ + 255)/256, 256>>>(y, sbuf, out);
}

// round 6
// speedup vs baseline: 2.3186x; 2.3186x over previous
#include <cuda_runtime.h>
#include <cuda_bf16.h>
#include <math.h>
#include <stdint.h>

#define B_    2
#define H_    256
#define W_    256
#define C_    192
#define L_    (H_*W_)         // 65536
#define M_    (B_*L_)         // 131072
#define HID_  768
#define NH    6
#define HD    32
#define WS    8
#define SHIFT 4
#define NWIN  (B_*(H_/WS)*(W_/WS))  // 2048
#define RED_  24

// ---------------- scratch (device globals; no allocations) ----------------
__device__ float g_xn [M_*C_];
__device__ float g_qkv[M_*3*C_];
__device__ float g_ao [M_*C_];
__device__ float g_x1 [M_*C_];
__device__ float g_x1n[M_*C_];
__device__ float g_hb [(size_t)M_*HID_];
__device__ float g_y1 [M_*RED_];
__device__ float g_y2 [M_*RED_];
__device__ float g_y  [M_*C_];
__device__ float g_pool[B_*C_];
__device__ float g_s  [B_*C_];

// ======================= helpers ===========================================
__device__ __forceinline__ uint32_t smem_to_u32(const void* p) {
    uint32_t a;
    asm("{ .reg .u64 t; cvta.to.shared.u64 t, %1; cvt.u32.u64 %0, t; }" : "=r"(a) : "l"(p));
    return a;
}
__device__ __forceinline__ void split2(float x, float y, uint32_t& hi, uint32_t& lo) {
    __nv_bfloat16 hx = __float2bfloat16(x), hy = __float2bfloat16(y);
    __nv_bfloat16 lx = __float2bfloat16(x - __bfloat162float(hx));
    __nv_bfloat16 ly = __float2bfloat16(y - __bfloat162float(hy));
    hi = ((uint32_t)__bfloat16_as_ushort(hy) << 16) | __bfloat16_as_ushort(hx);
    lo = ((uint32_t)__bfloat16_as_ushort(ly) << 16) | __bfloat16_as_ushort(lx);
}
#define LDSM4(r, addr) \
    asm volatile("ldmatrix.sync.aligned.m8n8.x4.shared.b16 {%0,%1,%2,%3}, [%4];" \
        : "=r"((r)[0]), "=r"((r)[1]), "=r"((r)[2]), "=r"((r)[3]) : "r"(addr))
#define MMA_BF16(d, a, b0, b1) \
    asm volatile("mma.sync.aligned.m16n8k16.row.col.f32.bf16.bf16.f32 " \
        "{%0,%1,%2,%3},{%4,%5,%6,%7},{%8,%9},{%0,%1,%2,%3};" \
        : "+f"((d)[0]), "+f"((d)[1]), "+f"((d)[2]), "+f"((d)[3]) \
        : "r"((a)[0]), "r"((a)[1]), "r"((a)[2]), "r"((a)[3]), "r"(b0), "r"(b1))

// ======================= bf16x3 mma.sync GEMM ==============================
// out[M,N] = epi(A[M,K] @ Wt[N,K]^T + bias), fp32 in/out.
// CTA tile 128x64, BK=32, double-buffered smem (80B row stride, conflict-free
// ldmatrix). bf16x3: Ahi*Bhi + Alo*Bhi + Ahi*Blo, fp32 accumulate.
// EPI: 0 none, 1 +res, 2 exact GELU, 3 LeakyReLU(0.2)
#define STG_STRIDE 30720
#define A_HI 0
#define A_LO 10240
#define B_HI 20480
#define B_LO 25600
#define GEMM_SMEM_SZ (2*STG_STRIDE)   // 61440

template<int EPI>
__global__ __launch_bounds__(256, 2) void gemm_mma(const float* __restrict__ A,
                                                   const float* __restrict__ Wt,
                                                   const float* __restrict__ bias,
                                                   const float* __restrict__ res,
                                                   float* __restrict__ out,
                                                   int N, int K) {
    extern __shared__ char smem[];
    const int tid  = threadIdx.x;
    const int lane = tid & 31;
    const int warp = tid >> 5;
    const int m0 = blockIdx.y * 128, n0 = blockIdx.x * 64;
    const int wm = (warp & 3) * 32, wn = (warp >> 2) * 32;

    float acc[2][4][4];
    #pragma unroll
    for (int i = 0; i < 2; i++)
        #pragma unroll
        for (int j = 0; j < 4; j++)
            #pragma unroll
            for (int q = 0; q < 4; q++) acc[i][j][q] = 0.f;

    const int arow = tid >> 1, akb = (tid & 1) * 16;   // 2 thr/row, 16 k each
    const int brow = tid >> 2, bkb = (tid & 3) * 8;    // 4 thr/row, 8 k each
    const float* aptr = A + (size_t)(m0 + arow) * K;
    const bool bvalid = (n0 + brow) < N;
    const float* bptr = Wt + (size_t)(n0 + brow) * K;

    const int nch = (K + 31) >> 5;
    float a_f[16], b_f[8];

#define FETCH(c) do { \
    int k0_ = (c) * 32; \
    _Pragma("unroll") \
    for (int i = 0; i < 4; i++) { \
        int kg = k0_ + akb + i * 4; \
        float4 v = make_float4(0.f, 0.f, 0.f, 0.f); \
        if (kg < K) v = *(const float4*)(aptr + kg); \
        a_f[i*4+0] = v.x; a_f[i*4+1] = v.y; a_f[i*4+2] = v.z; a_f[i*4+3] = v.w; \
    } \
    _Pragma("unroll") \
    for (int i = 0; i < 2; i++) { \
        int kg = k0_ + bkb + i * 4; \
        float4 v = make_float4(0.f, 0.f, 0.f, 0.f); \
        if (bvalid && kg < K) v = *(const float4*)(bptr + kg); \
        b_f[i*4+0] = v.x; b_f[i*4+1] = v.y; b_f[i*4+2] = v.z; b_f[i*4+3] = v.w; \
    } } while (0)

#define STORE(s) do { \
    char* base_ = smem + (s) * STG_STRIDE; \
    _Pragma("unroll") \
    for (int i = 0; i < 8; i++) { \
        uint32_t hi_, lo_; \
        split2(a_f[2*i], a_f[2*i+1], hi_, lo_); \
        int off = arow * 80 + (akb + 2*i) * 2; \
        *(uint32_t*)(base_ + A_HI + off) = hi_; \
        *(uint32_t*)(base_ + A_LO + off) = lo_; \
    } \
    _Pragma("unroll") \
    for (int i = 0; i < 4; i++) { \
        uint32_t hi_, lo_; \
        split2(b_f[2*i], b_f[2*i+1], hi_, lo_); \
        int off = brow * 80 + (bkb + 2*i) * 2; \
        *(uint32_t*)(base_ + B_HI + off) = hi_; \
        *(uint32_t*)(base_ + B_LO + off) = lo_; \
    } } while (0)

    FETCH(0);
    STORE(0);
    __syncthreads();

    for (int c = 0; c < nch; c++) {
        if (c + 1 < nch) FETCH(c + 1);
        {   // compute stage c&1
            char* base = smem + (c & 1) * STG_STRIDE;
            #pragma unroll
            for (int ks = 0; ks < 2; ks++) {
                uint32_t ahi[2][4], alo[2][4], bhi[2][4], blo[2][4];
                #pragma unroll
                for (int mt = 0; mt < 2; mt++) {
                    int row = wm + mt * 16 + (lane & 15);
                    int colb = ks * 32 + ((lane >> 4) & 1) * 16;
                    uint32_t ad = smem_to_u32(base + A_HI + row * 80 + colb);
                    LDSM4(ahi[mt], ad);
                    LDSM4(alo[mt], ad + (A_LO - A_HI));
                }
                #pragma unroll
                for (int np = 0; np < 2; np++) {
                    int n = wn + np * 16 + (lane & 7) + ((lane >> 4) & 1) * 8;
                    int colb = ks * 32 + ((lane >> 3) & 1) * 16;
                    uint32_t bd = smem_to_u32(base + B_HI + n * 80 + colb);
                    LDSM4(bhi[np], bd);
                    LDSM4(blo[np], bd + (B_LO - B_HI));
                }
                #pragma unroll
                for (int mt = 0; mt < 2; mt++)
                    #pragma unroll
                    for (int nt = 0; nt < 4; nt++) {
                        int np = nt >> 1, h = (nt & 1) * 2;
                        MMA_BF16(acc[mt][nt], ahi[mt], bhi[np][h], bhi[np][h+1]);
                        MMA_BF16(acc[mt][nt], alo[mt], bhi[np][h], bhi[np][h+1]);
                        MMA_BF16(acc[mt][nt], ahi[mt], blo[np][h], blo[np][h+1]);
                    }
            }
        }
        __syncthreads();
        if (c + 1 < nch) {
            STORE((c + 1) & 1);
            __syncthreads();
        }
    }

    // ---- epilogue: registers -> global (float2 per row-pair) ----
    #pragma unroll
    for (int mt = 0; mt < 2; mt++) {
        int r0 = m0 + wm + mt * 16 + (lane >> 2);
        #pragma unroll
        for (int nt = 0; nt < 4; nt++) {
            int col = n0 + wn + nt * 8 + (lane & 3) * 2;
            if (col < N) {
                float b0v = bias[col], b1v = bias[col + 1];
                #pragma unroll
                for (int rr = 0; rr < 2; rr++) {
                    int r = r0 + rr * 8;
                    float v0 = acc[mt][nt][rr*2+0] + b0v;
                    float v1 = acc[mt][nt][rr*2+1] + b1v;
                    if (EPI == 1) {
                        float2 rv = *(const float2*)(res + (size_t)r * N + col);
                        v0 += rv.x; v1 += rv.y;
                    }
                    if (EPI == 2) {
                        v0 = 0.5f * v0 * (1.f + erff(v0 * 0.70710678118654752f));
                        v1 = 0.5f * v1 * (1.f + erff(v1 * 0.70710678118654752f));
                    }
                    if (EPI == 3) {
                        v0 = (v0 >= 0.f) ? v0 : 0.2f * v0;
                        v1 = (v1 >= 0.f) ? v1 : 0.2f * v1;
                    }
                    *(float2*)(out + (size_t)r * N + col) = make_float2(v0, v1);
                }
            }
        }
    }
#undef FETCH
#undef STORE
}

// ---------------- LayerNorm: one warp per token (C=192 = 32*6) -------------
__global__ __launch_bounds__(256) void ln_kernel(const float* __restrict__ x,
                                                 const float* __restrict__ g,
                                                 const float* __restrict__ b,
                                                 float* __restrict__ out) {
    int token = blockIdx.x * 8 + (threadIdx.x >> 5);
    int lane  = threadIdx.x & 31;
    const float* p = x + (size_t)token * C_;
    float v[6];
    float s = 0.f;
    #pragma unroll
    for (int j = 0; j < 6; j++) { v[j] = p[lane + 32*j]; s += v[j]; }
    #pragma unroll
    for (int o = 16; o > 0; o >>= 1) s += __shfl_xor_sync(0xffffffffu, s, o);
    float mean = s * (1.f / C_);
    float q = 0.f;
    #pragma unroll
    for (int j = 0; j < 6; j++) { float d = v[j] - mean; q += d * d; }
    #pragma unroll
    for (int o = 16; o > 0; o >>= 1) q += __shfl_xor_sync(0xffffffffu, q, o);
    float rstd = rsqrtf(q * (1.f / C_) + 1e-5f);
    float* po = out + (size_t)token * C_;
    #pragma unroll
    for (int j = 0; j < 6; j++) {
        int c = lane + 32*j;
        po[c] = (v[j] - mean) * rstd * g[c] + b[c];
    }
}

// ---------------- Windowed attention, one block per window ----------------
__global__ __launch_bounds__(256) void attn_kernel(const float* __restrict__ qkv,
                                                   const float* __restrict__ rpb,
                                                   float* __restrict__ ao) {
    __shared__ int   gidx[64];
    __shared__ int   rid [64];
    __shared__ float qs[64][33];
    __shared__ float ks[64][33];
    __shared__ float vs[64][36];
    __shared__ float Sm[64][65];

    int tid = threadIdx.x;
    int wid = blockIdx.x;
    int b   = wid >> 10;
    int wib = wid & 1023;
    int wh  = wib >> 5;
    int ww  = wib & 31;

    if (tid < 64) {
        int ih = tid >> 3, iw = tid & 7;
        int h = wh * 8 + ih, w = ww * 8 + iw;
        int hs = (h + SHIFT) & (H_ - 1);
        int ws2 = (w + SHIFT) & (W_ - 1);
        gidx[tid] = b * L_ + hs * W_ + ws2;
        int rh = (h < H_ - WS) ? 0 : ((h < H_ - SHIFT) ? 1 : 2);
        int rw = (w < W_ - WS) ? 0 : ((w < W_ - SHIFT) ? 1 : 2);
        rid[tid] = rh * 3 + rw;
    }
    __syncthreads();

    const float SCALE = 0.17677669529663687f;
    int i  = tid >> 2;
    int jb = (tid & 3) * 16;
    int ihi = i >> 3, iwi = i & 7;
    int r_out = tid >> 2;
    int db    = (tid & 3) * 8;

    for (int h = 0; h < NH; h++) {
        for (int e = tid; e < 6144; e += 256) {
            int mat = e >> 11;
            int rem = e & 2047;
            int t = rem >> 5, d = rem & 31;
            float v = qkv[(size_t)gidx[t] * (3*C_) + mat * C_ + h * HD + d];
            if (mat == 0)      qs[t][d] = v * SCALE;
            else if (mat == 1) ks[t][d] = v;
            else               vs[t][d] = v;
        }
        __syncthreads();

        float qrow[32];
        #pragma unroll
        for (int kk = 0; kk < 32; kk++) qrow[kk] = qs[i][kk];
        int ridi = rid[i];
        float ex[16];
        float mx = -1e30f;
        #pragma unroll
        for (int jj = 0; jj < 16; jj++) {
            int j = jb + jj;
            float s = 0.f;
            #pragma unroll
            for (int kk = 0; kk < 32; kk++) s += qrow[kk] * ks[j][kk];
            int jh = j >> 3, jw = j & 7;
            int rel = (ihi - jh + 7) * 15 + (iwi - jw + 7);
            s += rpb[rel * NH + h];
            if (ridi != rid[j]) s -= 100.f;
            ex[jj] = s;
            mx = fmaxf(mx, s);
        }
        mx = fmaxf(mx, __shfl_xor_sync(0xffffffffu, mx, 1));
        mx = fmaxf(mx, __shfl_xor_sync(0xffffffffu, mx, 2));
        float sum = 0.f;
        #pragma unroll
        for (int jj = 0; jj < 16; jj++) { ex[jj] = expf(ex[jj] - mx); sum += ex[jj]; }
        sum += __shfl_xor_sync(0xffffffffu, sum, 1);
        sum += __shfl_xor_sync(0xffffffffu, sum, 2);
        float inv = 1.f / sum;
        #pragma unroll
        for (int jj = 0; jj < 16; jj++) Sm[i][jb + jj] = ex[jj] * inv;
        __syncthreads();

        float oacc[8];
        #pragma unroll
        for (int d = 0; d < 8; d++) oacc[d] = 0.f;
        for (int m = 0; m < 64; m++) {
            float sv = Sm[r_out][m];
            float4 v0 = *(const float4*)&vs[m][db];
            float4 v1 = *(const float4*)&vs[m][db + 4];
            oacc[0] += sv * v0.x; oacc[1] += sv * v0.y;
            oacc[2] += sv * v0.z; oacc[3] += sv * v0.w;
            oacc[4] += sv * v1.x; oacc[5] += sv * v1.y;
            oacc[6] += sv * v1.z; oacc[7] += sv * v1.w;
        }
        float* po = ao + (size_t)gidx[r_out] * C_ + h * HD + db;
        #pragma unroll
        for (int d = 0; d < 8; d++) po[d] = oacc[d];
        __syncthreads();
    }
}

// ---------------- 3x3 conv on r=24 channels, NHWC, pad 1 -------------------
__global__ __launch_bounds__(64) void conv3_kernel(const float* __restrict__ yin,
                                                   const float* __restrict__ w,
                                                   const float* __restrict__ bias,
                                                   float* __restrict__ yout) {
    __shared__ float patch[100][RED_];
    __shared__ float wts[RED_ * RED_ * 9];
    int tid = threadIdx.x;
    int b = blockIdx.z;
    int th0 = blockIdx.y * 8, tw0 = blockIdx.x * 8;

    for (int d = tid; d < RED_ * RED_ * 9; d += 64) {
        int oc = d % RED_;
        int t2 = d / RED_;
        int kk = t2 % 9;
        int ic = t2 / 9;
        wts[d] = w[(oc * RED_ + ic) * 9 + kk];
    }
    for (int d = tid; d < 100 * RED_; d += 64) {
        int ic = d % RED_;
        int pos = d / RED_;
        int ph = pos / 10, pw = pos % 10;
        int hh = th0 + ph - 1, ww = tw0 + pw - 1;
        float v = 0.f;
        if (hh >= 0 && hh < H_ && ww >= 0 && ww < W_)
            v = yin[((size_t)b * L_ + hh * W_ + ww) * RED_ + ic];
        patch[pos][ic] = v;
    }
    __syncthreads();

    int py = tid >> 3, px = tid & 7;
    float acc[RED_];
    #pragma unroll
    for (int oc = 0; oc < RED_; oc++) acc[oc] = __ldg(bias + oc);
    for (int ic = 0; ic < RED_; ic++) {
        #pragma unroll
        for (int kk = 0; kk < 9; kk++) {
            int kh = kk / 3, kw = kk % 3;
            float pv = patch[(py + kh) * 10 + (px + kw)][ic];
            const float4* wp = (const float4*)&wts[(ic * 9 + kk) * RED_];
            #pragma unroll
            for (int o4 = 0; o4 < 6; o4++) {
                float4 wv = wp[o4];
                acc[o4*4+0] += wv.x * pv; acc[o4*4+1] += wv.y * pv;
                acc[o4*4+2] += wv.z * pv; acc[o4*4+3] += wv.w * pv;
            }
        }
    }
    float* po = yout + ((size_t)b * L_ + (th0 + py) * W_ + (tw0 + px)) * RED_;
    #pragma unroll
    for (int oc = 0; oc < RED_; oc++) po[oc] = acc[oc];
}

// ---------------- pool / SE / final ---------------------------------------
__global__ void zero_pool_kernel(float* pool) {
    if (threadIdx.x < B_ * C_) pool[threadIdx.x] = 0.f;
}

__global__ __launch_bounds__(192) void pool_kernel(const float* __restrict__ y,
                                                   float* __restrict__ pool) {
    int base = blockIdx.x * 128;
    int b = base >> 16;
    int c = threadIdx.x;
    float acc = 0.f;
    for (int i = 0; i < 128; i++)
        acc += y[(size_t)(base + i) * C_ + c];
    atomicAdd(&pool[b * C_ + c], acc);
}

__global__ __launch_bounds__(192) void se_kernel(const float* __restrict__ pool,
                                                 const float* __restrict__ fc1,
                                                 const float* __restrict__ fc2,
                                                 float* __restrict__ sbuf) {
    __shared__ float t[RED_];
    int tid = threadIdx.x;
    const float inv = 1.f / (float)L_;
    for (int b = 0; b < B_; b++) {
        if (tid < RED_) {
            float s = 0.f;
            for (int c = 0; c < C_; c++)
                s += pool[b * C_ + c] * inv * fc1[tid * C_ + c];
            t[tid] = fmaxf(s, 0.f);
        }
        __syncthreads();
        float s = 0.f;
        #pragma unroll
        for (int j = 0; j < RED_; j++) s += t[j] * fc2[tid * RED_ + j];
        sbuf[b * C_ + tid] = 1.f / (1.f + expf(-s));
        __syncthreads();
    }
}

__global__ __launch_bounds__(256) void final_kernel(const float* __restrict__ y,
                                                    const float* __restrict__ sbuf,
                                                    float* __restrict__ out) {
    size_t i = (size_t)blockIdx.x * 256 + threadIdx.x;
    if (i >= (size_t)M_ * C_) return;
    int c = (int)(i % C_);
    int b = (int)(i / ((size_t)L_ * C_));
    out[i] += y[i] * sbuf[b * C_ + c];
}

// ---------------- launch ---------------------------------------------------
extern "C" void kernel_launch(void* const* d_in, const int* in_sizes, int n_in,
                              void* d_out, int out_size) {
    const float* x      = (const float*)d_in[0];
    const float* n1g    = (const float*)d_in[1];
    const float* n1b    = (const float*)d_in[2];
    const float* qkvw   = (const float*)d_in[3];
    const float* qkvb   = (const float*)d_in[4];
    const float* rpb    = (const float*)d_in[5];
    const float* projw  = (const float*)d_in[6];
    const float* projb  = (const float*)d_in[7];
    const float* n2g    = (const float*)d_in[8];
    const float* n2b    = (const float*)d_in[9];
    const float* fc1w   = (const float*)d_in[10];
    const float* fc1b   = (const float*)d_in[11];
    const float* fc2w   = (const float*)d_in[12];
    const float* fc2b   = (const float*)d_in[13];
    const float* c1w    = (const float*)d_in[14];
    const float* c1b    = (const float*)d_in[15];
    const float* c2w    = (const float*)d_in[16];
    const float* c2b    = (const float*)d_in[17];
    const float* c3w    = (const float*)d_in[18];
    const float* c3b    = (const float*)d_in[19];
    const float* sfc1   = (const float*)d_in[20];
    const float* sfc2   = (const float*)d_in[21];
    float* out = (float*)d_out;

    float *xn, *qkv, *ao, *x1, *x1n, *hb, *y1, *y2, *y, *pool, *sbuf;
    cudaGetSymbolAddress((void**)&xn,   g_xn);
    cudaGetSymbolAddress((void**)&qkv,  g_qkv);
    cudaGetSymbolAddress((void**)&ao,   g_ao);
    cudaGetSymbolAddress((void**)&x1,   g_x1);
    cudaGetSymbolAddress((void**)&x1n,  g_x1n);
    cudaGetSymbolAddress((void**)&hb,   g_hb);
    cudaGetSymbolAddress((void**)&y1,   g_y1);
    cudaGetSymbolAddress((void**)&y2,   g_y2);
    cudaGetSymbolAddress((void**)&y,    g_y);
    cudaGetSymbolAddress((void**)&pool, g_pool);
    cudaGetSymbolAddress((void**)&sbuf, g_s);

    cudaFuncSetAttribute(gemm_mma<0>, cudaFuncAttributeMaxDynamicSharedMemorySize, GEMM_SMEM_SZ);
    cudaFuncSetAttribute(gemm_mma<1>, cudaFuncAttributeMaxDynamicSharedMemorySize, GEMM_SMEM_SZ);
    cudaFuncSetAttribute(gemm_mma<2>, cudaFuncAttributeMaxDynamicSharedMemorySize, GEMM_SMEM_SZ);
    cudaFuncSetAttribute(gemm_mma<3>, cudaFuncAttributeMaxDynamicSharedMemorySize, GEMM_SMEM_SZ);

    // 1) LN1
    ln_kernel<<<M_/8, 256>>>(x, n1g, n1b, xn);
    // 2) QKV GEMM: [M,192] @ [576,192]^T
    gemm_mma<0><<<dim3(9, M_/128), 256, GEMM_SMEM_SZ>>>(xn, qkvw, qkvb, nullptr, qkv, 3*C_, C_);
    // 3) attention (gathered shifted windows; output scattered back)
    attn_kernel<<<NWIN, 256>>>(qkv, rpb, ao);
    // 4) proj + residual -> x1
    gemm_mma<1><<<dim3(3, M_/128), 256, GEMM_SMEM_SZ>>>(ao, projw, projb, x, x1, C_, C_);
    // 5) LN2
    ln_kernel<<<M_/8, 256>>>(x1, n2g, n2b, x1n);
    // 6) fc1 + GELU
    gemm_mma<2><<<dim3(12, M_/128), 256, GEMM_SMEM_SZ>>>(x1n, fc1w, fc1b, nullptr, hb, HID_, C_);
    // 7) fc2 + residual -> out (x2)
    gemm_mma<1><<<dim3(3, M_/128), 256, GEMM_SMEM_SZ>>>(hb, fc2w, fc2b, x1, out, C_, HID_);
    // 8) LCE conv1x1 C->24
    gemm_mma<0><<<dim3(1, M_/128), 256, GEMM_SMEM_SZ>>>(xn, c1w, c1b, nullptr, y1, RED_, C_);
    // 9) LCE conv3x3 24->24
    conv3_kernel<<<dim3(W_/8, H_/8, B_), 64>>>(y1, c2w, c2b, y2);
    // 10) LCE conv1x1 24->192 + LeakyReLU
    gemm_mma<3><<<dim3(3, M_/128), 256, GEMM_SMEM_SZ>>>(y2, c3w, c3b, nullptr, y, C_, RED_);
    // 11) global avg pool
    zero_pool_kernel<<<1, 384>>>(pool);
    pool_kernel<<<M_/128, 192>>>(y, pool);
    // 12) SE gate
    se_kernel<<<1, 192>>>(pool, sfc1, sfc2, sbuf);
    // 13) out += y * s
    final_kernel<<<(M_*C_ + 255)/256, 256>>>(y, sbuf, out);
}

// round 7
// speedup vs baseline: 2.6462x; 1.1413x over previous
#include <cuda_runtime.h>
#include <cuda_bf16.h>
#include <math.h>
#include <stdint.h>

#define B_    2
#define H_    256
#define W_    256
#define C_    192
#define L_    (H_*W_)         // 65536
#define M_    (B_*L_)         // 131072
#define HID_  768
#define NH    6
#define HD    32
#define WS    8
#define SHIFT 4
#define NWIN  (B_*(H_/WS)*(W_/WS))  // 2048
#define RED_  24

// ---------------- scratch (device globals; no allocations) ----------------
__device__ float g_qkv[M_*3*C_];
__device__ float g_x1 [M_*C_];
__device__ float g_y1 [M_*RED_];
__device__ float g_y  [M_*C_];
__device__ float g_pool[B_*C_];
__device__ float g_s  [B_*C_];
// bf16 hi/lo activation planes
__device__ __nv_bfloat16 g_xnh [M_*C_],  g_xnl [M_*C_];
__device__ __nv_bfloat16 g_aoh [M_*C_],  g_aol [M_*C_];
__device__ __nv_bfloat16 g_x1nh[M_*C_],  g_x1nl[M_*C_];
__device__ __nv_bfloat16 g_hbh [(size_t)M_*HID_], g_hbl[(size_t)M_*HID_];
__device__ __nv_bfloat16 g_y2h [M_*RED_], g_y2l[M_*RED_];
// bf16 hi/lo weight planes
__device__ __nv_bfloat16 g_wqh [3*C_*C_],  g_wql [3*C_*C_];
__device__ __nv_bfloat16 g_wph [C_*C_],    g_wpl [C_*C_];
__device__ __nv_bfloat16 g_w1h [HID_*C_],  g_w1l [HID_*C_];
__device__ __nv_bfloat16 g_w2h [C_*HID_],  g_w2l [C_*HID_];
__device__ __nv_bfloat16 g_wc1h[RED_*C_],  g_wc1l[RED_*C_];
__device__ __nv_bfloat16 g_wc3h[C_*RED_],  g_wc3l[C_*RED_];

// ======================= helpers ===========================================
__device__ __forceinline__ uint32_t smem_to_u32(const void* p) {
    uint32_t a;
    asm("{ .reg .u64 t; cvta.to.shared.u64 t, %1; cvt.u32.u64 %0, t; }" : "=r"(a) : "l"(p));
    return a;
}
__device__ __forceinline__ void split2(float x, float y, uint32_t& hi, uint32_t& lo) {
    __nv_bfloat16 hx = __float2bfloat16(x), hy = __float2bfloat16(y);
    __nv_bfloat16 lx = __float2bfloat16(x - __bfloat162float(hx));
    __nv_bfloat16 ly = __float2bfloat16(y - __bfloat162float(hy));
    hi = ((uint32_t)__bfloat16_as_ushort(hy) << 16) | __bfloat16_as_ushort(hx);
    lo = ((uint32_t)__bfloat16_as_ushort(ly) << 16) | __bfloat16_as_ushort(lx);
}
#define LDSM4(r, addr) \
    asm volatile("ldmatrix.sync.aligned.m8n8.x4.shared.b16 {%0,%1,%2,%3}, [%4];" \
        : "=r"((r)[0]), "=r"((r)[1]), "=r"((r)[2]), "=r"((r)[3]) : "r"(addr))
#define MMA_BF16(d, a, b0, b1) \
    asm volatile("mma.sync.aligned.m16n8k16.row.col.f32.bf16.bf16.f32 " \
        "{%0,%1,%2,%3},{%4,%5,%6,%7},{%8,%9},{%0,%1,%2,%3};" \
        : "+f"((d)[0]), "+f"((d)[1]), "+f"((d)[2]), "+f"((d)[3]) \
        : "r"((a)[0]), "r"((a)[1]), "r"((a)[2]), "r"((a)[3]), "r"(b0), "r"(b1))
#define CP_ASYNC(dst, src, sz) \
    asm volatile("cp.async.cg.shared.global [%0], [%1], 16, %2;" \
        :: "r"(dst), "l"(src), "r"(sz))
#define CP_COMMIT() asm volatile("cp.async.commit_group;" ::: "memory")

// ======================= bf16x3 mma.sync GEMM (cp.async 3-stage) ===========
// out[M,N] = epi(A @ W^T + bias); A,W given as bf16 hi/lo planes [rows][K].
// CTA tile 128x64, BK=32. bf16x3: Ahi*Bhi + Alo*Bhi + Ahi*Blo, fp32 acc.
// EPI: 0 none, 1 +res, 2 exact GELU, 3 LeakyReLU(0.2). OUTP: 1 = write planes.
#define STG_STRIDE 30720
#define A_HI 0
#define A_LO 10240
#define B_HI 20480
#define B_LO 25600
#define NSTG 3
#define GEMM_SMEM_SZ (NSTG*STG_STRIDE)   // 92160

template<int EPI, int OUTP>
__device__ __forceinline__ void gemm_body(const __nv_bfloat16* __restrict__ Ah,
                                          const __nv_bfloat16* __restrict__ Al,
                                          const __nv_bfloat16* __restrict__ Wh,
                                          const __nv_bfloat16* __restrict__ Wl,
                                          const float* __restrict__ bias,
                                          const float* __restrict__ res,
                                          float* __restrict__ out,
                                          __nv_bfloat16* __restrict__ outh,
                                          __nv_bfloat16* __restrict__ outl,
                                          int N, int K, char* smem) {
    const int tid  = threadIdx.x;
    const int lane = tid & 31;
    const int warp = tid >> 5;
    const int m0 = blockIdx.y * 128, n0 = blockIdx.x * 64;
    const int wm = (warp & 3) * 32, wn = (warp >> 2) * 32;
    const int nch = (K + 31) >> 5;

#define ISSUE(stg, c) do { \
    char* base_ = smem + (stg) * STG_STRIDE; \
    int k0_ = (c) * 32; \
    _Pragma("unroll") \
    for (int i = 0; i < 4; i++) { \
        int t = tid + i * 256; \
        int row = t >> 3, plane = (t >> 2) & 1, seg = t & 3; \
        const __nv_bfloat16* gp = plane ? Al : Ah; \
        int ke = k0_ + seg * 8; \
        int srcsz = (K - ke) * 2; \
        srcsz = srcsz < 0 ? 0 : (srcsz > 16 ? 16 : srcsz); \
        const __nv_bfloat16* g = gp + (size_t)(m0 + row) * K + (srcsz ? ke : 0); \
        uint32_t d = smem_to_u32(base_ + plane * 10240 + row * 80 + seg * 16); \
        CP_ASYNC(d, g, srcsz); \
    } \
    _Pragma("unroll") \
    for (int i = 0; i < 2; i++) { \
        int t = tid + i * 256; \
        int row = t >> 3, plane = (t >> 2) & 1, seg = t & 3; \
        const __nv_bfloat16* gp = plane ? Wl : Wh; \
        int ke = k0_ + seg * 8; \
        int srcsz = (K - ke) * 2; \
        srcsz = srcsz < 0 ? 0 : (srcsz > 16 ? 16 : srcsz); \
        if (n0 + row >= N) srcsz = 0; \
        int grow = (n0 + row < N) ? (n0 + row) : 0; \
        const __nv_bfloat16* g = gp + (size_t)grow * K + (srcsz ? ke : 0); \
        uint32_t d = smem_to_u32(base_ + B_HI + plane * 5120 + row * 80 + seg * 16); \
        CP_ASYNC(d, g, srcsz); \
    } \
    CP_COMMIT(); } while (0)

    float acc[2][4][4];
    #pragma unroll
    for (int i = 0; i < 2; i++)
        #pragma unroll
        for (int j = 0; j < 4; j++)
            #pragma unroll
            for (int q = 0; q < 4; q++) acc[i][j][q] = 0.f;

    ISSUE(0, 0);
    if (nch > 1) ISSUE(1, 1);

    int sc = 0;
    for (int c = 0; c < nch; c++) {
        if (c + 1 < nch) asm volatile("cp.async.wait_group 1;" ::: "memory");
        else             asm volatile("cp.async.wait_group 0;" ::: "memory");
        __syncthreads();
        char* base = smem + sc * STG_STRIDE;
        #pragma unroll
        for (int ks = 0; ks < 2; ks++) {
            uint32_t ahi[2][4], alo[2][4], bhi[2][4], blo[2][4];
            #pragma unroll
            for (int mt = 0; mt < 2; mt++) {
                int row = wm + mt * 16 + (lane & 15);
                int colb = ks * 32 + ((lane >> 4) & 1) * 16;
                uint32_t ad = smem_to_u32(base + A_HI + row * 80 + colb);
                LDSM4(ahi[mt], ad);
                LDSM4(alo[mt], ad + (A_LO - A_HI));
            }
            #pragma unroll
            for (int np = 0; np < 2; np++) {
                int n = wn + np * 16 + (lane & 7) + ((lane >> 4) & 1) * 8;
                int colb = ks * 32 + ((lane >> 3) & 1) * 16;
                uint32_t bd = smem_to_u32(base + B_HI + n * 80 + colb);
                LDSM4(bhi[np], bd);
                LDSM4(blo[np], bd + (B_LO - B_HI));
            }
            #pragma unroll
            for (int mt = 0; mt < 2; mt++)
                #pragma unroll
                for (int nt = 0; nt < 4; nt++) {
                    int np = nt >> 1, h = (nt & 1) * 2;
                    MMA_BF16(acc[mt][nt], ahi[mt], bhi[np][h], bhi[np][h+1]);
                    MMA_BF16(acc[mt][nt], alo[mt], bhi[np][h], bhi[np][h+1]);
                    MMA_BF16(acc[mt][nt], ahi[mt], blo[np][h], blo[np][h+1]);
                }
        }
        if (c + 2 < nch) {
            int si = sc + 2; if (si >= NSTG) si -= NSTG;
            ISSUE(si, c + 2);
        }
        sc = (sc + 1 == NSTG) ? 0 : sc + 1;
    }

    // ---- epilogue ----
    #pragma unroll
    for (int mt = 0; mt < 2; mt++) {
        int r0 = m0 + wm + mt * 16 + (lane >> 2);
        #pragma unroll
        for (int nt = 0; nt < 4; nt++) {
            int col = n0 + wn + nt * 8 + (lane & 3) * 2;
            if (col < N) {
                float b0v = bias[col], b1v = bias[col + 1];
                #pragma unroll
                for (int rr = 0; rr < 2; rr++) {
                    int r = r0 + rr * 8;
                    float v0 = acc[mt][nt][rr*2+0] + b0v;
                    float v1 = acc[mt][nt][rr*2+1] + b1v;
                    if (EPI == 1) {
                        float2 rv = *(const float2*)(res + (size_t)r * N + col);
                        v0 += rv.x; v1 += rv.y;
                    }
                    if (EPI == 2) {
                        v0 = 0.5f * v0 * (1.f + erff(v0 * 0.70710678118654752f));
                        v1 = 0.5f * v1 * (1.f + erff(v1 * 0.70710678118654752f));
                    }
                    if (EPI == 3) {
                        v0 = (v0 >= 0.f) ? v0 : 0.2f * v0;
                        v1 = (v1 >= 0.f) ? v1 : 0.2f * v1;
                    }
                    if (OUTP) {
                        uint32_t hi, lo;
                        split2(v0, v1, hi, lo);
                        *(uint32_t*)(outh + (size_t)r * N + col) = hi;
                        *(uint32_t*)(outl + (size_t)r * N + col) = lo;
                    } else {
                        *(float2*)(out + (size_t)r * N + col) = make_float2(v0, v1);
                    }
                }
            }
        }
    }
#undef ISSUE
}

template<int EPI, int OUTP>
__global__ __launch_bounds__(256, 2) void gemm_cp(const __nv_bfloat16* __restrict__ Ah,
                                                  const __nv_bfloat16* __restrict__ Al,
                                                  const __nv_bfloat16* __restrict__ Wh,
                                                  const __nv_bfloat16* __restrict__ Wl,
                                                  const float* __restrict__ bias,
                                                  const float* __restrict__ res,
                                                  float* __restrict__ out,
                                                  __nv_bfloat16* __restrict__ outh,
                                                  __nv_bfloat16* __restrict__ outl,
                                                  int N, int K) {
    extern __shared__ char smem[];
    gemm_body<EPI, OUTP>(Ah, Al, Wh, Wl, bias, res, out, outh, outl, N, K, smem);
}

// ---------------- weight split ---------------------------------------------
__global__ __launch_bounds__(256) void split_kernel(const float* __restrict__ s,
                                                    __nv_bfloat16* __restrict__ h,
                                                    __nv_bfloat16* __restrict__ l,
                                                    int n) {
    int i = blockIdx.x * 256 + threadIdx.x;
    if (i < n) {
        float v = s[i];
        __nv_bfloat16 hv = __float2bfloat16(v);
        h[i] = hv;
        l[i] = __float2bfloat16(v - __bfloat162float(hv));
    }
}

// ---------------- LayerNorm -> bf16 planes ---------------------------------
__global__ __launch_bounds__(256) void ln_split_kernel(const float* __restrict__ x,
                                                       const float* __restrict__ g,
                                                       const float* __restrict__ b,
                                                       __nv_bfloat16* __restrict__ oh,
                                                       __nv_bfloat16* __restrict__ ol) {
    int token = blockIdx.x * 8 + (threadIdx.x >> 5);
    int lane  = threadIdx.x & 31;
    const float* p = x + (size_t)token * C_;
    float v[6];
    float s = 0.f;
    #pragma unroll
    for (int j = 0; j < 6; j++) { v[j] = p[lane + 32*j]; s += v[j]; }
    #pragma unroll
    for (int o = 16; o > 0; o >>= 1) s += __shfl_xor_sync(0xffffffffu, s, o);
    float mean = s * (1.f / C_);
    float q = 0.f;
    #pragma unroll
    for (int j = 0; j < 6; j++) { float d = v[j] - mean; q += d * d; }
    #pragma unroll
    for (int o = 16; o > 0; o >>= 1) q += __shfl_xor_sync(0xffffffffu, q, o);
    float rstd = rsqrtf(q * (1.f / C_) + 1e-5f);
    #pragma unroll
    for (int j = 0; j < 6; j++) {
        int c = lane + 32*j;
        float val = (v[j] - mean) * rstd * g[c] + b[c];
        __nv_bfloat16 hv = __float2bfloat16(val);
        oh[(size_t)token * C_ + c] = hv;
        ol[(size_t)token * C_ + c] = __float2bfloat16(val - __bfloat162float(hv));
    }
}

// ---------------- Windowed attention, one block per window ----------------
__global__ __launch_bounds__(256) void attn_kernel(const float* __restrict__ qkv,
                                                   const float* __restrict__ rpb,
                                                   __nv_bfloat16* __restrict__ aoh,
                                                   __nv_bfloat16* __restrict__ aol) {
    __shared__ int   gidx[64];
    __shared__ int   rid [64];
    __shared__ float qs[64][33];
    __shared__ float ks[64][33];
    __shared__ float vs[64][36];
    __shared__ float Sm[64][65];

    int tid = threadIdx.x;
    int wid = blockIdx.x;
    int b   = wid >> 10;
    int wib = wid & 1023;
    int wh  = wib >> 5;
    int ww  = wib & 31;

    if (tid < 64) {
        int ih = tid >> 3, iw = tid & 7;
        int h = wh * 8 + ih, w = ww * 8 + iw;
        int hs = (h + SHIFT) & (H_ - 1);
        int ws2 = (w + SHIFT) & (W_ - 1);
        gidx[tid] = b * L_ + hs * W_ + ws2;
        int rh = (h < H_ - WS) ? 0 : ((h < H_ - SHIFT) ? 1 : 2);
        int rw = (w < W_ - WS) ? 0 : ((w < W_ - SHIFT) ? 1 : 2);
        rid[tid] = rh * 3 + rw;
    }
    __syncthreads();

    const float SCALE = 0.17677669529663687f;
    int i  = tid >> 2;
    int jb = (tid & 3) * 16;
    int ihi = i >> 3, iwi = i & 7;
    int r_out = tid >> 2;
    int db    = (tid & 3) * 8;

    for (int h = 0; h < NH; h++) {
        for (int e = tid; e < 6144; e += 256) {
            int mat = e >> 11;
            int rem = e & 2047;
            int t = rem >> 5, d = rem & 31;
            float v = qkv[(size_t)gidx[t] * (3*C_) + mat * C_ + h * HD + d];
            if (mat == 0)      qs[t][d] = v * SCALE;
            else if (mat == 1) ks[t][d] = v;
            else               vs[t][d] = v;
        }
        __syncthreads();

        float qrow[32];
        #pragma unroll
        for (int kk = 0; kk < 32; kk++) qrow[kk] = qs[i][kk];
        int ridi = rid[i];
        float ex[16];
        float mx = -1e30f;
        #pragma unroll
        for (int jj = 0; jj < 16; jj++) {
            int j = jb + jj;
            float s = 0.f;
            #pragma unroll
            for (int kk = 0; kk < 32; kk++) s += qrow[kk] * ks[j][kk];
            int jh = j >> 3, jw = j & 7;
            int rel = (ihi - jh + 7) * 15 + (iwi - jw + 7);
            s += rpb[rel * NH + h];
            if (ridi != rid[j]) s -= 100.f;
            ex[jj] = s;
            mx = fmaxf(mx, s);
        }
        mx = fmaxf(mx, __shfl_xor_sync(0xffffffffu, mx, 1));
        mx = fmaxf(mx, __shfl_xor_sync(0xffffffffu, mx, 2));
        float sum = 0.f;
        #pragma unroll
        for (int jj = 0; jj < 16; jj++) { ex[jj] = expf(ex[jj] - mx); sum += ex[jj]; }
        sum += __shfl_xor_sync(0xffffffffu, sum, 1);
        sum += __shfl_xor_sync(0xffffffffu, sum, 2);
        float inv = 1.f / sum;
        #pragma unroll
        for (int jj = 0; jj < 16; jj++) Sm[i][jb + jj] = ex[jj] * inv;
        __syncthreads();

        float oacc[8];
        #pragma unroll
        for (int d = 0; d < 8; d++) oacc[d] = 0.f;
        for (int m = 0; m < 64; m++) {
            float sv = Sm[r_out][m];
            float4 v0 = *(const float4*)&vs[m][db];
            float4 v1 = *(const float4*)&vs[m][db + 4];
            oacc[0] += sv * v0.x; oacc[1] += sv * v0.y;
            oacc[2] += sv * v0.z; oacc[3] += sv * v0.w;
            oacc[4] += sv * v1.x; oacc[5] += sv * v1.y;
            oacc[6] += sv * v1.z; oacc[7] += sv * v1.w;
        }
        size_t off = (size_t)gidx[r_out] * C_ + h * HD + db;
        #pragma unroll
        for (int d = 0; d < 8; d += 2) {
            uint32_t hi, lo;
            split2(oacc[d], oacc[d + 1], hi, lo);
            *(uint32_t*)(aoh + off + d) = hi;
            *(uint32_t*)(aol + off + d) = lo;
        }
        __syncthreads();
    }
}

// ---------------- 3x3 conv on r=24 channels, NHWC, pad 1 -------------------
__global__ __launch_bounds__(64) void conv3_kernel(const float* __restrict__ yin,
                                                   const float* __restrict__ w,
                                                   const float* __restrict__ bias,
                                                   __nv_bfloat16* __restrict__ yh,
                                                   __nv_bfloat16* __restrict__ yl) {
    __shared__ float patch[100][RED_];
    __shared__ float wts[RED_ * RED_ * 9];
    int tid = threadIdx.x;
    int b = blockIdx.z;
    int th0 = blockIdx.y * 8, tw0 = blockIdx.x * 8;

    for (int d = tid; d < RED_ * RED_ * 9; d += 64) {
        int oc = d % RED_;
        int t2 = d / RED_;
        int kk = t2 % 9;
        int ic = t2 / 9;
        wts[d] = w[(oc * RED_ + ic) * 9 + kk];
    }
    for (int d = tid; d < 100 * RED_; d += 64) {
        int ic = d % RED_;
        int pos = d / RED_;
        int ph = pos / 10, pw = pos % 10;
        int hh = th0 + ph - 1, ww = tw0 + pw - 1;
        float v = 0.f;
        if (hh >= 0 && hh < H_ && ww >= 0 && ww < W_)
            v = yin[((size_t)b * L_ + hh * W_ + ww) * RED_ + ic];
        patch[pos][ic] = v;
    }
    __syncthreads();

    int py = tid >> 3, px = tid & 7;
    float acc[RED_];
    #pragma unroll
    for (int oc = 0; oc < RED_; oc++) acc[oc] = __ldg(bias + oc);
    for (int ic = 0; ic < RED_; ic++) {
        #pragma unroll
        for (int kk = 0; kk < 9; kk++) {
            int kh = kk / 3, kw = kk % 3;
            float pv = patch[(py + kh) * 10 + (px + kw)][ic];
            const float4* wp = (const float4*)&wts[(ic * 9 + kk) * RED_];
            #pragma unroll
            for (int o4 = 0; o4 < 6; o4++) {
                float4 wv = wp[o4];
                acc[o4*4+0] += wv.x * pv; acc[o4*4+1] += wv.y * pv;
                acc[o4*4+2] += wv.z * pv; acc[o4*4+3] += wv.w * pv;
            }
        }
    }
    size_t off = ((size_t)b * L_ + (th0 + py) * W_ + (tw0 + px)) * RED_;
    #pragma unroll
    for (int oc = 0; oc < RED_; oc += 2) {
        uint32_t hi, lo;
        split2(acc[oc], acc[oc + 1], hi, lo);
        *(uint32_t*)(yh + off + oc) = hi;
        *(uint32_t*)(yl + off + oc) = lo;
    }
}

// ---------------- pool / SE / final ---------------------------------------
__global__ void zero_pool_kernel(float* pool) {
    if (threadIdx.x < B_ * C_) pool[threadIdx.x] = 0.f;
}

__global__ __launch_bounds__(192) void pool_kernel(const float* __restrict__ y,
                                                   float* __restrict__ pool) {
    int base = blockIdx.x * 128;
    int b = base >> 16;
    int c = threadIdx.x;
    float acc = 0.f;
    for (int i = 0; i < 128; i++)
        acc += y[(size_t)(base + i) * C_ + c];
    atomicAdd(&pool[b * C_ + c], acc);
}

__global__ __launch_bounds__(192) void se_kernel(const float* __restrict__ pool,
                                                 const float* __restrict__ fc1,
                                                 const float* __restrict__ fc2,
                                                 float* __restrict__ sbuf) {
    __shared__ float t[RED_];
    int tid = threadIdx.x;
    const float inv = 1.f / (float)L_;
    for (int b = 0; b < B_; b++) {
        if (tid < RED_) {
            float s = 0.f;
            for (int c = 0; c < C_; c++)
                s += pool[b * C_ + c] * inv * fc1[tid * C_ + c];
            t[tid] = fmaxf(s, 0.f);
        }
        __syncthreads();
        float s = 0.f;
        #pragma unroll
        for (int j = 0; j < RED_; j++) s += t[j] * fc2[tid * RED_ + j];
        sbuf[b * C_ + tid] = 1.f / (1.f + expf(-s));
        __syncthreads();
    }
}

__global__ __launch_bounds__(256) void final_kernel(const float* __restrict__ y,
                                                    const float* __restrict__ sbuf,
                                                    float* __restrict__ out) {
    size_t i = (size_t)blockIdx.x * 256 + threadIdx.x;
    if (i >= (size_t)M_ * C_) return;
    int c = (int)(i % C_);
    int b = (int)(i / ((size_t)L_ * C_));
    out[i] += y[i] * sbuf[b * C_ + c];
}

// ---------------- launch ---------------------------------------------------
extern "C" void kernel_launch(void* const* d_in, const int* in_sizes, int n_in,
                              void* d_out, int out_size) {
    const float* x      = (const float*)d_in[0];
    const float* n1g    = (const float*)d_in[1];
    const float* n1b    = (const float*)d_in[2];
    const float* qkvw   = (const float*)d_in[3];
    const float* qkvb   = (const float*)d_in[4];
    const float* rpb    = (const float*)d_in[5];
    const float* projw  = (const float*)d_in[6];
    const float* projb  = (const float*)d_in[7];
    const float* n2g    = (const float*)d_in[8];
    const float* n2b    = (const float*)d_in[9];
    const float* fc1w   = (const float*)d_in[10];
    const float* fc1b   = (const float*)d_in[11];
    const float* fc2w   = (const float*)d_in[12];
    const float* fc2b   = (const float*)d_in[13];
    const float* c1w    = (const float*)d_in[14];
    const float* c1b    = (const float*)d_in[15];
    const float* c2w    = (const float*)d_in[16];
    const float* c2b    = (const float*)d_in[17];
    const float* c3w    = (const float*)d_in[18];
    const float* c3b    = (const float*)d_in[19];
    const float* sfc1   = (const float*)d_in[20];
    const float* sfc2   = (const float*)d_in[21];
    float* out = (float*)d_out;

    float *qkv, *x1, *y1, *y, *pool, *sbuf;
    cudaGetSymbolAddress((void**)&qkv,  g_qkv);
    cudaGetSymbolAddress((void**)&x1,   g_x1);
    cudaGetSymbolAddress((void**)&y1,   g_y1);
    cudaGetSymbolAddress((void**)&y,    g_y);
    cudaGetSymbolAddress((void**)&pool, g_pool);
    cudaGetSymbolAddress((void**)&sbuf, g_s);
    __nv_bfloat16 *xnh, *xnl, *aoh, *aol, *x1nh, *x1nl, *hbh, *hbl, *y2h, *y2l;
    __nv_bfloat16 *wqh, *wql, *wph, *wpl, *w1h, *w1l, *w2h, *w2l, *wc1h, *wc1l, *wc3h, *wc3l;
    cudaGetSymbolAddress((void**)&xnh,  g_xnh);  cudaGetSymbolAddress((void**)&xnl,  g_xnl);
    cudaGetSymbolAddress((void**)&aoh,  g_aoh);  cudaGetSymbolAddress((void**)&aol,  g_aol);
    cudaGetSymbolAddress((void**)&x1nh, g_x1nh); cudaGetSymbolAddress((void**)&x1nl, g_x1nl);
    cudaGetSymbolAddress((void**)&hbh,  g_hbh);  cudaGetSymbolAddress((void**)&hbl,  g_hbl);
    cudaGetSymbolAddress((void**)&y2h,  g_y2h);  cudaGetSymbolAddress((void**)&y2l,  g_y2l);
    cudaGetSymbolAddress((void**)&wqh,  g_wqh);  cudaGetSymbolAddress((void**)&wql,  g_wql);
    cudaGetSymbolAddress((void**)&wph,  g_wph);  cudaGetSymbolAddress((void**)&wpl,  g_wpl);
    cudaGetSymbolAddress((void**)&w1h,  g_w1h);  cudaGetSymbolAddress((void**)&w1l,  g_w1l);
    cudaGetSymbolAddress((void**)&w2h,  g_w2h);  cudaGetSymbolAddress((void**)&w2l,  g_w2l);
    cudaGetSymbolAddress((void**)&wc1h, g_wc1h); cudaGetSymbolAddress((void**)&wc1l, g_wc1l);
    cudaGetSymbolAddress((void**)&wc3h, g_wc3h); cudaGetSymbolAddress((void**)&wc3l, g_wc3l);

    cudaFuncSetAttribute(gemm_cp<0,0>, cudaFuncAttributeMaxDynamicSharedMemorySize, GEMM_SMEM_SZ);
    cudaFuncSetAttribute(gemm_cp<1,0>, cudaFuncAttributeMaxDynamicSharedMemorySize, GEMM_SMEM_SZ);
    cudaFuncSetAttribute(gemm_cp<2,1>, cudaFuncAttributeMaxDynamicSharedMemorySize, GEMM_SMEM_SZ);
    cudaFuncSetAttribute(gemm_cp<3,0>, cudaFuncAttributeMaxDynamicSharedMemorySize, GEMM_SMEM_SZ);

    // 0) weight splits
    split_kernel<<<(3*C_*C_+255)/256, 256>>>(qkvw, wqh, wql, 3*C_*C_);
    split_kernel<<<(C_*C_+255)/256, 256>>>(projw, wph, wpl, C_*C_);
    split_kernel<<<(HID_*C_+255)/256, 256>>>(fc1w, w1h, w1l, HID_*C_);
    split_kernel<<<(C_*HID_+255)/256, 256>>>(fc2w, w2h, w2l, C_*HID_);
    split_kernel<<<(RED_*C_+255)/256, 256>>>(c1w, wc1h, wc1l, RED_*C_);
    split_kernel<<<(C_*RED_+255)/256, 256>>>(c3w, wc3h, wc3l, C_*RED_);
    // 1) LN1 -> planes
    ln_split_kernel<<<M_/8, 256>>>(x, n1g, n1b, xnh, xnl);
    // 2) QKV GEMM
    gemm_cp<0,0><<<dim3(9, M_/128), 256, GEMM_SMEM_SZ>>>(xnh, xnl, wqh, wql, qkvb, nullptr, qkv, nullptr, nullptr, 3*C_, C_);
    // 3) attention -> ao planes
    attn_kernel<<<NWIN, 256>>>(qkv, rpb, aoh, aol);
    // 4) proj + residual -> x1 (fp32)
    gemm_cp<1,0><<<dim3(3, M_/128), 256, GEMM_SMEM_SZ>>>(aoh, aol, wph, wpl, projb, x, x1, nullptr, nullptr, C_, C_);
    // 5) LN2 -> planes
    ln_split_kernel<<<M_/8, 256>>>(x1, n2g, n2b, x1nh, x1nl);
    // 6) fc1 + GELU -> hb planes
    gemm_cp<2,1><<<dim3(12, M_/128), 256, GEMM_SMEM_SZ>>>(x1nh, x1nl, w1h, w1l, fc1b, nullptr, nullptr, hbh, hbl, HID_, C_);
    // 7) fc2 + residual -> out
    gemm_cp<1,0><<<dim3(3, M_/128), 256, GEMM_SMEM_SZ>>>(hbh, hbl, w2h, w2l, fc2b, x1, out, nullptr, nullptr, C_, HID_);
    // 8) LCE conv1x1 C->24 -> y1 fp32
    gemm_cp<0,0><<<dim3(1, M_/128), 256, GEMM_SMEM_SZ>>>(xnh, xnl, wc1h, wc1l, c1b, nullptr, y1, nullptr, nullptr, RED_, C_);
    // 9) LCE conv3x3 -> y2 planes
    conv3_kernel<<<dim3(W_/8, H_/8, B_), 64>>>(y1, c2w, c2b, y2h, y2l);
    // 10) LCE conv1x1 24->192 + LeakyReLU -> y fp32
    gemm_cp<3,0><<<dim3(3, M_/128), 256, GEMM_SMEM_SZ>>>(y2h, y2l, wc3h, wc3l, c3b, nullptr, y, nullptr, nullptr, C_, RED_);
    // 11) global avg pool
    zero_pool_kernel<<<1, 384>>>(pool);
    pool_kernel<<<M_/128, 192>>>(y, pool);
    // 12) SE gate
    se_kernel<<<1, 192>>>(pool, sfc1, sfc2, sbuf);
    // 13) out += y * s
    final_kernel<<<(M_*C_ + 255)/256, 256>>>(y, sbuf, out);
}

// round 8
// speedup vs baseline: 2.7064x; 1.0228x over previous
#include <cuda_runtime.h>
#include <cuda_bf16.h>
#include <math.h>
#include <stdint.h>

#define B_    2
#define H_    256
#define W_    256
#define C_    192
#define L_    (H_*W_)         // 65536
#define M_    (B_*L_)         // 131072
#define HID_  768
#define NH    6
#define HD    32
#define WS    8
#define SHIFT 4
#define NWIN  (B_*(H_/WS)*(W_/WS))  // 2048
#define RED_  24

// ---------------- scratch (device globals; no allocations) ----------------
__device__ float g_qkv[M_*3*C_];
__device__ float g_x1 [M_*C_];
__device__ float g_y1 [M_*RED_];
__device__ float g_y  [M_*C_];
__device__ float g_pool[B_*C_];
__device__ float g_s  [B_*C_];
// bf16 hi/lo activation planes
__device__ __nv_bfloat16 g_xnh [M_*C_],  g_xnl [M_*C_];
__device__ __nv_bfloat16 g_aoh [M_*C_],  g_aol [M_*C_];
__device__ __nv_bfloat16 g_x1nh[M_*C_],  g_x1nl[M_*C_];
__device__ __nv_bfloat16 g_hbh [(size_t)M_*HID_], g_hbl[(size_t)M_*HID_];
__device__ __nv_bfloat16 g_y2h [M_*RED_], g_y2l[M_*RED_];
// bf16 hi/lo weight planes
__device__ __nv_bfloat16 g_wqh [3*C_*C_],  g_wql [3*C_*C_];
__device__ __nv_bfloat16 g_wph [C_*C_],    g_wpl [C_*C_];
__device__ __nv_bfloat16 g_w1h [HID_*C_],  g_w1l [HID_*C_];
__device__ __nv_bfloat16 g_w2h [C_*HID_],  g_w2l [C_*HID_];
__device__ __nv_bfloat16 g_wc1h[RED_*C_],  g_wc1l[RED_*C_];
__device__ __nv_bfloat16 g_wc3h[C_*RED_],  g_wc3l[C_*RED_];

// ======================= helpers ===========================================
__device__ __forceinline__ uint32_t smem_to_u32(const void* p) {
    uint32_t a;
    asm("{ .reg .u64 t; cvta.to.shared.u64 t, %1; cvt.u32.u64 %0, t; }" : "=r"(a) : "l"(p));
    return a;
}
__device__ __forceinline__ void split2(float x, float y, uint32_t& hi, uint32_t& lo) {
    __nv_bfloat16 hx = __float2bfloat16(x), hy = __float2bfloat16(y);
    __nv_bfloat16 lx = __float2bfloat16(x - __bfloat162float(hx));
    __nv_bfloat16 ly = __float2bfloat16(y - __bfloat162float(hy));
    hi = ((uint32_t)__bfloat16_as_ushort(hy) << 16) | __bfloat16_as_ushort(hx);
    lo = ((uint32_t)__bfloat16_as_ushort(ly) << 16) | __bfloat16_as_ushort(lx);
}
#define LDSM4(r, addr) \
    asm volatile("ldmatrix.sync.aligned.m8n8.x4.shared.b16 {%0,%1,%2,%3}, [%4];" \
        : "=r"((r)[0]), "=r"((r)[1]), "=r"((r)[2]), "=r"((r)[3]) : "r"(addr))
#define MMA_BF16(d, a, b0, b1) \
    asm volatile("mma.sync.aligned.m16n8k16.row.col.f32.bf16.bf16.f32 " \
        "{%0,%1,%2,%3},{%4,%5,%6,%7},{%8,%9},{%0,%1,%2,%3};" \
        : "+f"((d)[0]), "+f"((d)[1]), "+f"((d)[2]), "+f"((d)[3]) \
        : "r"((a)[0]), "r"((a)[1]), "r"((a)[2]), "r"((a)[3]), "r"(b0), "r"(b1))
#define CP_ASYNC(dst, src, sz) \
    asm volatile("cp.async.cg.shared.global [%0], [%1], 16, %2;" \
        :: "r"(dst), "l"(src), "r"(sz))
#define CP_COMMIT() asm volatile("cp.async.commit_group;" ::: "memory")

// ======================= bf16x3 mma.sync GEMM (cp.async 3-stage) ===========
// out[M,N] = epi(A @ W^T + bias); A,W given as bf16 hi/lo planes [rows][K].
// CTA tile 128x64, BK=32. bf16x3 passes interleaved across 8 accumulators.
// EPI: 0 none, 1 +res, 2 exact GELU, 3 LeakyReLU(0.2),
//      4 +res + gate (out = v + res + yy*s[b,col]). OUTP: 1 = write planes.
#define STG_STRIDE 30720
#define A_HI 0
#define A_LO 10240
#define B_HI 20480
#define B_LO 25600
#define NSTG 3
#define GEMM_SMEM_SZ (NSTG*STG_STRIDE)   // 92160

template<int EPI, int OUTP>
__device__ __forceinline__ void gemm_body(const __nv_bfloat16* __restrict__ Ah,
                                          const __nv_bfloat16* __restrict__ Al,
                                          const __nv_bfloat16* __restrict__ Wh,
                                          const __nv_bfloat16* __restrict__ Wl,
                                          const float* __restrict__ bias,
                                          const float* __restrict__ res,
                                          const float* __restrict__ yy,
                                          const float* __restrict__ sgate,
                                          float* __restrict__ out,
                                          __nv_bfloat16* __restrict__ outh,
                                          __nv_bfloat16* __restrict__ outl,
                                          int N, int K, char* smem) {
    const int tid  = threadIdx.x;
    const int lane = tid & 31;
    const int warp = tid >> 5;
    const int m0 = blockIdx.y * 128, n0 = blockIdx.x * 64;
    const int wm = (warp & 3) * 32, wn = (warp >> 2) * 32;
    const int nch = (K + 31) >> 5;

#define ISSUE(stg, c) do { \
    char* base_ = smem + (stg) * STG_STRIDE; \
    int k0_ = (c) * 32; \
    _Pragma("unroll") \
    for (int i = 0; i < 4; i++) { \
        int t = tid + i * 256; \
        int row = t >> 3, plane = (t >> 2) & 1, seg = t & 3; \
        const __nv_bfloat16* gp = plane ? Al : Ah; \
        int ke = k0_ + seg * 8; \
        int srcsz = (K - ke) * 2; \
        srcsz = srcsz < 0 ? 0 : (srcsz > 16 ? 16 : srcsz); \
        const __nv_bfloat16* g = gp + (size_t)(m0 + row) * K + (srcsz ? ke : 0); \
        uint32_t d = smem_to_u32(base_ + plane * 10240 + row * 80 + seg * 16); \
        CP_ASYNC(d, g, srcsz); \
    } \
    _Pragma("unroll") \
    for (int i = 0; i < 2; i++) { \
        int t = tid + i * 256; \
        int row = t >> 3, plane = (t >> 2) & 1, seg = t & 3; \
        const __nv_bfloat16* gp = plane ? Wl : Wh; \
        int ke = k0_ + seg * 8; \
        int srcsz = (K - ke) * 2; \
        srcsz = srcsz < 0 ? 0 : (srcsz > 16 ? 16 : srcsz); \
        if (n0 + row >= N) srcsz = 0; \
        int grow = (n0 + row < N) ? (n0 + row) : 0; \
        const __nv_bfloat16* g = gp + (size_t)grow * K + (srcsz ? ke : 0); \
        uint32_t d = smem_to_u32(base_ + B_HI + plane * 5120 + row * 80 + seg * 16); \
        CP_ASYNC(d, g, srcsz); \
    } \
    CP_COMMIT(); } while (0)

    float acc[2][4][4];
    #pragma unroll
    for (int i = 0; i < 2; i++)
        #pragma unroll
        for (int j = 0; j < 4; j++)
            #pragma unroll
            for (int q = 0; q < 4; q++) acc[i][j][q] = 0.f;

    ISSUE(0, 0);
    if (nch > 1) ISSUE(1, 1);

    int sc = 0;
    for (int c = 0; c < nch; c++) {
        if (c + 1 < nch) asm volatile("cp.async.wait_group 1;" ::: "memory");
        else             asm volatile("cp.async.wait_group 0;" ::: "memory");
        __syncthreads();
        char* base = smem + sc * STG_STRIDE;
        #pragma unroll
        for (int ks = 0; ks < 2; ks++) {
            uint32_t ahi[2][4], alo[2][4], bhi[2][4], blo[2][4];
            #pragma unroll
            for (int mt = 0; mt < 2; mt++) {
                int row = wm + mt * 16 + (lane & 15);
                int colb = ks * 32 + ((lane >> 4) & 1) * 16;
                uint32_t ad = smem_to_u32(base + A_HI + row * 80 + colb);
                LDSM4(ahi[mt], ad);
                LDSM4(alo[mt], ad + (A_LO - A_HI));
            }
            #pragma unroll
            for (int np = 0; np < 2; np++) {
                int n = wn + np * 16 + (lane & 7) + ((lane >> 4) & 1) * 8;
                int colb = ks * 32 + ((lane >> 3) & 1) * 16;
                uint32_t bd = smem_to_u32(base + B_HI + n * 80 + colb);
                LDSM4(bhi[np], bd);
                LDSM4(blo[np], bd + (B_LO - B_HI));
            }
            // pass-outer ordering: consecutive MMAs hit different accumulators
            #pragma unroll
            for (int pass = 0; pass < 3; pass++)
                #pragma unroll
                for (int mt = 0; mt < 2; mt++)
                    #pragma unroll
                    for (int nt = 0; nt < 4; nt++) {
                        int np = nt >> 1, h = (nt & 1) * 2;
                        const uint32_t* af = (pass == 1) ? alo[mt] : ahi[mt];
                        const uint32_t (*bf)[4] = (pass == 2) ? blo : bhi;
                        MMA_BF16(acc[mt][nt], af, bf[np][h], bf[np][h+1]);
                    }
        }
        if (c + 2 < nch) {
            int si = sc + 2; if (si >= NSTG) si -= NSTG;
            ISSUE(si, c + 2);
        }
        sc = (sc + 1 == NSTG) ? 0 : sc + 1;
    }

    // ---- epilogue ----
    #pragma unroll
    for (int mt = 0; mt < 2; mt++) {
        int r0 = m0 + wm + mt * 16 + (lane >> 2);
        #pragma unroll
        for (int nt = 0; nt < 4; nt++) {
            int col = n0 + wn + nt * 8 + (lane & 3) * 2;
            if (col < N) {
                float b0v = bias[col], b1v = bias[col + 1];
                #pragma unroll
                for (int rr = 0; rr < 2; rr++) {
                    int r = r0 + rr * 8;
                    float v0 = acc[mt][nt][rr*2+0] + b0v;
                    float v1 = acc[mt][nt][rr*2+1] + b1v;
                    if (EPI == 1 || EPI == 4) {
                        float2 rv = *(const float2*)(res + (size_t)r * N + col);
                        v0 += rv.x; v1 += rv.y;
                    }
                    if (EPI == 2) {
                        v0 = 0.5f * v0 * (1.f + erff(v0 * 0.70710678118654752f));
                        v1 = 0.5f * v1 * (1.f + erff(v1 * 0.70710678118654752f));
                    }
                    if (EPI == 3) {
                        v0 = (v0 >= 0.f) ? v0 : 0.2f * v0;
                        v1 = (v1 >= 0.f) ? v1 : 0.2f * v1;
                    }
                    if (EPI == 4) {
                        const float* sb = sgate + (r >> 16) * C_;
                        float2 yv = *(const float2*)(yy + (size_t)r * N + col);
                        v0 += yv.x * sb[col];
                        v1 += yv.y * sb[col + 1];
                    }
                    if (OUTP) {
                        uint32_t hi, lo;
                        split2(v0, v1, hi, lo);
                        *(uint32_t*)(outh + (size_t)r * N + col) = hi;
                        *(uint32_t*)(outl + (size_t)r * N + col) = lo;
                    } else {
                        *(float2*)(out + (size_t)r * N + col) = make_float2(v0, v1);
                    }
                }
            }
        }
    }
#undef ISSUE
}

template<int EPI, int OUTP>
__global__ __launch_bounds__(256, 2) void gemm_cp(const __nv_bfloat16* __restrict__ Ah,
                                                  const __nv_bfloat16* __restrict__ Al,
                                                  const __nv_bfloat16* __restrict__ Wh,
                                                  const __nv_bfloat16* __restrict__ Wl,
                                                  const float* __restrict__ bias,
                                                  const float* __restrict__ res,
                                                  const float* __restrict__ yy,
                                                  const float* __restrict__ sgate,
                                                  float* __restrict__ out,
                                                  __nv_bfloat16* __restrict__ outh,
                                                  __nv_bfloat16* __restrict__ outl,
                                                  int N, int K) {
    extern __shared__ char smem[];
    gemm_body<EPI, OUTP>(Ah, Al, Wh, Wl, bias, res, yy, sgate, out, outh, outl, N, K, smem);
}

// ---------------- weight split ---------------------------------------------
__global__ __launch_bounds__(256) void split_kernel(const float* __restrict__ s,
                                                    __nv_bfloat16* __restrict__ h,
                                                    __nv_bfloat16* __restrict__ l,
                                                    int n) {
    int i = blockIdx.x * 256 + threadIdx.x;
    if (i < n) {
        float v = s[i];
        __nv_bfloat16 hv = __float2bfloat16(v);
        h[i] = hv;
        l[i] = __float2bfloat16(v - __bfloat162float(hv));
    }
}

// ---------------- LayerNorm -> bf16 planes ---------------------------------
__global__ __launch_bounds__(256) void ln_split_kernel(const float* __restrict__ x,
                                                       const float* __restrict__ g,
                                                       const float* __restrict__ b,
                                                       __nv_bfloat16* __restrict__ oh,
                                                       __nv_bfloat16* __restrict__ ol) {
    int token = blockIdx.x * 8 + (threadIdx.x >> 5);
    int lane  = threadIdx.x & 31;
    const float* p = x + (size_t)token * C_;
    float v[6];
    float s = 0.f;
    #pragma unroll
    for (int j = 0; j < 6; j++) { v[j] = p[lane + 32*j]; s += v[j]; }
    #pragma unroll
    for (int o = 16; o > 0; o >>= 1) s += __shfl_xor_sync(0xffffffffu, s, o);
    float mean = s * (1.f / C_);
    float q = 0.f;
    #pragma unroll
    for (int j = 0; j < 6; j++) { float d = v[j] - mean; q += d * d; }
    #pragma unroll
    for (int o = 16; o > 0; o >>= 1) q += __shfl_xor_sync(0xffffffffu, q, o);
    float rstd = rsqrtf(q * (1.f / C_) + 1e-5f);
    #pragma unroll
    for (int j = 0; j < 6; j++) {
        int c = lane + 32*j;
        float val = (v[j] - mean) * rstd * g[c] + b[c];
        __nv_bfloat16 hv = __float2bfloat16(val);
        oh[(size_t)token * C_ + c] = hv;
        ol[(size_t)token * C_ + c] = __float2bfloat16(val - __bfloat162float(hv));
    }
}

// ---------------- Windowed attention, one block per window ----------------
__global__ __launch_bounds__(256) void attn_kernel(const float* __restrict__ qkv,
                                                   const float* __restrict__ rpb,
                                                   __nv_bfloat16* __restrict__ aoh,
                                                   __nv_bfloat16* __restrict__ aol) {
    __shared__ int   gidx[64];
    __shared__ int   rid [64];
    __shared__ float qs[64][33];
    __shared__ float ks[64][33];
    __shared__ float vs[64][36];
    __shared__ float Sm[64][65];

    int tid = threadIdx.x;
    int wid = blockIdx.x;
    int b   = wid >> 10;
    int wib = wid & 1023;
    int wh  = wib >> 5;
    int ww  = wib & 31;

    if (tid < 64) {
        int ih = tid >> 3, iw = tid & 7;
        int h = wh * 8 + ih, w = ww * 8 + iw;
        int hs = (h + SHIFT) & (H_ - 1);
        int ws2 = (w + SHIFT) & (W_ - 1);
        gidx[tid] = b * L_ + hs * W_ + ws2;
        int rh = (h < H_ - WS) ? 0 : ((h < H_ - SHIFT) ? 1 : 2);
        int rw = (w < W_ - WS) ? 0 : ((w < W_ - SHIFT) ? 1 : 2);
        rid[tid] = rh * 3 + rw;
    }
    __syncthreads();

    const float SCALE = 0.17677669529663687f;
    int i  = tid >> 2;
    int jb = (tid & 3) * 16;
    int ihi = i >> 3, iwi = i & 7;
    int r_out = tid >> 2;
    int db    = (tid & 3) * 8;

    for (int h = 0; h < NH; h++) {
        for (int e = tid; e < 6144; e += 256) {
            int mat = e >> 11;
            int rem = e & 2047;
            int t = rem >> 5, d = rem & 31;
            float v = qkv[(size_t)gidx[t] * (3*C_) + mat * C_ + h * HD + d];
            if (mat == 0)      qs[t][d] = v * SCALE;
            else if (mat == 1) ks[t][d] = v;
            else               vs[t][d] = v;
        }
        __syncthreads();

        float qrow[32];
        #pragma unroll
        for (int kk = 0; kk < 32; kk++) qrow[kk] = qs[i][kk];
        int ridi = rid[i];
        float ex[16];
        float mx = -1e30f;
        #pragma unroll
        for (int jj = 0; jj < 16; jj++) {
            int j = jb + jj;
            float s = 0.f;
            #pragma unroll
            for (int kk = 0; kk < 32; kk++) s += qrow[kk] * ks[j][kk];
            int jh = j >> 3, jw = j & 7;
            int rel = (ihi - jh + 7) * 15 + (iwi - jw + 7);
            s += rpb[rel * NH + h];
            if (ridi != rid[j]) s -= 100.f;
            ex[jj] = s;
            mx = fmaxf(mx, s);
        }
        mx = fmaxf(mx, __shfl_xor_sync(0xffffffffu, mx, 1));
        mx = fmaxf(mx, __shfl_xor_sync(0xffffffffu, mx, 2));
        float sum = 0.f;
        #pragma unroll
        for (int jj = 0; jj < 16; jj++) { ex[jj] = expf(ex[jj] - mx); sum += ex[jj]; }
        sum += __shfl_xor_sync(0xffffffffu, sum, 1);
        sum += __shfl_xor_sync(0xffffffffu, sum, 2);
        float inv = 1.f / sum;
        #pragma unroll
        for (int jj = 0; jj < 16; jj++) Sm[i][jb + jj] = ex[jj] * inv;
        __syncthreads();

        float oacc[8];
        #pragma unroll
        for (int d = 0; d < 8; d++) oacc[d] = 0.f;
        for (int m = 0; m < 64; m++) {
            float sv = Sm[r_out][m];
            float4 v0 = *(const float4*)&vs[m][db];
            float4 v1 = *(const float4*)&vs[m][db + 4];
            oacc[0] += sv * v0.x; oacc[1] += sv * v0.y;
            oacc[2] += sv * v0.z; oacc[3] += sv * v0.w;
            oacc[4] += sv * v1.x; oacc[5] += sv * v1.y;
            oacc[6] += sv * v1.z; oacc[7] += sv * v1.w;
        }
        size_t off = (size_t)gidx[r_out] * C_ + h * HD + db;
        #pragma unroll
        for (int d = 0; d < 8; d += 2) {
            uint32_t hi, lo;
            split2(oacc[d], oacc[d + 1], hi, lo);
            *(uint32_t*)(aoh + off + d) = hi;
            *(uint32_t*)(aol + off + d) = lo;
        }
        __syncthreads();
    }
}

// ---------------- 3x3 conv on r=24 channels, NHWC, pad 1 -------------------
__global__ __launch_bounds__(64) void conv3_kernel(const float* __restrict__ yin,
                                                   const float* __restrict__ w,
                                                   const float* __restrict__ bias,
                                                   __nv_bfloat16* __restrict__ yh,
                                                   __nv_bfloat16* __restrict__ yl) {
    __shared__ float patch[100][RED_];
    __shared__ float wts[RED_ * RED_ * 9];
    int tid = threadIdx.x;
    int b = blockIdx.z;
    int th0 = blockIdx.y * 8, tw0 = blockIdx.x * 8;

    for (int d = tid; d < RED_ * RED_ * 9; d += 64) {
        int oc = d % RED_;
        int t2 = d / RED_;
        int kk = t2 % 9;
        int ic = t2 / 9;
        wts[d] = w[(oc * RED_ + ic) * 9 + kk];
    }
    for (int d = tid; d < 100 * RED_; d += 64) {
        int ic = d % RED_;
        int pos = d / RED_;
        int ph = pos / 10, pw = pos % 10;
        int hh = th0 + ph - 1, ww = tw0 + pw - 1;
        float v = 0.f;
        if (hh >= 0 && hh < H_ && ww >= 0 && ww < W_)
            v = yin[((size_t)b * L_ + hh * W_ + ww) * RED_ + ic];
        patch[pos][ic] = v;
    }
    __syncthreads();

    int py = tid >> 3, px = tid & 7;
    float acc[RED_];
    #pragma unroll
    for (int oc = 0; oc < RED_; oc++) acc[oc] = __ldg(bias + oc);
    for (int ic = 0; ic < RED_; ic++) {
        #pragma unroll
        for (int kk = 0; kk < 9; kk++) {
            int kh = kk / 3, kw = kk % 3;
            float pv = patch[(py + kh) * 10 + (px + kw)][ic];
            const float4* wp = (const float4*)&wts[(ic * 9 + kk) * RED_];
            #pragma unroll
            for (int o4 = 0; o4 < 6; o4++) {
                float4 wv = wp[o4];
                acc[o4*4+0] += wv.x * pv; acc[o4*4+1] += wv.y * pv;
                acc[o4*4+2] += wv.z * pv; acc[o4*4+3] += wv.w * pv;
            }
        }
    }
    size_t off = ((size_t)b * L_ + (th0 + py) * W_ + (tw0 + px)) * RED_;
    #pragma unroll
    for (int oc = 0; oc < RED_; oc += 2) {
        uint32_t hi, lo;
        split2(acc[oc], acc[oc + 1], hi, lo);
        *(uint32_t*)(yh + off + oc) = hi;
        *(uint32_t*)(yl + off + oc) = lo;
    }
}

// ---------------- pool / SE ------------------------------------------------
__global__ void zero_pool_kernel(float* pool) {
    if (threadIdx.x < B_ * C_) pool[threadIdx.x] = 0.f;
}

__global__ __launch_bounds__(192) void pool_kernel(const float* __restrict__ y,
                                                   float* __restrict__ pool) {
    int base = blockIdx.x * 128;
    int b = base >> 16;
    int c = threadIdx.x;
    float acc = 0.f;
    for (int i = 0; i < 128; i++)
        acc += y[(size_t)(base + i) * C_ + c];
    atomicAdd(&pool[b * C_ + c], acc);
}

__global__ __launch_bounds__(192) void se_kernel(const float* __restrict__ pool,
                                                 const float* __restrict__ fc1,
                                                 const float* __restrict__ fc2,
                                                 float* __restrict__ sbuf) {
    __shared__ float t[RED_];
    int tid = threadIdx.x;
    const float inv = 1.f / (float)L_;
    for (int b = 0; b < B_; b++) {
        if (tid < RED_) {
            float s = 0.f;
            for (int c = 0; c < C_; c++)
                s += pool[b * C_ + c] * inv * fc1[tid * C_ + c];
            t[tid] = fmaxf(s, 0.f);
        }
        __syncthreads();
        float s = 0.f;
        #pragma unroll
        for (int j = 0; j < RED_; j++) s += t[j] * fc2[tid * RED_ + j];
        sbuf[b * C_ + tid] = 1.f / (1.f + expf(-s));
        __syncthreads();
    }
}

// ---------------- launch ---------------------------------------------------
extern "C" void kernel_launch(void* const* d_in, const int* in_sizes, int n_in,
                              void* d_out, int out_size) {
    const float* x      = (const float*)d_in[0];
    const float* n1g    = (const float*)d_in[1];
    const float* n1b    = (const float*)d_in[2];
    const float* qkvw   = (const float*)d_in[3];
    const float* qkvb   = (const float*)d_in[4];
    const float* rpb    = (const float*)d_in[5];
    const float* projw  = (const float*)d_in[6];
    const float* projb  = (const float*)d_in[7];
    const float* n2g    = (const float*)d_in[8];
    const float* n2b    = (const float*)d_in[9];
    const float* fc1w   = (const float*)d_in[10];
    const float* fc1b   = (const float*)d_in[11];
    const float* fc2w   = (const float*)d_in[12];
    const float* fc2b   = (const float*)d_in[13];
    const float* c1w    = (const float*)d_in[14];
    const float* c1b    = (const float*)d_in[15];
    const float* c2w    = (const float*)d_in[16];
    const float* c2b    = (const float*)d_in[17];
    const float* c3w    = (const float*)d_in[18];
    const float* c3b    = (const float*)d_in[19];
    const float* sfc1   = (const float*)d_in[20];
    const float* sfc2   = (const float*)d_in[21];
    float* out = (float*)d_out;

    float *qkv, *x1, *y1, *y, *pool, *sbuf;
    cudaGetSymbolAddress((void**)&qkv,  g_qkv);
    cudaGetSymbolAddress((void**)&x1,   g_x1);
    cudaGetSymbolAddress((void**)&y1,   g_y1);
    cudaGetSymbolAddress((void**)&y,    g_y);
    cudaGetSymbolAddress((void**)&pool, g_pool);
    cudaGetSymbolAddress((void**)&sbuf, g_s);
    __nv_bfloat16 *xnh, *xnl, *aoh, *aol, *x1nh, *x1nl, *hbh, *hbl, *y2h, *y2l;
    __nv_bfloat16 *wqh, *wql, *wph, *wpl, *w1h, *w1l, *w2h, *w2l, *wc1h, *wc1l, *wc3h, *wc3l;
    cudaGetSymbolAddress((void**)&xnh,  g_xnh);  cudaGetSymbolAddress((void**)&xnl,  g_xnl);
    cudaGetSymbolAddress((void**)&aoh,  g_aoh);  cudaGetSymbolAddress((void**)&aol,  g_aol);
    cudaGetSymbolAddress((void**)&x1nh, g_x1nh); cudaGetSymbolAddress((void**)&x1nl, g_x1nl);
    cudaGetSymbolAddress((void**)&hbh,  g_hbh);  cudaGetSymbolAddress((void**)&hbl,  g_hbl);
    cudaGetSymbolAddress((void**)&y2h,  g_y2h);  cudaGetSymbolAddress((void**)&y2l,  g_y2l);
    cudaGetSymbolAddress((void**)&wqh,  g_wqh);  cudaGetSymbolAddress((void**)&wql,  g_wql);
    cudaGetSymbolAddress((void**)&wph,  g_wph);  cudaGetSymbolAddress((void**)&wpl,  g_wpl);
    cudaGetSymbolAddress((void**)&w1h,  g_w1h);  cudaGetSymbolAddress((void**)&w1l,  g_w1l);
    cudaGetSymbolAddress((void**)&w2h,  g_w2h);  cudaGetSymbolAddress((void**)&w2l,  g_w2l);
    cudaGetSymbolAddress((void**)&wc1h, g_wc1h); cudaGetSymbolAddress((void**)&wc1l, g_wc1l);
    cudaGetSymbolAddress((void**)&wc3h, g_wc3h); cudaGetSymbolAddress((void**)&wc3l, g_wc3l);

    cudaFuncSetAttribute(gemm_cp<0,0>, cudaFuncAttributeMaxDynamicSharedMemorySize, GEMM_SMEM_SZ);
    cudaFuncSetAttribute(gemm_cp<1,0>, cudaFuncAttributeMaxDynamicSharedMemorySize, GEMM_SMEM_SZ);
    cudaFuncSetAttribute(gemm_cp<2,1>, cudaFuncAttributeMaxDynamicSharedMemorySize, GEMM_SMEM_SZ);
    cudaFuncSetAttribute(gemm_cp<3,0>, cudaFuncAttributeMaxDynamicSharedMemorySize, GEMM_SMEM_SZ);
    cudaFuncSetAttribute(gemm_cp<4,0>, cudaFuncAttributeMaxDynamicSharedMemorySize, GEMM_SMEM_SZ);

    // 0) weight splits
    split_kernel<<<(3*C_*C_+255)/256, 256>>>(qkvw, wqh, wql, 3*C_*C_);
    split_kernel<<<(C_*C_+255)/256, 256>>>(projw, wph, wpl, C_*C_);
    split_kernel<<<(HID_*C_+255)/256, 256>>>(fc1w, w1h, w1l, HID_*C_);
    split_kernel<<<(C_*HID_+255)/256, 256>>>(fc2w, w2h, w2l, C_*HID_);
    split_kernel<<<(RED_*C_+255)/256, 256>>>(c1w, wc1h, wc1l, RED_*C_);
    split_kernel<<<(C_*RED_+255)/256, 256>>>(c3w, wc3h, wc3l, C_*RED_);
    // 1) LN1 -> planes
    ln_split_kernel<<<M_/8, 256>>>(x, n1g, n1b, xnh, xnl);
    // 2) QKV GEMM
    gemm_cp<0,0><<<dim3(9, M_/128), 256, GEMM_SMEM_SZ>>>(xnh, xnl, wqh, wql, qkvb, nullptr, nullptr, nullptr, qkv, nullptr, nullptr, 3*C_, C_);
    // 3) attention -> ao planes
    attn_kernel<<<NWIN, 256>>>(qkv, rpb, aoh, aol);
    // 4) proj + residual -> x1 (fp32)
    gemm_cp<1,0><<<dim3(3, M_/128), 256, GEMM_SMEM_SZ>>>(aoh, aol, wph, wpl, projb, x, nullptr, nullptr, x1, nullptr, nullptr, C_, C_);
    // 5) LN2 -> planes
    ln_split_kernel<<<M_/8, 256>>>(x1, n2g, n2b, x1nh, x1nl);
    // 6) fc1 + GELU -> hb planes
    gemm_cp<2,1><<<dim3(12, M_/128), 256, GEMM_SMEM_SZ>>>(x1nh, x1nl, w1h, w1l, fc1b, nullptr, nullptr, nullptr, nullptr, hbh, hbl, HID_, C_);
    // 7) LCE conv1x1 C->24 -> y1 fp32
    gemm_cp<0,0><<<dim3(1, M_/128), 256, GEMM_SMEM_SZ>>>(xnh, xnl, wc1h, wc1l, c1b, nullptr, nullptr, nullptr, y1, nullptr, nullptr, RED_, C_);
    // 8) LCE conv3x3 -> y2 planes
    conv3_kernel<<<dim3(W_/8, H_/8, B_), 64>>>(y1, c2w, c2b, y2h, y2l);
    // 9) LCE conv1x1 24->192 + LeakyReLU -> y fp32
    gemm_cp<3,0><<<dim3(3, M_/128), 256, GEMM_SMEM_SZ>>>(y2h, y2l, wc3h, wc3l, c3b, nullptr, nullptr, nullptr, y, nullptr, nullptr, C_, RED_);
    // 10) global avg pool + SE gate
    zero_pool_kernel<<<1, 384>>>(pool);
    pool_kernel<<<M_/128, 192>>>(y, pool);
    se_kernel<<<1, 192>>>(pool, sfc1, sfc2, sbuf);
    // 11) fc2 + residual + SE-gated local context -> out (fused final)
    gemm_cp<4,0><<<dim3(3, M_/128), 256, GEMM_SMEM_SZ>>>(hbh, hbl, w2h, w2l, fc2b, x1, y, sbuf, out, nullptr, nullptr, C_, HID_);
}

// round 9
// speedup vs baseline: 3.2287x; 1.1929x over previous
#include <cuda_runtime.h>
#include <cuda_fp16.h>
#include <math.h>
#include <stdint.h>

#define B_    2
#define H_    256
#define W_    256
#define C_    192
#define L_    (H_*W_)         // 65536
#define M_    (B_*L_)         // 131072
#define HID_  768
#define NH    6
#define HD    32
#define WS    8
#define SHIFT 4
#define NWIN  (B_*(H_/WS)*(W_/WS))  // 2048
#define RED_  24

// ---------------- scratch (device globals; no allocations) ----------------
__device__ float g_qkv[M_*3*C_];
__device__ float g_x1 [M_*C_];
__device__ float g_y1 [M_*RED_];
__device__ float g_y  [M_*C_];
__device__ float g_pool[B_*C_];
__device__ float g_s  [B_*C_];
// fp16 activation planes (single)
__device__ __half g_xn16 [M_*C_];
__device__ __half g_ao16 [M_*C_];
__device__ __half g_x1n16[M_*C_];
__device__ __half g_hb16 [(size_t)M_*HID_];
__device__ __half g_y216 [M_*RED_];
// fp16 weight hi/lo planes
__device__ __half g_wqh [3*C_*C_],  g_wql [3*C_*C_];
__device__ __half g_wph [C_*C_],    g_wpl [C_*C_];
__device__ __half g_w1h [HID_*C_],  g_w1l [HID_*C_];
__device__ __half g_w2h [C_*HID_],  g_w2l [C_*HID_];
__device__ __half g_wc1h[RED_*C_],  g_wc1l[RED_*C_];
__device__ __half g_wc3h[C_*RED_],  g_wc3l[C_*RED_];

// ======================= helpers ===========================================
__device__ __forceinline__ uint32_t smem_to_u32(const void* p) {
    uint32_t a;
    asm("{ .reg .u64 t; cvta.to.shared.u64 t, %1; cvt.u32.u64 %0, t; }" : "=r"(a) : "l"(p));
    return a;
}
__device__ __forceinline__ uint32_t pack_h2(float x, float y) {
    __half2 h = __floats2half2_rn(x, y);
    return *reinterpret_cast<uint32_t*>(&h);
}
#define LDSM4(r, addr) \
    asm volatile("ldmatrix.sync.aligned.m8n8.x4.shared.b16 {%0,%1,%2,%3}, [%4];" \
        : "=r"((r)[0]), "=r"((r)[1]), "=r"((r)[2]), "=r"((r)[3]) : "r"(addr))
#define MMA_F16(d, a, b0, b1) \
    asm volatile("mma.sync.aligned.m16n8k16.row.col.f32.f16.f16.f32 " \
        "{%0,%1,%2,%3},{%4,%5,%6,%7},{%8,%9},{%0,%1,%2,%3};" \
        : "+f"((d)[0]), "+f"((d)[1]), "+f"((d)[2]), "+f"((d)[3]) \
        : "r"((a)[0]), "r"((a)[1]), "r"((a)[2]), "r"((a)[3]), "r"(b0), "r"(b1))
#define CP_ASYNC(dst, src, sz) \
    asm volatile("cp.async.cg.shared.global [%0], [%1], 16, %2;" \
        :: "r"(dst), "l"(src), "r"(sz))
#define CP_COMMIT() asm volatile("cp.async.commit_group;" ::: "memory")

// ======================= fp16 Wx2 mma.sync GEMM (cp.async 4-stage) =========
// out[M,N] = epi(A @ W^T + bias); A single fp16 plane, W fp16 hi/lo planes.
// CTA tile 128x64, BK=32. 2 passes: A*Whi + A*Wlo, fp32 accumulate.
// EPI: 0 none, 1 +res, 2 exact GELU, 3 LeakyReLU(0.2),
//      4 +res + gate (out = v + res + yy*s[b,col]). OUTP: 1 = write fp16 plane.
#define STG_STRIDE 20480   // A 10240 | Whi 5120 | Wlo 5120
#define W_HI 10240
#define NSTG 4
#define GEMM_SMEM_SZ (NSTG*STG_STRIDE)   // 81920

template<int EPI, int OUTP>
__device__ __forceinline__ void gemm_body(const __half* __restrict__ A16,
                                          const __half* __restrict__ Wh,
                                          const __half* __restrict__ Wl,
                                          const float* __restrict__ bias,
                                          const float* __restrict__ res,
                                          const float* __restrict__ yy,
                                          const float* __restrict__ sgate,
                                          float* __restrict__ out,
                                          __half* __restrict__ out16,
                                          int N, int K, char* smem) {
    const int tid  = threadIdx.x;
    const int lane = tid & 31;
    const int warp = tid >> 5;
    const int m0 = blockIdx.y * 128, n0 = blockIdx.x * 64;
    const int wm = (warp & 3) * 32, wn = (warp >> 2) * 32;
    const int nch = (K + 31) >> 5;

#define ISSUE(stg, c) do { \
    char* base_ = smem + (stg) * STG_STRIDE; \
    int k0_ = (c) * 32; \
    _Pragma("unroll") \
    for (int i = 0; i < 2; i++) { \
        int t = tid + i * 256; \
        int row = t >> 2, seg = t & 3; \
        int ke = k0_ + seg * 8; \
        int srcsz = (K - ke) * 2; \
        srcsz = srcsz < 0 ? 0 : (srcsz > 16 ? 16 : srcsz); \
        const __half* g = A16 + (size_t)(m0 + row) * K + (srcsz ? ke : 0); \
        uint32_t d = smem_to_u32(base_ + row * 80 + seg * 16); \
        CP_ASYNC(d, g, srcsz); \
    } \
    _Pragma("unroll") \
    for (int i = 0; i < 2; i++) { \
        const __half* gp = i ? Wl : Wh; \
        int row = tid >> 2, seg = tid & 3; \
        int ke = k0_ + seg * 8; \
        int srcsz = (K - ke) * 2; \
        srcsz = srcsz < 0 ? 0 : (srcsz > 16 ? 16 : srcsz); \
        if (n0 + row >= N) srcsz = 0; \
        int grow = (n0 + row < N) ? (n0 + row) : 0; \
        const __half* g = gp + (size_t)grow * K + (srcsz ? ke : 0); \
        uint32_t d = smem_to_u32(base_ + W_HI + i * 5120 + row * 80 + seg * 16); \
        CP_ASYNC(d, g, srcsz); \
    } \
    CP_COMMIT(); } while (0)

    float acc[2][4][4];
    #pragma unroll
    for (int i = 0; i < 2; i++)
        #pragma unroll
        for (int j = 0; j < 4; j++)
            #pragma unroll
            for (int q = 0; q < 4; q++) acc[i][j][q] = 0.f;

    ISSUE(0, 0);
    if (nch > 1) ISSUE(1, 1);
    if (nch > 2) ISSUE(2, 2);

    int sc = 0;
    for (int c = 0; c < nch; c++) {
        int rem = nch - 1 - c;
        if (rem >= 2)      asm volatile("cp.async.wait_group 2;" ::: "memory");
        else if (rem == 1) asm volatile("cp.async.wait_group 1;" ::: "memory");
        else               asm volatile("cp.async.wait_group 0;" ::: "memory");
        __syncthreads();
        char* base = smem + sc * STG_STRIDE;
        #pragma unroll
        for (int ks = 0; ks < 2; ks++) {
            uint32_t af[2][4], whf[2][4], wlf[2][4];
            #pragma unroll
            for (int mt = 0; mt < 2; mt++) {
                int row = wm + mt * 16 + (lane & 15);
                int colb = ks * 32 + ((lane >> 4) & 1) * 16;
                LDSM4(af[mt], smem_to_u32(base + row * 80 + colb));
            }
            #pragma unroll
            for (int np = 0; np < 2; np++) {
                int n = wn + np * 16 + (lane & 7) + ((lane >> 4) & 1) * 8;
                int colb = ks * 32 + ((lane >> 3) & 1) * 16;
                uint32_t wd = smem_to_u32(base + W_HI + n * 80 + colb);
                LDSM4(whf[np], wd);
                LDSM4(wlf[np], wd + 5120);
            }
            #pragma unroll
            for (int pass = 0; pass < 2; pass++)
                #pragma unroll
                for (int mt = 0; mt < 2; mt++)
                    #pragma unroll
                    for (int nt = 0; nt < 4; nt++) {
                        int np = nt >> 1, h = (nt & 1) * 2;
                        const uint32_t (*wf)[4] = pass ? wlf : whf;
                        MMA_F16(acc[mt][nt], af[mt], wf[np][h], wf[np][h+1]);
                    }
        }
        if (c + 3 < nch) {
            int si = sc + 3; if (si >= NSTG) si -= NSTG;
            ISSUE(si, c + 3);
        }
        sc = (sc + 1 == NSTG) ? 0 : sc + 1;
    }

    // ---- epilogue ----
    #pragma unroll
    for (int mt = 0; mt < 2; mt++) {
        int r0 = m0 + wm + mt * 16 + (lane >> 2);
        #pragma unroll
        for (int nt = 0; nt < 4; nt++) {
            int col = n0 + wn + nt * 8 + (lane & 3) * 2;
            if (col < N) {
                float b0v = bias[col], b1v = bias[col + 1];
                #pragma unroll
                for (int rr = 0; rr < 2; rr++) {
                    int r = r0 + rr * 8;
                    float v0 = acc[mt][nt][rr*2+0] + b0v;
                    float v1 = acc[mt][nt][rr*2+1] + b1v;
                    if (EPI == 1 || EPI == 4) {
                        float2 rv = *(const float2*)(res + (size_t)r * N + col);
                        v0 += rv.x; v1 += rv.y;
                    }
                    if (EPI == 2) {
                        v0 = 0.5f * v0 * (1.f + erff(v0 * 0.70710678118654752f));
                        v1 = 0.5f * v1 * (1.f + erff(v1 * 0.70710678118654752f));
                    }
                    if (EPI == 3) {
                        v0 = (v0 >= 0.f) ? v0 : 0.2f * v0;
                        v1 = (v1 >= 0.f) ? v1 : 0.2f * v1;
                    }
                    if (EPI == 4) {
                        const float* sb = sgate + (r >> 16) * C_;
                        float2 yv = *(const float2*)(yy + (size_t)r * N + col);
                        v0 += yv.x * sb[col];
                        v1 += yv.y * sb[col + 1];
                    }
                    if (OUTP) {
                        *(uint32_t*)(out16 + (size_t)r * N + col) = pack_h2(v0, v1);
                    } else {
                        *(float2*)(out + (size_t)r * N + col) = make_float2(v0, v1);
                    }
                }
            }
        }
    }
#undef ISSUE
}

template<int EPI, int OUTP>
__global__ __launch_bounds__(256, 2) void gemm_cp(const __half* __restrict__ A16,
                                                  const __half* __restrict__ Wh,
                                                  const __half* __restrict__ Wl,
                                                  const float* __restrict__ bias,
                                                  const float* __restrict__ res,
                                                  const float* __restrict__ yy,
                                                  const float* __restrict__ sgate,
                                                  float* __restrict__ out,
                                                  __half* __restrict__ out16,
                                                  int N, int K) {
    extern __shared__ char smem[];
    gemm_body<EPI, OUTP>(A16, Wh, Wl, bias, res, yy, sgate, out, out16, N, K, smem);
}

// ---------------- merged weight split (6 tensors, one launch) --------------
#define S0 (3*C_*C_)
#define S1 (C_*C_)
#define S2 (HID_*C_)
#define S3 (C_*HID_)
#define S4 (RED_*C_)
#define S5 (C_*RED_)
#define STOT (S0+S1+S2+S3+S4+S5)
__global__ __launch_bounds__(256) void split_all_kernel(
        const float* __restrict__ w0, const float* __restrict__ w1,
        const float* __restrict__ w2, const float* __restrict__ w3,
        const float* __restrict__ w4, const float* __restrict__ w5,
        __half* h0, __half* l0, __half* h1, __half* l1,
        __half* h2, __half* l2, __half* h3, __half* l3,
        __half* h4, __half* l4, __half* h5, __half* l5) {
    int i = blockIdx.x * 256 + threadIdx.x;
    const float* s; __half *h, *l; int off;
    if      (i < S0)                { s = w0; h = h0; l = l0; off = i; }
    else if (i < S0+S1)             { s = w1; h = h1; l = l1; off = i - S0; }
    else if (i < S0+S1+S2)          { s = w2; h = h2; l = l2; off = i - S0-S1; }
    else if (i < S0+S1+S2+S3)       { s = w3; h = h3; l = l3; off = i - S0-S1-S2; }
    else if (i < S0+S1+S2+S3+S4)    { s = w4; h = h4; l = l4; off = i - S0-S1-S2-S3; }
    else if (i < STOT)              { s = w5; h = h5; l = l5; off = i - S0-S1-S2-S3-S4; }
    else return;
    float v = s[off];
    __half hv = __float2half_rn(v);
    h[off] = hv;
    l[off] = __float2half_rn(v - __half2float(hv));
}

// ---------------- LayerNorm -> single fp16 plane ---------------------------
__global__ __launch_bounds__(256) void ln16_kernel(const float* __restrict__ x,
                                                   const float* __restrict__ g,
                                                   const float* __restrict__ b,
                                                   __half* __restrict__ o16) {
    int token = blockIdx.x * 8 + (threadIdx.x >> 5);
    int lane  = threadIdx.x & 31;
    const float* p = x + (size_t)token * C_;
    float v[6];
    float s = 0.f;
    #pragma unroll
    for (int j = 0; j < 6; j++) { v[j] = p[lane + 32*j]; s += v[j]; }
    #pragma unroll
    for (int o = 16; o > 0; o >>= 1) s += __shfl_xor_sync(0xffffffffu, s, o);
    float mean = s * (1.f / C_);
    float q = 0.f;
    #pragma unroll
    for (int j = 0; j < 6; j++) { float d = v[j] - mean; q += d * d; }
    #pragma unroll
    for (int o = 16; o > 0; o >>= 1) q += __shfl_xor_sync(0xffffffffu, q, o);
    float rstd = rsqrtf(q * (1.f / C_) + 1e-5f);
    #pragma unroll
    for (int j = 0; j < 6; j++) {
        int c = lane + 32*j;
        o16[(size_t)token * C_ + c] = __float2half_rn((v[j] - mean) * rstd * g[c] + b[c]);
    }
}

// ---------------- Windowed attention, one block per window ----------------
__global__ __launch_bounds__(256) void attn_kernel(const float* __restrict__ qkv,
                                                   const float* __restrict__ rpb,
                                                   __half* __restrict__ ao16) {
    __shared__ int   gidx[64];
    __shared__ int   rid [64];
    __shared__ float qs[64][33];
    __shared__ float ks[64][33];
    __shared__ float vs[64][36];
    __shared__ float Sm[64][65];

    int tid = threadIdx.x;
    int wid = blockIdx.x;
    int b   = wid >> 10;
    int wib = wid & 1023;
    int wh  = wib >> 5;
    int ww  = wib & 31;

    if (tid < 64) {
        int ih = tid >> 3, iw = tid & 7;
        int h = wh * 8 + ih, w = ww * 8 + iw;
        int hs = (h + SHIFT) & (H_ - 1);
        int ws2 = (w + SHIFT) & (W_ - 1);
        gidx[tid] = b * L_ + hs * W_ + ws2;
        int rh = (h < H_ - WS) ? 0 : ((h < H_ - SHIFT) ? 1 : 2);
        int rw = (w < W_ - WS) ? 0 : ((w < W_ - SHIFT) ? 1 : 2);
        rid[tid] = rh * 3 + rw;
    }
    __syncthreads();

    const float SCALE = 0.17677669529663687f;
    int i  = tid >> 2;
    int jb = (tid & 3) * 16;
    int ihi = i >> 3, iwi = i & 7;
    int r_out = tid >> 2;
    int db    = (tid & 3) * 8;

    for (int h = 0; h < NH; h++) {
        for (int e = tid; e < 6144; e += 256) {
            int mat = e >> 11;
            int rem = e & 2047;
            int t = rem >> 5, d = rem & 31;
            float v = qkv[(size_t)gidx[t] * (3*C_) + mat * C_ + h * HD + d];
            if (mat == 0)      qs[t][d] = v * SCALE;
            else if (mat == 1) ks[t][d] = v;
            else               vs[t][d] = v;
        }
        __syncthreads();

        float qrow[32];
        #pragma unroll
        for (int kk = 0; kk < 32; kk++) qrow[kk] = qs[i][kk];
        int ridi = rid[i];
        float ex[16];
        float mx = -1e30f;
        #pragma unroll
        for (int jj = 0; jj < 16; jj++) {
            int j = jb + jj;
            float s = 0.f;
            #pragma unroll
            for (int kk = 0; kk < 32; kk++) s += qrow[kk] * ks[j][kk];
            int jh = j >> 3, jw = j & 7;
            int rel = (ihi - jh + 7) * 15 + (iwi - jw + 7);
            s += rpb[rel * NH + h];
            if (ridi != rid[j]) s -= 100.f;
            ex[jj] = s;
            mx = fmaxf(mx, s);
        }
        mx = fmaxf(mx, __shfl_xor_sync(0xffffffffu, mx, 1));
        mx = fmaxf(mx, __shfl_xor_sync(0xffffffffu, mx, 2));
        float sum = 0.f;
        #pragma unroll
        for (int jj = 0; jj < 16; jj++) { ex[jj] = expf(ex[jj] - mx); sum += ex[jj]; }
        sum += __shfl_xor_sync(0xffffffffu, sum, 1);
        sum += __shfl_xor_sync(0xffffffffu, sum, 2);
        float inv = 1.f / sum;
        #pragma unroll
        for (int jj = 0; jj < 16; jj++) Sm[i][jb + jj] = ex[jj] * inv;
        __syncthreads();

        float oacc[8];
        #pragma unroll
        for (int d = 0; d < 8; d++) oacc[d] = 0.f;
        for (int m = 0; m < 64; m++) {
            float sv = Sm[r_out][m];
            float4 v0 = *(const float4*)&vs[m][db];
            float4 v1 = *(const float4*)&vs[m][db + 4];
            oacc[0] += sv * v0.x; oacc[1] += sv * v0.y;
            oacc[2] += sv * v0.z; oacc[3] += sv * v0.w;
            oacc[4] += sv * v1.x; oacc[5] += sv * v1.y;
            oacc[6] += sv * v1.z; oacc[7] += sv * v1.w;
        }
        size_t off = (size_t)gidx[r_out] * C_ + h * HD + db;
        #pragma unroll
        for (int d = 0; d < 8; d += 2)
            *(uint32_t*)(ao16 + off + d) = pack_h2(oacc[d], oacc[d + 1]);
        __syncthreads();
    }
}

// ---------------- 3x3 conv on r=24 channels, NHWC, pad 1 -------------------
__global__ __launch_bounds__(64) void conv3_kernel(const float* __restrict__ yin,
                                                   const float* __restrict__ w,
                                                   const float* __restrict__ bias,
                                                   __half* __restrict__ y16) {
    __shared__ float patch[100][RED_];
    __shared__ float wts[RED_ * RED_ * 9];
    int tid = threadIdx.x;
    int b = blockIdx.z;
    int th0 = blockIdx.y * 8, tw0 = blockIdx.x * 8;

    for (int d = tid; d < RED_ * RED_ * 9; d += 64) {
        int oc = d % RED_;
        int t2 = d / RED_;
        int kk = t2 % 9;
        int ic = t2 / 9;
        wts[d] = w[(oc * RED_ + ic) * 9 + kk];
    }
    for (int d = tid; d < 100 * RED_; d += 64) {
        int ic = d % RED_;
        int pos = d / RED_;
        int ph = pos / 10, pw = pos % 10;
        int hh = th0 + ph - 1, ww = tw0 + pw - 1;
        float v = 0.f;
        if (hh >= 0 && hh < H_ && ww >= 0 && ww < W_)
            v = yin[((size_t)b * L_ + hh * W_ + ww) * RED_ + ic];
        patch[pos][ic] = v;
    }
    __syncthreads();

    int py = tid >> 3, px = tid & 7;
    float acc[RED_];
    #pragma unroll
    for (int oc = 0; oc < RED_; oc++) acc[oc] = __ldg(bias + oc);
    for (int ic = 0; ic < RED_; ic++) {
        #pragma unroll
        for (int kk = 0; kk < 9; kk++) {
            int kh = kk / 3, kw = kk % 3;
            float pv = patch[(py + kh) * 10 + (px + kw)][ic];
            const float4* wp = (const float4*)&wts[(ic * 9 + kk) * RED_];
            #pragma unroll
            for (int o4 = 0; o4 < 6; o4++) {
                float4 wv = wp[o4];
                acc[o4*4+0] += wv.x * pv; acc[o4*4+1] += wv.y * pv;
                acc[o4*4+2] += wv.z * pv; acc[o4*4+3] += wv.w * pv;
            }
        }
    }
    size_t off = ((size_t)b * L_ + (th0 + py) * W_ + (tw0 + px)) * RED_;
    #pragma unroll
    for (int oc = 0; oc < RED_; oc += 2)
        *(uint32_t*)(y16 + off + oc) = pack_h2(acc[oc], acc[oc + 1]);
}

// ---------------- pool / SE ------------------------------------------------
__global__ void zero_pool_kernel(float* pool) {
    if (threadIdx.x < B_ * C_) pool[threadIdx.x] = 0.f;
}

__global__ __launch_bounds__(192) void pool_kernel(const float* __restrict__ y,
                                                   float* __restrict__ pool) {
    int base = blockIdx.x * 128;
    int b = base >> 16;
    int c = threadIdx.x;
    float acc = 0.f;
    for (int i = 0; i < 128; i++)
        acc += y[(size_t)(base + i) * C_ + c];
    atomicAdd(&pool[b * C_ + c], acc);
}

__global__ __launch_bounds__(192) void se_kernel(const float* __restrict__ pool,
                                                 const float* __restrict__ fc1,
                                                 const float* __restrict__ fc2,
                                                 float* __restrict__ sbuf) {
    __shared__ float t[RED_];
    int tid = threadIdx.x;
    const float inv = 1.f / (float)L_;
    for (int b = 0; b < B_; b++) {
        if (tid < RED_) {
            float s = 0.f;
            for (int c = 0; c < C_; c++)
                s += pool[b * C_ + c] * inv * fc1[tid * C_ + c];
            t[tid] = fmaxf(s, 0.f);
        }
        __syncthreads();
        float s = 0.f;
        #pragma unroll
        for (int j = 0; j < RED_; j++) s += t[j] * fc2[tid * RED_ + j];
        sbuf[b * C_ + tid] = 1.f / (1.f + expf(-s));
        __syncthreads();
    }
}

// ---------------- launch ---------------------------------------------------
extern "C" void kernel_launch(void* const* d_in, const int* in_sizes, int n_in,
                              void* d_out, int out_size) {
    const float* x      = (const float*)d_in[0];
    const float* n1g    = (const float*)d_in[1];
    const float* n1b    = (const float*)d_in[2];
    const float* qkvw   = (const float*)d_in[3];
    const float* qkvb   = (const float*)d_in[4];
    const float* rpb    = (const float*)d_in[5];
    const float* projw  = (const float*)d_in[6];
    const float* projb  = (const float*)d_in[7];
    const float* n2g    = (const float*)d_in[8];
    const float* n2b    = (const float*)d_in[9];
    const float* fc1w   = (const float*)d_in[10];
    const float* fc1b   = (const float*)d_in[11];
    const float* fc2w   = (const float*)d_in[12];
    const float* fc2b   = (const float*)d_in[13];
    const float* c1w    = (const float*)d_in[14];
    const float* c1b    = (const float*)d_in[15];
    const float* c2w    = (const float*)d_in[16];
    const float* c2b    = (const float*)d_in[17];
    const float* c3w    = (const float*)d_in[18];
    const float* c3b    = (const float*)d_in[19];
    const float* sfc1   = (const float*)d_in[20];
    const float* sfc2   = (const float*)d_in[21];
    float* out = (float*)d_out;

    float *qkv, *x1, *y1, *y, *pool, *sbuf;
    cudaGetSymbolAddress((void**)&qkv,  g_qkv);
    cudaGetSymbolAddress((void**)&x1,   g_x1);
    cudaGetSymbolAddress((void**)&y1,   g_y1);
    cudaGetSymbolAddress((void**)&y,    g_y);
    cudaGetSymbolAddress((void**)&pool, g_pool);
    cudaGetSymbolAddress((void**)&sbuf, g_s);
    __half *xn16, *ao16, *x1n16, *hb16, *y216;
    __half *wqh, *wql, *wph, *wpl, *w1h, *w1l, *w2h, *w2l, *wc1h, *wc1l, *wc3h, *wc3l;
    cudaGetSymbolAddress((void**)&xn16,  g_xn16);
    cudaGetSymbolAddress((void**)&ao16,  g_ao16);
    cudaGetSymbolAddress((void**)&x1n16, g_x1n16);
    cudaGetSymbolAddress((void**)&hb16,  g_hb16);
    cudaGetSymbolAddress((void**)&y216,  g_y216);
    cudaGetSymbolAddress((void**)&wqh,  g_wqh);  cudaGetSymbolAddress((void**)&wql,  g_wql);
    cudaGetSymbolAddress((void**)&wph,  g_wph);  cudaGetSymbolAddress((void**)&wpl,  g_wpl);
    cudaGetSymbolAddress((void**)&w1h,  g_w1h);  cudaGetSymbolAddress((void**)&w1l,  g_w1l);
    cudaGetSymbolAddress((void**)&w2h,  g_w2h);  cudaGetSymbolAddress((void**)&w2l,  g_w2l);
    cudaGetSymbolAddress((void**)&wc1h, g_wc1h); cudaGetSymbolAddress((void**)&wc1l, g_wc1l);
    cudaGetSymbolAddress((void**)&wc3h, g_wc3h); cudaGetSymbolAddress((void**)&wc3l, g_wc3l);

    cudaFuncSetAttribute(gemm_cp<0,0>, cudaFuncAttributeMaxDynamicSharedMemorySize, GEMM_SMEM_SZ);
    cudaFuncSetAttribute(gemm_cp<1,0>, cudaFuncAttributeMaxDynamicSharedMemorySize, GEMM_SMEM_SZ);
    cudaFuncSetAttribute(gemm_cp<2,1>, cudaFuncAttributeMaxDynamicSharedMemorySize, GEMM_SMEM_SZ);
    cudaFuncSetAttribute(gemm_cp<3,0>, cudaFuncAttributeMaxDynamicSharedMemorySize, GEMM_SMEM_SZ);
    cudaFuncSetAttribute(gemm_cp<4,0>, cudaFuncAttributeMaxDynamicSharedMemorySize, GEMM_SMEM_SZ);

    // 1) weight splits (one launch)
    split_all_kernel<<<(STOT+255)/256, 256>>>(qkvw, projw, fc1w, fc2w, c1w, c3w,
        wqh, wql, wph, wpl, w1h, w1l, w2h, w2l, wc1h, wc1l, wc3h, wc3l);
    // 2) LN1 -> fp16 plane
    ln16_kernel<<<M_/8, 256>>>(x, n1g, n1b, xn16);
    // 3) QKV GEMM
    gemm_cp<0,0><<<dim3(9, M_/128), 256, GEMM_SMEM_SZ>>>(xn16, wqh, wql, qkvb, nullptr, nullptr, nullptr, qkv, nullptr, 3*C_, C_);
    // 4) LCE conv1x1 C->24 -> y1 fp32
    gemm_cp<0,0><<<dim3(1, M_/128), 256, GEMM_SMEM_SZ>>>(xn16, wc1h, wc1l, c1b, nullptr, nullptr, nullptr, y1, nullptr, RED_, C_);
    // 5) attention -> ao fp16
    attn_kernel<<<NWIN, 256>>>(qkv, rpb, ao16);
    // 6) proj + residual -> x1 fp32   (launch #6 — ncu capture slot)
    gemm_cp<1,0><<<dim3(3, M_/128), 256, GEMM_SMEM_SZ>>>(ao16, wph, wpl, projb, x, nullptr, nullptr, x1, nullptr, C_, C_);
    // 7) LN2 -> fp16 plane
    ln16_kernel<<<M_/8, 256>>>(x1, n2g, n2b, x1n16);
    // 8) fc1 + GELU -> hb fp16
    gemm_cp<2,1><<<dim3(12, M_/128), 256, GEMM_SMEM_SZ>>>(x1n16, w1h, w1l, fc1b, nullptr, nullptr, nullptr, nullptr, hb16, HID_, C_);
    // 9) LCE conv3x3 -> y2 fp16
    conv3_kernel<<<dim3(W_/8, H_/8, B_), 64>>>(y1, c2w, c2b, y216);
    // 10) LCE conv1x1 24->192 + LeakyReLU -> y fp32
    gemm_cp<3,0><<<dim3(3, M_/128), 256, GEMM_SMEM_SZ>>>(y216, wc3h, wc3l, c3b, nullptr, nullptr, nullptr, y, nullptr, C_, RED_);
    // 11) global avg pool + SE gate
    zero_pool_kernel<<<1, 384>>>(pool);
    pool_kernel<<<M_/128, 192>>>(y, pool);
    se_kernel<<<1, 192>>>(pool, sfc1, sfc2, sbuf);
    // 12) fc2 + residual + SE-gated local context -> out (fused final)
    gemm_cp<4,0><<<dim3(3, M_/128), 256, GEMM_SMEM_SZ>>>(hb16, w2h, w2l, fc2b, x1, y, sbuf, out, nullptr, C_, HID_);
}

// round 10
// speedup vs baseline: 5.6461x; 1.7487x over previous
#include <cuda_runtime.h>
#include <cuda_fp16.h>
#include <math.h>
#include <stdint.h>

#define B_    2
#define H_    256
#define W_    256
#define C_    192
#define L_    (H_*W_)         // 65536
#define M_    (B_*L_)         // 131072
#define HID_  768
#define NH    6
#define HD    32
#define WS    8
#define SHIFT 4
#define NWIN  (B_*(H_/WS)*(W_/WS))  // 2048
#define RED_  24

// ---------------- scratch (device globals; no allocations) ----------------
__device__ float g_x1 [M_*C_];
__device__ float g_y1 [M_*RED_];
__device__ float g_y  [M_*C_];
__device__ float g_pool[B_*C_];
__device__ float g_s  [B_*C_];
// fp16 activation planes
__device__ __half g_qkv16[(size_t)M_*3*C_];
__device__ __half g_xn16 [M_*C_];
__device__ __half g_ao16 [M_*C_];
__device__ __half g_x1n16[M_*C_];
__device__ __half g_hb16 [(size_t)M_*HID_];
__device__ __half g_y216 [M_*RED_];
// fp16 weight hi/lo planes
__device__ __half g_wqh [3*C_*C_],  g_wql [3*C_*C_];
__device__ __half g_wph [C_*C_],    g_wpl [C_*C_];
__device__ __half g_w1h [HID_*C_],  g_w1l [HID_*C_];
__device__ __half g_w2h [C_*HID_],  g_w2l [C_*HID_];
__device__ __half g_wc1h[RED_*C_],  g_wc1l[RED_*C_];
__device__ __half g_wc3h[C_*RED_],  g_wc3l[C_*RED_];

// ======================= helpers ===========================================
__device__ __forceinline__ uint32_t smem_to_u32(const void* p) {
    uint32_t a;
    asm("{ .reg .u64 t; cvta.to.shared.u64 t, %1; cvt.u32.u64 %0, t; }" : "=r"(a) : "l"(p));
    return a;
}
__device__ __forceinline__ uint32_t pack_h2(float x, float y) {
    __half2 h = __floats2half2_rn(x, y);
    return *reinterpret_cast<uint32_t*>(&h);
}
#define LDSM4(r, addr) \
    asm volatile("ldmatrix.sync.aligned.m8n8.x4.shared.b16 {%0,%1,%2,%3}, [%4];" \
        : "=r"((r)[0]), "=r"((r)[1]), "=r"((r)[2]), "=r"((r)[3]) : "r"(addr))
#define LDSM4T(r, addr) \
    asm volatile("ldmatrix.sync.aligned.m8n8.x4.trans.shared.b16 {%0,%1,%2,%3}, [%4];" \
        : "=r"((r)[0]), "=r"((r)[1]), "=r"((r)[2]), "=r"((r)[3]) : "r"(addr))
#define MMA_F16(d, a, b0, b1) \
    asm volatile("mma.sync.aligned.m16n8k16.row.col.f32.f16.f16.f32 " \
        "{%0,%1,%2,%3},{%4,%5,%6,%7},{%8,%9},{%0,%1,%2,%3};" \
        : "+f"((d)[0]), "+f"((d)[1]), "+f"((d)[2]), "+f"((d)[3]) \
        : "r"((a)[0]), "r"((a)[1]), "r"((a)[2]), "r"((a)[3]), "r"(b0), "r"(b1))
#define CP_ASYNC(dst, src, sz) \
    asm volatile("cp.async.cg.shared.global [%0], [%1], 16, %2;" \
        :: "r"(dst), "l"(src), "r"(sz))
#define CP_COMMIT() asm volatile("cp.async.commit_group;" ::: "memory")

// ======================= fp16 Wx2 mma.sync GEMM (cp.async 4-stage) =========
#define STG_STRIDE 20480   // A 10240 | Whi 5120 | Wlo 5120
#define W_HI 10240
#define NSTG 4
#define GEMM_SMEM_SZ (NSTG*STG_STRIDE)   // 81920

template<int EPI, int OUTP>
__device__ __forceinline__ void gemm_body(const __half* __restrict__ A16,
                                          const __half* __restrict__ Wh,
                                          const __half* __restrict__ Wl,
                                          const float* __restrict__ bias,
                                          const float* __restrict__ res,
                                          const float* __restrict__ yy,
                                          const float* __restrict__ sgate,
                                          float* __restrict__ out,
                                          __half* __restrict__ out16,
                                          int N, int K, char* smem) {
    const int tid  = threadIdx.x;
    const int lane = tid & 31;
    const int warp = tid >> 5;
    const int m0 = blockIdx.y * 128, n0 = blockIdx.x * 64;
    const int wm = (warp & 3) * 32, wn = (warp >> 2) * 32;
    const int nch = (K + 31) >> 5;

#define ISSUE(stg, c) do { \
    char* base_ = smem + (stg) * STG_STRIDE; \
    int k0_ = (c) * 32; \
    _Pragma("unroll") \
    for (int i = 0; i < 2; i++) { \
        int t = tid + i * 256; \
        int row = t >> 2, seg = t & 3; \
        int ke = k0_ + seg * 8; \
        int srcsz = (K - ke) * 2; \
        srcsz = srcsz < 0 ? 0 : (srcsz > 16 ? 16 : srcsz); \
        const __half* g = A16 + (size_t)(m0 + row) * K + (srcsz ? ke : 0); \
        uint32_t d = smem_to_u32(base_ + row * 80 + seg * 16); \
        CP_ASYNC(d, g, srcsz); \
    } \
    _Pragma("unroll") \
    for (int i = 0; i < 2; i++) { \
        const __half* gp = i ? Wl : Wh; \
        int row = tid >> 2, seg = tid & 3; \
        int ke = k0_ + seg * 8; \
        int srcsz = (K - ke) * 2; \
        srcsz = srcsz < 0 ? 0 : (srcsz > 16 ? 16 : srcsz); \
        if (n0 + row >= N) srcsz = 0; \
        int grow = (n0 + row < N) ? (n0 + row) : 0; \
        const __half* g = gp + (size_t)grow * K + (srcsz ? ke : 0); \
        uint32_t d = smem_to_u32(base_ + W_HI + i * 5120 + row * 80 + seg * 16); \
        CP_ASYNC(d, g, srcsz); \
    } \
    CP_COMMIT(); } while (0)

    float acc[2][4][4];
    #pragma unroll
    for (int i = 0; i < 2; i++)
        #pragma unroll
        for (int j = 0; j < 4; j++)
            #pragma unroll
            for (int q = 0; q < 4; q++) acc[i][j][q] = 0.f;

    ISSUE(0, 0);
    if (nch > 1) ISSUE(1, 1);
    if (nch > 2) ISSUE(2, 2);

    int sc = 0;
    for (int c = 0; c < nch; c++) {
        int rem = nch - 1 - c;
        if (rem >= 2)      asm volatile("cp.async.wait_group 2;" ::: "memory");
        else if (rem == 1) asm volatile("cp.async.wait_group 1;" ::: "memory");
        else               asm volatile("cp.async.wait_group 0;" ::: "memory");
        __syncthreads();
        char* base = smem + sc * STG_STRIDE;
        #pragma unroll
        for (int ks = 0; ks < 2; ks++) {
            uint32_t af[2][4], whf[2][4], wlf[2][4];
            #pragma unroll
            for (int mt = 0; mt < 2; mt++) {
                int row = wm + mt * 16 + (lane & 15);
                int colb = ks * 32 + ((lane >> 4) & 1) * 16;
                LDSM4(af[mt], smem_to_u32(base + row * 80 + colb));
            }
            #pragma unroll
            for (int np = 0; np < 2; np++) {
                int n = wn + np * 16 + (lane & 7) + ((lane >> 4) & 1) * 8;
                int colb = ks * 32 + ((lane >> 3) & 1) * 16;
                uint32_t wd = smem_to_u32(base + W_HI + n * 80 + colb);
                LDSM4(whf[np], wd);
                LDSM4(wlf[np], wd + 5120);
            }
            #pragma unroll
            for (int pass = 0; pass < 2; pass++)
                #pragma unroll
                for (int mt = 0; mt < 2; mt++)
                    #pragma unroll
                    for (int nt = 0; nt < 4; nt++) {
                        int np = nt >> 1, h = (nt & 1) * 2;
                        const uint32_t (*wf)[4] = pass ? wlf : whf;
                        MMA_F16(acc[mt][nt], af[mt], wf[np][h], wf[np][h+1]);
                    }
        }
        if (c + 3 < nch) {
            int si = sc + 3; if (si >= NSTG) si -= NSTG;
            ISSUE(si, c + 3);
        }
        sc = (sc + 1 == NSTG) ? 0 : sc + 1;
    }

    // ---- epilogue ----
    #pragma unroll
    for (int mt = 0; mt < 2; mt++) {
        int r0 = m0 + wm + mt * 16 + (lane >> 2);
        #pragma unroll
        for (int nt = 0; nt < 4; nt++) {
            int col = n0 + wn + nt * 8 + (lane & 3) * 2;
            if (col < N) {
                float b0v = bias[col], b1v = bias[col + 1];
                #pragma unroll
                for (int rr = 0; rr < 2; rr++) {
                    int r = r0 + rr * 8;
                    float v0 = acc[mt][nt][rr*2+0] + b0v;
                    float v1 = acc[mt][nt][rr*2+1] + b1v;
                    if (EPI == 1 || EPI == 4) {
                        float2 rv = *(const float2*)(res + (size_t)r * N + col);
                        v0 += rv.x; v1 += rv.y;
                    }
                    if (EPI == 2) {
                        v0 = 0.5f * v0 * (1.f + erff(v0 * 0.70710678118654752f));
                        v1 = 0.5f * v1 * (1.f + erff(v1 * 0.70710678118654752f));
                    }
                    if (EPI == 3) {
                        v0 = (v0 >= 0.f) ? v0 : 0.2f * v0;
                        v1 = (v1 >= 0.f) ? v1 : 0.2f * v1;
                    }
                    if (EPI == 4) {
                        const float* sb = sgate + (r >> 16) * C_;
                        float2 yv = *(const float2*)(yy + (size_t)r * N + col);
                        v0 += yv.x * sb[col];
                        v1 += yv.y * sb[col + 1];
                    }
                    if (OUTP) {
                        *(uint32_t*)(out16 + (size_t)r * N + col) = pack_h2(v0, v1);
                    } else {
                        *(float2*)(out + (size_t)r * N + col) = make_float2(v0, v1);
                    }
                }
            }
        }
    }
#undef ISSUE
}

template<int EPI, int OUTP>
__global__ __launch_bounds__(256, 2) void gemm_cp(const __half* __restrict__ A16,
                                                  const __half* __restrict__ Wh,
                                                  const __half* __restrict__ Wl,
                                                  const float* __restrict__ bias,
                                                  const float* __restrict__ res,
                                                  const float* __restrict__ yy,
                                                  const float* __restrict__ sgate,
                                                  float* __restrict__ out,
                                                  __half* __restrict__ out16,
                                                  int N, int K) {
    extern __shared__ char smem[];
    gemm_body<EPI, OUTP>(A16, Wh, Wl, bias, res, yy, sgate, out, out16, N, K, smem);
}

// ---------------- merged weight split (6 tensors, one launch) --------------
#define S0 (3*C_*C_)
#define S1 (C_*C_)
#define S2 (HID_*C_)
#define S3 (C_*HID_)
#define S4 (RED_*C_)
#define S5 (C_*RED_)
#define STOT (S0+S1+S2+S3+S4+S5)
__global__ __launch_bounds__(256) void split_all_kernel(
        const float* __restrict__ w0, const float* __restrict__ w1,
        const float* __restrict__ w2, const float* __restrict__ w3,
        const float* __restrict__ w4, const float* __restrict__ w5,
        __half* h0, __half* l0, __half* h1, __half* l1,
        __half* h2, __half* l2, __half* h3, __half* l3,
        __half* h4, __half* l4, __half* h5, __half* l5) {
    int i = blockIdx.x * 256 + threadIdx.x;
    const float* s; __half *h, *l; int off;
    if      (i < S0)                { s = w0; h = h0; l = l0; off = i; }
    else if (i < S0+S1)             { s = w1; h = h1; l = l1; off = i - S0; }
    else if (i < S0+S1+S2)          { s = w2; h = h2; l = l2; off = i - S0-S1; }
    else if (i < S0+S1+S2+S3)       { s = w3; h = h3; l = l3; off = i - S0-S1-S2; }
    else if (i < S0+S1+S2+S3+S4)    { s = w4; h = h4; l = l4; off = i - S0-S1-S2-S3; }
    else if (i < STOT)              { s = w5; h = h5; l = l5; off = i - S0-S1-S2-S3-S4; }
    else return;
    float v = s[off];
    __half hv = __float2half_rn(v);
    h[off] = hv;
    l[off] = __float2half_rn(v - __half2float(hv));
}

// ---------------- LayerNorm -> single fp16 plane ---------------------------
__global__ __launch_bounds__(256) void ln16_kernel(const float* __restrict__ x,
                                                   const float* __restrict__ g,
                                                   const float* __restrict__ b,
                                                   __half* __restrict__ o16) {
    int token = blockIdx.x * 8 + (threadIdx.x >> 5);
    int lane  = threadIdx.x & 31;
    const float* p = x + (size_t)token * C_;
    float v[6];
    float s = 0.f;
    #pragma unroll
    for (int j = 0; j < 6; j++) { v[j] = p[lane + 32*j]; s += v[j]; }
    #pragma unroll
    for (int o = 16; o > 0; o >>= 1) s += __shfl_xor_sync(0xffffffffu, s, o);
    float mean = s * (1.f / C_);
    float q = 0.f;
    #pragma unroll
    for (int j = 0; j < 6; j++) { float d = v[j] - mean; q += d * d; }
    #pragma unroll
    for (int o = 16; o > 0; o >>= 1) q += __shfl_xor_sync(0xffffffffu, q, o);
    float rstd = rsqrtf(q * (1.f / C_) + 1e-5f);
    #pragma unroll
    for (int j = 0; j < 6; j++) {
        int c = lane + 32*j;
        o16[(size_t)token * C_ + c] = __float2half_rn((v[j] - mean) * rstd * g[c] + b[c]);
    }
}

// ============ Windowed attention: tensor-core (FA-style), 1 block/window ===
// 8 warps: warps 0-3 = head h0 (rows (w&3)*16..+16), warps 4-7 = head h0+1.
// 3 head-pair iterations. Q/K/V fp16 smem planes, stride 80B.
__global__ __launch_bounds__(256) void attn_mma_kernel(const __half* __restrict__ qkv16,
                                                       const float* __restrict__ rpb,
                                                       __half* __restrict__ ao16) {
    __shared__ __half planes[6 * 64 * 40];   // q0,k0,v0,q1,k1,v1 : 30720 B
    __shared__ float  srpb[225 * NH];        // 5400 B
    __shared__ int    gidx[64];
    __shared__ int    rid [64];

    const int tid  = threadIdx.x;
    const int lane = tid & 31;
    const int warp = tid >> 5;
    const int wid  = blockIdx.x;
    const int bb   = wid >> 10;
    const int wib  = wid & 1023;
    const int wh   = wib >> 5, ww = wib & 31;

    if (tid < 64) {
        int ih = tid >> 3, iw = tid & 7;
        int h = wh * 8 + ih, w = ww * 8 + iw;
        gidx[tid] = bb * L_ + ((h + SHIFT) & (H_ - 1)) * W_ + ((w + SHIFT) & (W_ - 1));
        int rh = (h < H_ - WS) ? 0 : ((h < H_ - SHIFT) ? 1 : 2);
        int rw = (w < W_ - WS) ? 0 : ((w < W_ - SHIFT) ? 1 : 2);
        rid[tid] = rh * 3 + rw;
    }
    for (int i = tid; i < 225 * NH; i += 256) srpb[i] = rpb[i];
    __syncthreads();

    const uint32_t pb = smem_to_u32(planes);
    const int hp   = warp >> 2;            // which head of the pair
    const int r0   = (warp & 3) * 16;      // S-strip row base
    const int i_lo = r0 + (lane >> 2);
    const int i_hi = i_lo + 8;
    const int ihlo = i_lo >> 3, iwlo = i_lo & 7;
    const int ihhi = i_hi >> 3, iwhi = i_hi & 7;
    const float SCALE = 0.17677669529663687f;

    const uint32_t qbase = pb + hp * 15360;
    const uint32_t kbase = qbase + 5120;
    const uint32_t vbase = qbase + 10240;

    for (int it = 0; it < 3; ++it) {
        const int h0 = it * 2;
        // ---- load q,k,v for this head pair (6 planes x 64 rows x 64B) ----
        #pragma unroll
        for (int i = 0; i < 6; i++) {
            int t   = tid + i * 256;
            int rowid = t >> 2, seg = t & 3;
            int p   = rowid >> 6, tok = rowid & 63;
            int mat = p % 3, php = p / 3;
            const __half* g = qkv16 + (size_t)gidx[tok] * (3*C_) + mat * C_ + (h0 + php) * HD + seg * 8;
            uint32_t d = pb + p * 5120 + tok * 80 + seg * 16;
            CP_ASYNC(d, g, 16);
        }
        CP_COMMIT();
        asm volatile("cp.async.wait_group 0;" ::: "memory");
        __syncthreads();

        const int head = h0 + hp;
        // ---- S = Q K^T ----
        float S[8][4];
        #pragma unroll
        for (int t = 0; t < 8; t++)
            #pragma unroll
            for (int q = 0; q < 4; q++) S[t][q] = 0.f;
        #pragma unroll
        for (int ks = 0; ks < 2; ks++) {
            uint32_t qf[4];
            LDSM4(qf, qbase + (r0 + (lane & 15)) * 80 + ks * 32 + ((lane >> 4) & 1) * 16);
            #pragma unroll
            for (int np = 0; np < 4; np++) {
                uint32_t kf[4];
                LDSM4(kf, kbase + ((lane & 7) + ((lane >> 4) & 1) * 8 + np * 16) * 80
                          + ks * 32 + ((lane >> 3) & 1) * 16);
                MMA_F16(S[np*2+0], qf, kf[0], kf[1]);
                MMA_F16(S[np*2+1], qf, kf[2], kf[3]);
            }
        }
        // ---- scale + bias + mask, softmax (rows i_lo, i_hi) ----
        const int ridlo = rid[i_lo], ridhi = rid[i_hi];
        float mlo = -1e30f, mhi = -1e30f;
        #pragma unroll
        for (int t = 0; t < 8; t++) {
            int jc = (t >> 1) * 16 + (t & 1) * 8 + (lane & 3) * 2;
            #pragma unroll
            for (int e = 0; e < 2; e++) {
                int j = jc + e;
                int jh = j >> 3, jw = j & 7;
                float blo = srpb[((ihlo - jh + 7) * 15 + (iwlo - jw + 7)) * NH + head];
                float bhi = srpb[((ihhi - jh + 7) * 15 + (iwhi - jw + 7)) * NH + head];
                int rj = rid[j];
                float v0 = S[t][e]     * SCALE + blo + ((ridlo != rj) ? -100.f : 0.f);
                float v1 = S[t][e + 2] * SCALE + bhi + ((ridhi != rj) ? -100.f : 0.f);
                S[t][e] = v0; S[t][e + 2] = v1;
                mlo = fmaxf(mlo, v0); mhi = fmaxf(mhi, v1);
            }
        }
        mlo = fmaxf(mlo, __shfl_xor_sync(0xffffffffu, mlo, 1));
        mlo = fmaxf(mlo, __shfl_xor_sync(0xffffffffu, mlo, 2));
        mhi = fmaxf(mhi, __shfl_xor_sync(0xffffffffu, mhi, 1));
        mhi = fmaxf(mhi, __shfl_xor_sync(0xffffffffu, mhi, 2));
        float slo = 0.f, shi = 0.f;
        #pragma unroll
        for (int t = 0; t < 8; t++) {
            #pragma unroll
            for (int e = 0; e < 2; e++) {
                float v0 = __expf(S[t][e] - mlo);
                float v1 = __expf(S[t][e + 2] - mhi);
                S[t][e] = v0; S[t][e + 2] = v1;
                slo += v0; shi += v1;
            }
        }
        slo += __shfl_xor_sync(0xffffffffu, slo, 1);
        slo += __shfl_xor_sync(0xffffffffu, slo, 2);
        shi += __shfl_xor_sync(0xffffffffu, shi, 1);
        shi += __shfl_xor_sync(0xffffffffu, shi, 2);
        float ilo = 1.f / slo, ihi2 = 1.f / shi;
        // ---- pack P into A-frags ----
        uint32_t pa[4][4];
        #pragma unroll
        for (int kt = 0; kt < 4; kt++) {
            pa[kt][0] = pack_h2(S[kt*2][0] * ilo,  S[kt*2][1] * ilo);
            pa[kt][1] = pack_h2(S[kt*2][2] * ihi2, S[kt*2][3] * ihi2);
            pa[kt][2] = pack_h2(S[kt*2+1][0] * ilo,  S[kt*2+1][1] * ilo);
            pa[kt][3] = pack_h2(S[kt*2+1][2] * ihi2, S[kt*2+1][3] * ihi2);
        }
        // ---- O = P V ----
        float O[4][4];
        #pragma unroll
        for (int t = 0; t < 4; t++)
            #pragma unroll
            for (int q = 0; q < 4; q++) O[t][q] = 0.f;
        #pragma unroll
        for (int kt = 0; kt < 4; kt++) {
            #pragma unroll
            for (int nc = 0; nc < 2; nc++) {
                uint32_t vf[4];
                LDSM4T(vf, vbase + (kt * 16 + (lane & 7) + ((lane >> 3) & 1) * 8) * 80
                           + nc * 32 + ((lane >> 4) & 1) * 16);
                MMA_F16(O[nc*2+0], pa[kt], vf[0], vf[1]);
                MMA_F16(O[nc*2+1], pa[kt], vf[2], vf[3]);
            }
        }
        // ---- write O (fp16, scattered rows) ----
        #pragma unroll
        for (int t = 0; t < 4; t++) {
            int col = t * 8 + (lane & 3) * 2;
            *(uint32_t*)(ao16 + (size_t)gidx[i_lo] * C_ + head * HD + col) = pack_h2(O[t][0], O[t][1]);
            *(uint32_t*)(ao16 + (size_t)gidx[i_hi] * C_ + head * HD + col) = pack_h2(O[t][2], O[t][3]);
        }
        __syncthreads();
    }
}

// ---------------- 3x3 conv on r=24 channels, NHWC, pad 1 -------------------
__global__ __launch_bounds__(64) void conv3_kernel(const float* __restrict__ yin,
                                                   const float* __restrict__ w,
                                                   const float* __restrict__ bias,
                                                   __half* __restrict__ y16) {
    __shared__ float patch[100][RED_];
    __shared__ float wts[RED_ * RED_ * 9];
    int tid = threadIdx.x;
    int b = blockIdx.z;
    int th0 = blockIdx.y * 8, tw0 = blockIdx.x * 8;

    for (int d = tid; d < RED_ * RED_ * 9; d += 64) {
        int oc = d % RED_;
        int t2 = d / RED_;
        int kk = t2 % 9;
        int ic = t2 / 9;
        wts[d] = w[(oc * RED_ + ic) * 9 + kk];
    }
    for (int d = tid; d < 100 * RED_; d += 64) {
        int ic = d % RED_;
        int pos = d / RED_;
        int ph = pos / 10, pw = pos % 10;
        int hh = th0 + ph - 1, ww = tw0 + pw - 1;
        float v = 0.f;
        if (hh >= 0 && hh < H_ && ww >= 0 && ww < W_)
            v = yin[((size_t)b * L_ + hh * W_ + ww) * RED_ + ic];
        patch[pos][ic] = v;
    }
    __syncthreads();

    int py = tid >> 3, px = tid & 7;
    float acc[RED_];
    #pragma unroll
    for (int oc = 0; oc < RED_; oc++) acc[oc] = __ldg(bias + oc);
    for (int ic = 0; ic < RED_; ic++) {
        #pragma unroll
        for (int kk = 0; kk < 9; kk++) {
            int kh = kk / 3, kw = kk % 3;
            float pv = patch[(py + kh) * 10 + (px + kw)][ic];
            const float4* wp = (const float4*)&wts[(ic * 9 + kk) * RED_];
            #pragma unroll
            for (int o4 = 0; o4 < 6; o4++) {
                float4 wv = wp[o4];
                acc[o4*4+0] += wv.x * pv; acc[o4*4+1] += wv.y * pv;
                acc[o4*4+2] += wv.z * pv; acc[o4*4+3] += wv.w * pv;
            }
        }
    }
    size_t off = ((size_t)b * L_ + (th0 + py) * W_ + (tw0 + px)) * RED_;
    #pragma unroll
    for (int oc = 0; oc < RED_; oc += 2)
        *(uint32_t*)(y16 + off + oc) = pack_h2(acc[oc], acc[oc + 1]);
}

// ---------------- pool / SE ------------------------------------------------
__global__ void zero_pool_kernel(float* pool) {
    if (threadIdx.x < B_ * C_) pool[threadIdx.x] = 0.f;
}

__global__ __launch_bounds__(192) void pool_kernel(const float* __restrict__ y,
                                                   float* __restrict__ pool) {
    int base = blockIdx.x * 128;
    int b = base >> 16;
    int c = threadIdx.x;
    float acc = 0.f;
    for (int i = 0; i < 128; i++)
        acc += y[(size_t)(base + i) * C_ + c];
    atomicAdd(&pool[b * C_ + c], acc);
}

__global__ __launch_bounds__(192) void se_kernel(const float* __restrict__ pool,
                                                 const float* __restrict__ fc1,
                                                 const float* __restrict__ fc2,
                                                 float* __restrict__ sbuf) {
    __shared__ float t[RED_];
    int tid = threadIdx.x;
    const float inv = 1.f / (float)L_;
    for (int b = 0; b < B_; b++) {
        if (tid < RED_) {
            float s = 0.f;
            for (int c = 0; c < C_; c++)
                s += pool[b * C_ + c] * inv * fc1[tid * C_ + c];
            t[tid] = fmaxf(s, 0.f);
        }
        __syncthreads();
        float s = 0.f;
        #pragma unroll
        for (int j = 0; j < RED_; j++) s += t[j] * fc2[tid * RED_ + j];
        sbuf[b * C_ + tid] = 1.f / (1.f + expf(-s));
        __syncthreads();
    }
}

// ---------------- launch ---------------------------------------------------
extern "C" void kernel_launch(void* const* d_in, const int* in_sizes, int n_in,
                              void* d_out, int out_size) {
    const float* x      = (const float*)d_in[0];
    const float* n1g    = (const float*)d_in[1];
    const float* n1b    = (const float*)d_in[2];
    const float* qkvw   = (const float*)d_in[3];
    const float* qkvb   = (const float*)d_in[4];
    const float* rpb    = (const float*)d_in[5];
    const float* projw  = (const float*)d_in[6];
    const float* projb  = (const float*)d_in[7];
    const float* n2g    = (const float*)d_in[8];
    const float* n2b    = (const float*)d_in[9];
    const float* fc1w   = (const float*)d_in[10];
    const float* fc1b   = (const float*)d_in[11];
    const float* fc2w   = (const float*)d_in[12];
    const float* fc2b   = (const float*)d_in[13];
    const float* c1w    = (const float*)d_in[14];
    const float* c1b    = (const float*)d_in[15];
    const float* c2w    = (const float*)d_in[16];
    const float* c2b    = (const float*)d_in[17];
    const float* c3w    = (const float*)d_in[18];
    const float* c3b    = (const float*)d_in[19];
    const float* sfc1   = (const float*)d_in[20];
    const float* sfc2   = (const float*)d_in[21];
    float* out = (float*)d_out;

    float *x1, *y1, *y, *pool, *sbuf;
    cudaGetSymbolAddress((void**)&x1,   g_x1);
    cudaGetSymbolAddress((void**)&y1,   g_y1);
    cudaGetSymbolAddress((void**)&y,    g_y);
    cudaGetSymbolAddress((void**)&pool, g_pool);
    cudaGetSymbolAddress((void**)&sbuf, g_s);
    __half *qkv16, *xn16, *ao16, *x1n16, *hb16, *y216;
    __half *wqh, *wql, *wph, *wpl, *w1h, *w1l, *w2h, *w2l, *wc1h, *wc1l, *wc3h, *wc3l;
    cudaGetSymbolAddress((void**)&qkv16, g_qkv16);
    cudaGetSymbolAddress((void**)&xn16,  g_xn16);
    cudaGetSymbolAddress((void**)&ao16,  g_ao16);
    cudaGetSymbolAddress((void**)&x1n16, g_x1n16);
    cudaGetSymbolAddress((void**)&hb16,  g_hb16);
    cudaGetSymbolAddress((void**)&y216,  g_y216);
    cudaGetSymbolAddress((void**)&wqh,  g_wqh);  cudaGetSymbolAddress((void**)&wql,  g_wql);
    cudaGetSymbolAddress((void**)&wph,  g_wph);  cudaGetSymbolAddress((void**)&wpl,  g_wpl);
    cudaGetSymbolAddress((void**)&w1h,  g_w1h);  cudaGetSymbolAddress((void**)&w1l,  g_w1l);
    cudaGetSymbolAddress((void**)&w2h,  g_w2h);  cudaGetSymbolAddress((void**)&w2l,  g_w2l);
    cudaGetSymbolAddress((void**)&wc1h, g_wc1h); cudaGetSymbolAddress((void**)&wc1l, g_wc1l);
    cudaGetSymbolAddress((void**)&wc3h, g_wc3h); cudaGetSymbolAddress((void**)&wc3l, g_wc3l);

    cudaFuncSetAttribute(gemm_cp<0,0>, cudaFuncAttributeMaxDynamicSharedMemorySize, GEMM_SMEM_SZ);
    cudaFuncSetAttribute(gemm_cp<0,1>, cudaFuncAttributeMaxDynamicSharedMemorySize, GEMM_SMEM_SZ);
    cudaFuncSetAttribute(gemm_cp<1,0>, cudaFuncAttributeMaxDynamicSharedMemorySize, GEMM_SMEM_SZ);
    cudaFuncSetAttribute(gemm_cp<2,1>, cudaFuncAttributeMaxDynamicSharedMemorySize, GEMM_SMEM_SZ);
    cudaFuncSetAttribute(gemm_cp<3,0>, cudaFuncAttributeMaxDynamicSharedMemorySize, GEMM_SMEM_SZ);
    cudaFuncSetAttribute(gemm_cp<4,0>, cudaFuncAttributeMaxDynamicSharedMemorySize, GEMM_SMEM_SZ);

    // 1) weight splits
    split_all_kernel<<<(STOT+255)/256, 256>>>(qkvw, projw, fc1w, fc2w, c1w, c3w,
        wqh, wql, wph, wpl, w1h, w1l, w2h, w2l, wc1h, wc1l, wc3h, wc3l);
    // 2) LN1 -> fp16 plane
    ln16_kernel<<<M_/8, 256>>>(x, n1g, n1b, xn16);
    // 3) QKV GEMM -> fp16
    gemm_cp<0,1><<<dim3(9, M_/128), 256, GEMM_SMEM_SZ>>>(xn16, wqh, wql, qkvb, nullptr, nullptr, nullptr, nullptr, qkv16, 3*C_, C_);
    // 4) LCE conv1x1 C->24 -> y1 fp32
    gemm_cp<0,0><<<dim3(1, M_/128), 256, GEMM_SMEM_SZ>>>(xn16, wc1h, wc1l, c1b, nullptr, nullptr, nullptr, y1, nullptr, RED_, C_);
    // 5) attention (tensor-core) -> ao fp16
    attn_mma_kernel<<<NWIN, 256>>>(qkv16, rpb, ao16);
    // 6) proj + residual -> x1 fp32
    gemm_cp<1,0><<<dim3(3, M_/128), 256, GEMM_SMEM_SZ>>>(ao16, wph, wpl, projb, x, nullptr, nullptr, x1, nullptr, C_, C_);
    // 7) LN2 -> fp16 plane
    ln16_kernel<<<M_/8, 256>>>(x1, n2g, n2b, x1n16);
    // 8) fc1 + GELU -> hb fp16
    gemm_cp<2,1><<<dim3(12, M_/128), 256, GEMM_SMEM_SZ>>>(x1n16, w1h, w1l, fc1b, nullptr, nullptr, nullptr, nullptr, hb16, HID_, C_);
    // 9) LCE conv3x3 -> y2 fp16
    conv3_kernel<<<dim3(W_/8, H_/8, B_), 64>>>(y1, c2w, c2b, y216);
    // 10) LCE conv1x1 24->192 + LeakyReLU -> y fp32
    gemm_cp<3,0><<<dim3(3, M_/128), 256, GEMM_SMEM_SZ>>>(y216, wc3h, wc3l, c3b, nullptr, nullptr, nullptr, y, nullptr, C_, RED_);
    // 11) global avg pool + SE gate
    zero_pool_kernel<<<1, 384>>>(pool);
    pool_kernel<<<M_/128, 192>>>(y, pool);
    se_kernel<<<1, 192>>>(pool, sfc1, sfc2, sbuf);
    // 12) fc2 + residual + SE-gated local context -> out
    gemm_cp<4,0><<<dim3(3, M_/128), 256, GEMM_SMEM_SZ>>>(hb16, w2h, w2l, fc2b, x1, y, sbuf, out, nullptr, C_, HID_);
}

// round 12
// speedup vs baseline: 6.7785x; 1.2006x over previous
#include <cuda_runtime.h>
#include <cuda_fp16.h>
#include <math.h>
#include <stdint.h>

#define B_    2
#define H_    256
#define W_    256
#define C_    192
#define L_    (H_*W_)         // 65536
#define M_    (B_*L_)         // 131072
#define HID_  768
#define NH    6
#define HD    32
#define WS    8
#define SHIFT 4
#define NWIN  (B_*(H_/WS)*(W_/WS))  // 2048
#define RED_  24

// ---------------- scratch (device globals; no allocations) ----------------
__device__ float g_x1 [M_*C_];
__device__ float g_y1 [M_*RED_];
__device__ float g_y  [M_*C_];
__device__ float g_pool[B_*C_];
__device__ float g_s  [B_*C_];
// fp16 activation planes
__device__ __half g_qkv16[(size_t)M_*3*C_];
__device__ __half g_xn16 [M_*C_];
__device__ __half g_ao16 [M_*C_];
__device__ __half g_x1n16[M_*C_];
__device__ __half g_hb16 [(size_t)M_*HID_];
__device__ __half g_y216 [M_*RED_];
// fp16 weights (single plane)
__device__ __half g_wq [3*C_*C_];
__device__ __half g_wp [C_*C_];
__device__ __half g_w1 [HID_*C_];
__device__ __half g_w2 [C_*HID_];
__device__ __half g_wc1[RED_*C_];
__device__ __half g_wc3[C_*RED_];

// ======================= helpers ===========================================
__device__ __forceinline__ uint32_t smem_to_u32(const void* p) {
    uint32_t a;
    asm("{ .reg .u64 t; cvta.to.shared.u64 t, %1; cvt.u32.u64 %0, t; }" : "=r"(a) : "l"(p));
    return a;
}
__device__ __forceinline__ uint32_t pack_h2(float x, float y) {
    __half2 h = __floats2half2_rn(x, y);
    return *reinterpret_cast<uint32_t*>(&h);
}
#define LDSM4(r, addr) \
    asm volatile("ldmatrix.sync.aligned.m8n8.x4.shared.b16 {%0,%1,%2,%3}, [%4];" \
        : "=r"((r)[0]), "=r"((r)[1]), "=r"((r)[2]), "=r"((r)[3]) : "r"(addr))
#define LDSM4T(r, addr) \
    asm volatile("ldmatrix.sync.aligned.m8n8.x4.trans.shared.b16 {%0,%1,%2,%3}, [%4];" \
        : "=r"((r)[0]), "=r"((r)[1]), "=r"((r)[2]), "=r"((r)[3]) : "r"(addr))
#define MMA_F16(d, a, b0, b1) \
    asm volatile("mma.sync.aligned.m16n8k16.row.col.f32.f16.f16.f32 " \
        "{%0,%1,%2,%3},{%4,%5,%6,%7},{%8,%9},{%0,%1,%2,%3};" \
        : "+f"((d)[0]), "+f"((d)[1]), "+f"((d)[2]), "+f"((d)[3]) \
        : "r"((a)[0]), "r"((a)[1]), "r"((a)[2]), "r"((a)[3]), "r"(b0), "r"(b1))
#define CP_ASYNC(dst, src, sz) \
    asm volatile("cp.async.cg.shared.global [%0], [%1], 16, %2;" \
        :: "r"(dst), "l"(src), "r"(sz))
#define CP_COMMIT() asm volatile("cp.async.commit_group;" ::: "memory")

// ======================= fp16 mma.sync GEMM (cp.async 4-stage) =============
// out[M,N] = epi(A @ W^T + bias); A and W single fp16 planes [rows][K].
// CTA tile 128x64, BK=32, fp32 accumulate.
// EPI: 0 none, 1 +res, 2 exact GELU, 3 LeakyReLU(0.2),
//      4 +res + gate (out = v + res + yy*s[b,col]). OUTP: 1 = write fp16 plane.
#define STG_STRIDE 15360   // A 10240 | W 5120
#define W_OFF 10240
#define NSTG 4
#define GEMM_SMEM_SZ (NSTG*STG_STRIDE)   // 61440

template<int EPI, int OUTP>
__device__ __forceinline__ void gemm_body(const __half* __restrict__ A16,
                                          const __half* __restrict__ Wt,
                                          const float* __restrict__ bias,
                                          const float* __restrict__ res,
                                          const float* __restrict__ yy,
                                          const float* __restrict__ sgate,
                                          float* __restrict__ out,
                                          __half* __restrict__ out16,
                                          int N, int K, char* smem) {
    const int tid  = threadIdx.x;
    const int lane = tid & 31;
    const int warp = tid >> 5;
    const int m0 = blockIdx.y * 128, n0 = blockIdx.x * 64;
    const int wm = (warp & 3) * 32, wn = (warp >> 2) * 32;
    const int nch = (K + 31) >> 5;

#define ISSUE(stg, c) do { \
    char* base_ = smem + (stg) * STG_STRIDE; \
    int k0_ = (c) * 32; \
    _Pragma("unroll") \
    for (int i = 0; i < 2; i++) { \
        int t = tid + i * 256; \
        int row = t >> 2, seg = t & 3; \
        int ke = k0_ + seg * 8; \
        int srcsz = (K - ke) * 2; \
        srcsz = srcsz < 0 ? 0 : (srcsz > 16 ? 16 : srcsz); \
        const __half* g = A16 + (size_t)(m0 + row) * K + (srcsz ? ke : 0); \
        uint32_t d = smem_to_u32(base_ + row * 80 + seg * 16); \
        CP_ASYNC(d, g, srcsz); \
    } \
    { \
        int row = tid >> 2, seg = tid & 3; \
        int ke = k0_ + seg * 8; \
        int srcsz = (K - ke) * 2; \
        srcsz = srcsz < 0 ? 0 : (srcsz > 16 ? 16 : srcsz); \
        if (n0 + row >= N) srcsz = 0; \
        int grow = (n0 + row < N) ? (n0 + row) : 0; \
        const __half* g = Wt + (size_t)grow * K + (srcsz ? ke : 0); \
        uint32_t d = smem_to_u32(base_ + W_OFF + row * 80 + seg * 16); \
        CP_ASYNC(d, g, srcsz); \
    } \
    CP_COMMIT(); } while (0)

    float acc[2][4][4];
    #pragma unroll
    for (int i = 0; i < 2; i++)
        #pragma unroll
        for (int j = 0; j < 4; j++)
            #pragma unroll
            for (int q = 0; q < 4; q++) acc[i][j][q] = 0.f;

    ISSUE(0, 0);
    if (nch > 1) ISSUE(1, 1);
    if (nch > 2) ISSUE(2, 2);

    int sc = 0;
    for (int c = 0; c < nch; c++) {
        int rem = nch - 1 - c;
        if (rem >= 2)      asm volatile("cp.async.wait_group 2;" ::: "memory");
        else if (rem == 1) asm volatile("cp.async.wait_group 1;" ::: "memory");
        else               asm volatile("cp.async.wait_group 0;" ::: "memory");
        __syncthreads();
        char* base = smem + sc * STG_STRIDE;
        #pragma unroll
        for (int ks = 0; ks < 2; ks++) {
            uint32_t af[2][4], wf[2][4];
            #pragma unroll
            for (int mt = 0; mt < 2; mt++) {
                int row = wm + mt * 16 + (lane & 15);
                int colb = ks * 32 + ((lane >> 4) & 1) * 16;
                LDSM4(af[mt], smem_to_u32(base + row * 80 + colb));
            }
            #pragma unroll
            for (int np = 0; np < 2; np++) {
                int n = wn + np * 16 + (lane & 7) + ((lane >> 4) & 1) * 8;
                int colb = ks * 32 + ((lane >> 3) & 1) * 16;
                LDSM4(wf[np], smem_to_u32(base + W_OFF + n * 80 + colb));
            }
            #pragma unroll
            for (int mt = 0; mt < 2; mt++)
                #pragma unroll
                for (int nt = 0; nt < 4; nt++) {
                    int np = nt >> 1, h = (nt & 1) * 2;
                    MMA_F16(acc[mt][nt], af[mt], wf[np][h], wf[np][h+1]);
                }
        }
        if (c + 3 < nch) {
            int si = sc + 3; if (si >= NSTG) si -= NSTG;
            ISSUE(si, c + 3);
        }
        sc = (sc + 1 == NSTG) ? 0 : sc + 1;
    }

    // ---- epilogue ----
    #pragma unroll
    for (int mt = 0; mt < 2; mt++) {
        int r0 = m0 + wm + mt * 16 + (lane >> 2);
        #pragma unroll
        for (int nt = 0; nt < 4; nt++) {
            int col = n0 + wn + nt * 8 + (lane & 3) * 2;
            if (col < N) {
                float b0v = bias[col], b1v = bias[col + 1];
                #pragma unroll
                for (int rr = 0; rr < 2; rr++) {
                    int r = r0 + rr * 8;
                    float v0 = acc[mt][nt][rr*2+0] + b0v;
                    float v1 = acc[mt][nt][rr*2+1] + b1v;
                    if (EPI == 1 || EPI == 4) {
                        float2 rv = *(const float2*)(res + (size_t)r * N + col);
                        v0 += rv.x; v1 += rv.y;
                    }
                    if (EPI == 2) {
                        v0 = 0.5f * v0 * (1.f + erff(v0 * 0.70710678118654752f));
                        v1 = 0.5f * v1 * (1.f + erff(v1 * 0.70710678118654752f));
                    }
                    if (EPI == 3) {
                        v0 = (v0 >= 0.f) ? v0 : 0.2f * v0;
                        v1 = (v1 >= 0.f) ? v1 : 0.2f * v1;
                    }
                    if (EPI == 4) {
                        const float* sb = sgate + (r >> 16) * C_;
                        float2 yv = *(const float2*)(yy + (size_t)r * N + col);
                        v0 += yv.x * sb[col];
                        v1 += yv.y * sb[col + 1];
                    }
                    if (OUTP) {
                        *(uint32_t*)(out16 + (size_t)r * N + col) = pack_h2(v0, v1);
                    } else {
                        *(float2*)(out + (size_t)r * N + col) = make_float2(v0, v1);
                    }
                }
            }
        }
    }
#undef ISSUE
}

template<int EPI, int OUTP>
__global__ __launch_bounds__(256, 2) void gemm_cp(const __half* __restrict__ A16,
                                                  const __half* __restrict__ Wt,
                                                  const float* __restrict__ bias,
                                                  const float* __restrict__ res,
                                                  const float* __restrict__ yy,
                                                  const float* __restrict__ sgate,
                                                  float* __restrict__ out,
                                                  __half* __restrict__ out16,
                                                  int N, int K) {
    extern __shared__ char smem[];
    gemm_body<EPI, OUTP>(A16, Wt, bias, res, yy, sgate, out, out16, N, K, smem);
}

// ---------------- merged weight convert (6 tensors, one launch) ------------
#define S0 (3*C_*C_)
#define S1 (C_*C_)
#define S2 (HID_*C_)
#define S3 (C_*HID_)
#define S4 (RED_*C_)
#define S5 (C_*RED_)
#define STOT (S0+S1+S2+S3+S4+S5)
__global__ __launch_bounds__(256) void convert_all_kernel(
        const float* __restrict__ w0, const float* __restrict__ w1,
        const float* __restrict__ w2, const float* __restrict__ w3,
        const float* __restrict__ w4, const float* __restrict__ w5,
        __half* h0, __half* h1, __half* h2, __half* h3, __half* h4, __half* h5) {
    int i = blockIdx.x * 256 + threadIdx.x;
    const float* s; __half* h; int off;
    if      (i < S0)                { s = w0; h = h0; off = i; }
    else if (i < S0+S1)             { s = w1; h = h1; off = i - S0; }
    else if (i < S0+S1+S2)          { s = w2; h = h2; off = i - S0-S1; }
    else if (i < S0+S1+S2+S3)       { s = w3; h = h3; off = i - S0-S1-S2; }
    else if (i < S0+S1+S2+S3+S4)    { s = w4; h = h4; off = i - S0-S1-S2-S3; }
    else if (i < STOT)              { s = w5; h = h5; off = i - S0-S1-S2-S3-S4; }
    else return;
    h[off] = __float2half_rn(s[off]);
}

// ---------------- LayerNorm -> single fp16 plane ---------------------------
__global__ __launch_bounds__(256) void ln16_kernel(const float* __restrict__ x,
                                                   const float* __restrict__ g,
                                                   const float* __restrict__ b,
                                                   __half* __restrict__ o16) {
    int token = blockIdx.x * 8 + (threadIdx.x >> 5);
    int lane  = threadIdx.x & 31;
    const float* p = x + (size_t)token * C_;
    float v[6];
    float s = 0.f;
    #pragma unroll
    for (int j = 0; j < 6; j++) { v[j] = p[lane + 32*j]; s += v[j]; }
    #pragma unroll
    for (int o = 16; o > 0; o >>= 1) s += __shfl_xor_sync(0xffffffffu, s, o);
    float mean = s * (1.f / C_);
    float q = 0.f;
    #pragma unroll
    for (int j = 0; j < 6; j++) { float d = v[j] - mean; q += d * d; }
    #pragma unroll
    for (int o = 16; o > 0; o >>= 1) q += __shfl_xor_sync(0xffffffffu, q, o);
    float rstd = rsqrtf(q * (1.f / C_) + 1e-5f);
    #pragma unroll
    for (int j = 0; j < 6; j++) {
        int c = lane + 32*j;
        o16[(size_t)token * C_ + c] = __float2half_rn((v[j] - mean) * rstd * g[c] + b[c]);
    }
}

// ============ Windowed attention: tensor-core (FA-style), 1 block/window ===
__global__ __launch_bounds__(256) void attn_mma_kernel(const __half* __restrict__ qkv16,
                                                       const float* __restrict__ rpb,
                                                       __half* __restrict__ ao16) {
    __shared__ __half planes[6 * 64 * 40];   // q0,k0,v0,q1,k1,v1 : 30720 B
    __shared__ float  srpb[225 * NH];        // 5400 B
    __shared__ int    gidx[64];
    __shared__ int    rid [64];

    const int tid  = threadIdx.x;
    const int lane = tid & 31;
    const int warp = tid >> 5;
    const int wid  = blockIdx.x;
    const int bb   = wid >> 10;
    const int wib  = wid & 1023;
    const int wh   = wib >> 5, ww = wib & 31;

    if (tid < 64) {
        int ih = tid >> 3, iw = tid & 7;
        int h = wh * 8 + ih, w = ww * 8 + iw;
        gidx[tid] = bb * L_ + ((h + SHIFT) & (H_ - 1)) * W_ + ((w + SHIFT) & (W_ - 1));
        int rh = (h < H_ - WS) ? 0 : ((h < H_ - SHIFT) ? 1 : 2);
        int rw = (w < W_ - WS) ? 0 : ((w < W_ - SHIFT) ? 1 : 2);
        rid[tid] = rh * 3 + rw;
    }
    for (int i = tid; i < 225 * NH; i += 256) srpb[i] = rpb[i];
    __syncthreads();

    const uint32_t pb = smem_to_u32(planes);
    const int hp   = warp >> 2;
    const int r0   = (warp & 3) * 16;
    const int i_lo = r0 + (lane >> 2);
    const int i_hi = i_lo + 8;
    const int ihlo = i_lo >> 3, iwlo = i_lo & 7;
    const int ihhi = i_hi >> 3, iwhi = i_hi & 7;
    const float SCALE = 0.17677669529663687f;

    const uint32_t qbase = pb + hp * 15360;
    const uint32_t kbase = qbase + 5120;
    const uint32_t vbase = qbase + 10240;

    for (int it = 0; it < 3; ++it) {
        const int h0 = it * 2;
        #pragma unroll
        for (int i = 0; i < 6; i++) {
            int t   = tid + i * 256;
            int rowid = t >> 2, seg = t & 3;
            int p   = rowid >> 6, tok = rowid & 63;
            int mat = p % 3, php = p / 3;
            const __half* g = qkv16 + (size_t)gidx[tok] * (3*C_) + mat * C_ + (h0 + php) * HD + seg * 8;
            uint32_t d = pb + p * 5120 + tok * 80 + seg * 16;
            CP_ASYNC(d, g, 16);
        }
        CP_COMMIT();
        asm volatile("cp.async.wait_group 0;" ::: "memory");
        __syncthreads();

        const int head = h0 + hp;
        float S[8][4];
        #pragma unroll
        for (int t = 0; t < 8; t++)
            #pragma unroll
            for (int q = 0; q < 4; q++) S[t][q] = 0.f;
        #pragma unroll
        for (int ks = 0; ks < 2; ks++) {
            uint32_t qf[4];
            LDSM4(qf, qbase + (r0 + (lane & 15)) * 80 + ks * 32 + ((lane >> 4) & 1) * 16);
            #pragma unroll
            for (int np = 0; np < 4; np++) {
                uint32_t kf[4];
                LDSM4(kf, kbase + ((lane & 7) + ((lane >> 4) & 1) * 8 + np * 16) * 80
                          + ks * 32 + ((lane >> 3) & 1) * 16);
                MMA_F16(S[np*2+0], qf, kf[0], kf[1]);
                MMA_F16(S[np*2+1], qf, kf[2], kf[3]);
            }
        }
        const int ridlo = rid[i_lo], ridhi = rid[i_hi];
        float mlo = -1e30f, mhi = -1e30f;
        #pragma unroll
        for (int t = 0; t < 8; t++) {
            int jc = (t >> 1) * 16 + (t & 1) * 8 + (lane & 3) * 2;
            #pragma unroll
            for (int e = 0; e < 2; e++) {
                int j = jc + e;
                int jh = j >> 3, jw = j & 7;
                float blo = srpb[((ihlo - jh + 7) * 15 + (iwlo - jw + 7)) * NH + head];
                float bhi = srpb[((ihhi - jh + 7) * 15 + (iwhi - jw + 7)) * NH + head];
                int rj = rid[j];
                float v0 = S[t][e]     * SCALE + blo + ((ridlo != rj) ? -100.f : 0.f);
                float v1 = S[t][e + 2] * SCALE + bhi + ((ridhi != rj) ? -100.f : 0.f);
                S[t][e] = v0; S[t][e + 2] = v1;
                mlo = fmaxf(mlo, v0); mhi = fmaxf(mhi, v1);
            }
        }
        mlo = fmaxf(mlo, __shfl_xor_sync(0xffffffffu, mlo, 1));
        mlo = fmaxf(mlo, __shfl_xor_sync(0xffffffffu, mlo, 2));
        mhi = fmaxf(mhi, __shfl_xor_sync(0xffffffffu, mhi, 1));
        mhi = fmaxf(mhi, __shfl_xor_sync(0xffffffffu, mhi, 2));
        float slo = 0.f, shi = 0.f;
        #pragma unroll
        for (int t = 0; t < 8; t++) {
            #pragma unroll
            for (int e = 0; e < 2; e++) {
                float v0 = __expf(S[t][e] - mlo);
                float v1 = __expf(S[t][e + 2] - mhi);
                S[t][e] = v0; S[t][e + 2] = v1;
                slo += v0; shi += v1;
            }
        }
        slo += __shfl_xor_sync(0xffffffffu, slo, 1);
        slo += __shfl_xor_sync(0xffffffffu, slo, 2);
        shi += __shfl_xor_sync(0xffffffffu, shi, 1);
        shi += __shfl_xor_sync(0xffffffffu, shi, 2);
        float ilo = 1.f / slo, ihi2 = 1.f / shi;
        uint32_t pa[4][4];
        #pragma unroll
        for (int kt = 0; kt < 4; kt++) {
            pa[kt][0] = pack_h2(S[kt*2][0] * ilo,  S[kt*2][1] * ilo);
            pa[kt][1] = pack_h2(S[kt*2][2] * ihi2, S[kt*2][3] * ihi2);
            pa[kt][2] = pack_h2(S[kt*2+1][0] * ilo,  S[kt*2+1][1] * ilo);
            pa[kt][3] = pack_h2(S[kt*2+1][2] * ihi2, S[kt*2+1][3] * ihi2);
        }
        float O[4][4];
        #pragma unroll
        for (int t = 0; t < 4; t++)
            #pragma unroll
            for (int q = 0; q < 4; q++) O[t][q] = 0.f;
        #pragma unroll
        for (int kt = 0; kt < 4; kt++) {
            #pragma unroll
            for (int nc = 0; nc < 2; nc++) {
                uint32_t vf[4];
                LDSM4T(vf, vbase + (kt * 16 + (lane & 7) + ((lane >> 3) & 1) * 8) * 80
                           + nc * 32 + ((lane >> 4) & 1) * 16);
                MMA_F16(O[nc*2+0], pa[kt], vf[0], vf[1]);
                MMA_F16(O[nc*2+1], pa[kt], vf[2], vf[3]);
            }
        }
        #pragma unroll
        for (int t = 0; t < 4; t++) {
            int col = t * 8 + (lane & 3) * 2;
            *(uint32_t*)(ao16 + (size_t)gidx[i_lo] * C_ + head * HD + col) = pack_h2(O[t][0], O[t][1]);
            *(uint32_t*)(ao16 + (size_t)gidx[i_hi] * C_ + head * HD + col) = pack_h2(O[t][2], O[t][3]);
        }
        __syncthreads();
    }
}

// ---------------- 3x3 conv on r=24 channels, NHWC, pad 1 -------------------
__global__ __launch_bounds__(64) void conv3_kernel(const float* __restrict__ yin,
                                                   const float* __restrict__ w,
                                                   const float* __restrict__ bias,
                                                   __half* __restrict__ y16) {
    __shared__ float patch[100][RED_];
    __shared__ float wts[RED_ * RED_ * 9];
    int tid = threadIdx.x;
    int b = blockIdx.z;
    int th0 = blockIdx.y * 8, tw0 = blockIdx.x * 8;

    for (int d = tid; d < RED_ * RED_ * 9; d += 64) {
        int oc = d % RED_;
        int t2 = d / RED_;
        int kk = t2 % 9;
        int ic = t2 / 9;
        wts[d] = w[(oc * RED_ + ic) * 9 + kk];
    }
    for (int d = tid; d < 100 * RED_; d += 64) {
        int ic = d % RED_;
        int pos = d / RED_;
        int ph = pos / 10, pw = pos % 10;
        int hh = th0 + ph - 1, ww = tw0 + pw - 1;
        float v = 0.f;
        if (hh >= 0 && hh < H_ && ww >= 0 && ww < W_)
            v = yin[((size_t)b * L_ + hh * W_ + ww) * RED_ + ic];
        patch[pos][ic] = v;
    }
    __syncthreads();

    int py = tid >> 3, px = tid & 7;
    float acc[RED_];
    #pragma unroll
    for (int oc = 0; oc < RED_; oc++) acc[oc] = __ldg(bias + oc);
    for (int ic = 0; ic < RED_; ic++) {
        #pragma unroll
        for (int kk = 0; kk < 9; kk++) {
            int kh = kk / 3, kw = kk % 3;
            float pv = patch[(py + kh) * 10 + (px + kw)][ic];
            const float4* wp = (const float4*)&wts[(ic * 9 + kk) * RED_];
            #pragma unroll
            for (int o4 = 0; o4 < 6; o4++) {
                float4 wv = wp[o4];
                acc[o4*4+0] += wv.x * pv; acc[o4*4+1] += wv.y * pv;
                acc[o4*4+2] += wv.z * pv; acc[o4*4+3] += wv.w * pv;
            }
        }
    }
    size_t off = ((size_t)b * L_ + (th0 + py) * W_ + (tw0 + px)) * RED_;
    #pragma unroll
    for (int oc = 0; oc < RED_; oc += 2)
        *(uint32_t*)(y16 + off + oc) = pack_h2(acc[oc], acc[oc + 1]);
}

// ---------------- pool / SE ------------------------------------------------
__global__ void zero_pool_kernel(float* pool) {
    if (threadIdx.x < B_ * C_) pool[threadIdx.x] = 0.f;
}

__global__ __launch_bounds__(192) void pool_kernel(const float* __restrict__ y,
                                                   float* __restrict__ pool) {
    int base = blockIdx.x * 128;
    int b = base >> 16;
    int c = threadIdx.x;
    float acc = 0.f;
    for (int i = 0; i < 128; i++)
        acc += y[(size_t)(base + i) * C_ + c];
    atomicAdd(&pool[b * C_ + c], acc);
}

__global__ __launch_bounds__(192) void se_kernel(const float* __restrict__ pool,
                                                 const float* __restrict__ fc1,
                                                 const float* __restrict__ fc2,
                                                 float* __restrict__ sbuf) {
    __shared__ float t[RED_];
    int tid = threadIdx.x;
    const float inv = 1.f / (float)L_;
    for (int b = 0; b < B_; b++) {
        if (tid < RED_) {
            float s = 0.f;
            for (int c = 0; c < C_; c++)
                s += pool[b * C_ + c] * inv * fc1[tid * C_ + c];
            t[tid] = fmaxf(s, 0.f);
        }
        __syncthreads();
        float s = 0.f;
        #pragma unroll
        for (int j = 0; j < RED_; j++) s += t[j] * fc2[tid * RED_ + j];
        sbuf[b * C_ + tid] = 1.f / (1.f + expf(-s));
        __syncthreads();
    }
}

// ---------------- launch ---------------------------------------------------
extern "C" void kernel_launch(void* const* d_in, const int* in_sizes, int n_in,
                              void* d_out, int out_size) {
    const float* x      = (const float*)d_in[0];
    const float* n1g    = (const float*)d_in[1];
    const float* n1b    = (const float*)d_in[2];
    const float* qkvw   = (const float*)d_in[3];
    const float* qkvb   = (const float*)d_in[4];
    const float* rpb    = (const float*)d_in[5];
    const float* projw  = (const float*)d_in[6];
    const float* projb  = (const float*)d_in[7];
    const float* n2g    = (const float*)d_in[8];
    const float* n2b    = (const float*)d_in[9];
    const float* fc1w   = (const float*)d_in[10];
    const float* fc1b   = (const float*)d_in[11];
    const float* fc2w   = (const float*)d_in[12];
    const float* fc2b   = (const float*)d_in[13];
    const float* c1w    = (const float*)d_in[14];
    const float* c1b    = (const float*)d_in[15];
    const float* c2w    = (const float*)d_in[16];
    const float* c2b    = (const float*)d_in[17];
    const float* c3w    = (const float*)d_in[18];
    const float* c3b    = (const float*)d_in[19];
    const float* sfc1   = (const float*)d_in[20];
    const float* sfc2   = (const float*)d_in[21];
    float* out = (float*)d_out;

    float *x1, *y1, *y, *pool, *sbuf;
    cudaGetSymbolAddress((void**)&x1,   g_x1);
    cudaGetSymbolAddress((void**)&y1,   g_y1);
    cudaGetSymbolAddress((void**)&y,    g_y);
    cudaGetSymbolAddress((void**)&pool, g_pool);
    cudaGetSymbolAddress((void**)&sbuf, g_s);
    __half *qkv16, *xn16, *ao16, *x1n16, *hb16, *y216;
    __half *wq, *wp, *w1, *w2, *wc1, *wc3;
    cudaGetSymbolAddress((void**)&qkv16, g_qkv16);
    cudaGetSymbolAddress((void**)&xn16,  g_xn16);
    cudaGetSymbolAddress((void**)&ao16,  g_ao16);
    cudaGetSymbolAddress((void**)&x1n16, g_x1n16);
    cudaGetSymbolAddress((void**)&hb16,  g_hb16);
    cudaGetSymbolAddress((void**)&y216,  g_y216);
    cudaGetSymbolAddress((void**)&wq,  g_wq);
    cudaGetSymbolAddress((void**)&wp,  g_wp);
    cudaGetSymbolAddress((void**)&w1,  g_w1);
    cudaGetSymbolAddress((void**)&w2,  g_w2);
    cudaGetSymbolAddress((void**)&wc1, g_wc1);
    cudaGetSymbolAddress((void**)&wc3, g_wc3);

    cudaFuncSetAttribute(gemm_cp<0,0>, cudaFuncAttributeMaxDynamicSharedMemorySize, GEMM_SMEM_SZ);
    cudaFuncSetAttribute(gemm_cp<0,1>, cudaFuncAttributeMaxDynamicSharedMemorySize, GEMM_SMEM_SZ);
    cudaFuncSetAttribute(gemm_cp<1,0>, cudaFuncAttributeMaxDynamicSharedMemorySize, GEMM_SMEM_SZ);
    cudaFuncSetAttribute(gemm_cp<2,1>, cudaFuncAttributeMaxDynamicSharedMemorySize, GEMM_SMEM_SZ);
    cudaFuncSetAttribute(gemm_cp<3,0>, cudaFuncAttributeMaxDynamicSharedMemorySize, GEMM_SMEM_SZ);
    cudaFuncSetAttribute(gemm_cp<4,0>, cudaFuncAttributeMaxDynamicSharedMemorySize, GEMM_SMEM_SZ);

    // 1) weight convert (one launch)
    convert_all_kernel<<<(STOT+255)/256, 256>>>(qkvw, projw, fc1w, fc2w, c1w, c3w,
        wq, wp, w1, w2, wc1, wc3);
    // 2) LN1 -> fp16 plane
    ln16_kernel<<<M_/8, 256>>>(x, n1g, n1b, xn16);
    // 3) QKV GEMM -> fp16
    gemm_cp<0,1><<<dim3(9, M_/128), 256, GEMM_SMEM_SZ>>>(xn16, wq, qkvb, nullptr, nullptr, nullptr, nullptr, qkv16, 3*C_, C_);
    // 4) LCE conv1x1 C->24 -> y1 fp32
    gemm_cp<0,0><<<dim3(1, M_/128), 256, GEMM_SMEM_SZ>>>(xn16, wc1, c1b, nullptr, nullptr, nullptr, y1, nullptr, RED_, C_);
    // 5) attention (tensor-core) -> ao fp16
    attn_mma_kernel<<<NWIN, 256>>>(qkv16, rpb, ao16);
    // 6) proj + residual -> x1 fp32
    gemm_cp<1,0><<<dim3(3, M_/128), 256, GEMM_SMEM_SZ>>>(ao16, wp, projb, x, nullptr, nullptr, x1, nullptr, C_, C_);
    // 7) LN2 -> fp16 plane
    ln16_kernel<<<M_/8, 256>>>(x1, n2g, n2b, x1n16);
    // 8) fc1 + GELU -> hb fp16
    gemm_cp<2,1><<<dim3(12, M_/128), 256, GEMM_SMEM_SZ>>>(x1n16, w1, fc1b, nullptr, nullptr, nullptr, nullptr, hb16, HID_, C_);
    // 9) LCE conv3x3 -> y2 fp16
    conv3_kernel<<<dim3(W_/8, H_/8, B_), 64>>>(y1, c2w, c2b, y216);
    // 10) LCE conv1x1 24->192 + LeakyReLU -> y fp32
    gemm_cp<3,0><<<dim3(3, M_/128), 256, GEMM_SMEM_SZ>>>(y216, wc3, c3b, nullptr, nullptr, nullptr, y, nullptr, C_, RED_);
    // 11) global avg pool + SE gate
    zero_pool_kernel<<<1, 384>>>(pool);
    pool_kernel<<<M_/128, 192>>>(y, pool);
    se_kernel<<<1, 192>>>(pool, sfc1, sfc2, sbuf);
    // 12) fc2 + residual + SE-gated local context -> out
    gemm_cp<4,0><<<dim3(3, M_/128), 256, GEMM_SMEM_SZ>>>(hb16, w2, fc2b, x1, y, sbuf, out, nullptr, C_, HID_);
}

// round 13
// speedup vs baseline: 7.2176x; 1.0648x over previous
#include <cuda_runtime.h>
#include <cuda_fp16.h>
#include <math.h>
#include <stdint.h>

#define B_    2
#define H_    256
#define W_    256
#define C_    192
#define L_    (H_*W_)         // 65536
#define M_    (B_*L_)         // 131072
#define HID_  768
#define NH    6
#define HD    32
#define WS    8
#define SHIFT 4
#define NWIN  (B_*(H_/WS)*(W_/WS))  // 2048
#define RED_  24

// ---------------- scratch (device globals; no allocations) ----------------
__device__ float g_x1 [M_*C_];
__device__ float g_y1 [M_*RED_];
__device__ float g_y  [M_*C_];
__device__ float g_pool[B_*C_];
__device__ float g_s  [B_*C_];
// fp16 activation planes
__device__ __half g_qkv16[(size_t)M_*3*C_];
__device__ __half g_xn16 [M_*C_];
__device__ __half g_ao16 [M_*C_];
__device__ __half g_x1n16[M_*C_];
__device__ __half g_hb16 [(size_t)M_*HID_];
__device__ __half g_y216 [M_*RED_];
// fp16 weights (single plane)
__device__ __half g_wq [3*C_*C_];
__device__ __half g_wp [C_*C_];
__device__ __half g_w1 [HID_*C_];
__device__ __half g_w2 [C_*HID_];
__device__ __half g_wc1[RED_*C_];
__device__ __half g_wc3[C_*RED_];

// ======================= helpers ===========================================
__device__ __forceinline__ uint32_t smem_to_u32(const void* p) {
    uint32_t a;
    asm("{ .reg .u64 t; cvta.to.shared.u64 t, %1; cvt.u32.u64 %0, t; }" : "=r"(a) : "l"(p));
    return a;
}
__device__ __forceinline__ uint32_t pack_h2(float x, float y) {
    __half2 h = __floats2half2_rn(x, y);
    return *reinterpret_cast<uint32_t*>(&h);
}
#define LDSM4(r, addr) \
    asm volatile("ldmatrix.sync.aligned.m8n8.x4.shared.b16 {%0,%1,%2,%3}, [%4];" \
        : "=r"((r)[0]), "=r"((r)[1]), "=r"((r)[2]), "=r"((r)[3]) : "r"(addr))
#define LDSM4T(r, addr) \
    asm volatile("ldmatrix.sync.aligned.m8n8.x4.trans.shared.b16 {%0,%1,%2,%3}, [%4];" \
        : "=r"((r)[0]), "=r"((r)[1]), "=r"((r)[2]), "=r"((r)[3]) : "r"(addr))
#define MMA_F16(d, a, b0, b1) \
    asm volatile("mma.sync.aligned.m16n8k16.row.col.f32.f16.f16.f32 " \
        "{%0,%1,%2,%3},{%4,%5,%6,%7},{%8,%9},{%0,%1,%2,%3};" \
        : "+f"((d)[0]), "+f"((d)[1]), "+f"((d)[2]), "+f"((d)[3]) \
        : "r"((a)[0]), "r"((a)[1]), "r"((a)[2]), "r"((a)[3]), "r"(b0), "r"(b1))
#define CP_ASYNC(dst, src, sz) \
    asm volatile("cp.async.cg.shared.global [%0], [%1], 16, %2;" \
        :: "r"(dst), "l"(src), "r"(sz))
#define CP_COMMIT() asm volatile("cp.async.commit_group;" ::: "memory")

// ======================= fp16 mma.sync GEMM (128x96 tile, 4-stage) =========
// out[M,N] = epi(A @ W^T + bias); A and W single fp16 planes [rows][K].
// CTA tile 128x96, BK=32. 8 warps = 4(M) x 2(N); warp tile 32x48.
// EPI: 0 none, 1 +res, 2 exact GELU, 3 LeakyReLU(0.2),
//      4 +res + gate (out = v + res + yy*s[b,col]). OUTP: 1 = write fp16 plane.
#define STG_STRIDE 17920   // A 10240 | W 7680
#define W_OFF 10240
#define NSTG 4
#define GEMM_SMEM_SZ (NSTG*STG_STRIDE)   // 71680

template<int EPI, int OUTP>
__device__ __forceinline__ void gemm_body(const __half* __restrict__ A16,
                                          const __half* __restrict__ Wt,
                                          const float* __restrict__ bias,
                                          const float* __restrict__ res,
                                          const float* __restrict__ yy,
                                          const float* __restrict__ sgate,
                                          float* __restrict__ out,
                                          __half* __restrict__ out16,
                                          int N, int K, char* smem) {
    const int tid  = threadIdx.x;
    const int lane = tid & 31;
    const int warp = tid >> 5;
    const int m0 = blockIdx.y * 128, n0 = blockIdx.x * 96;
    const int wm = (warp & 3) * 32, wn = (warp >> 2) * 48;
    const int nch = (K + 31) >> 5;

#define ISSUE(stg, c) do { \
    char* base_ = smem + (stg) * STG_STRIDE; \
    int k0_ = (c) * 32; \
    _Pragma("unroll") \
    for (int i = 0; i < 2; i++) { \
        int t = tid + i * 256; \
        int row = t >> 2, seg = t & 3; \
        int ke = k0_ + seg * 8; \
        int srcsz = (K - ke) * 2; \
        srcsz = srcsz < 0 ? 0 : (srcsz > 16 ? 16 : srcsz); \
        const __half* g = A16 + (size_t)(m0 + row) * K + (srcsz ? ke : 0); \
        uint32_t d = smem_to_u32(base_ + row * 80 + seg * 16); \
        CP_ASYNC(d, g, srcsz); \
    } \
    _Pragma("unroll") \
    for (int i = 0; i < 2; i++) { \
        int t = tid + i * 256; \
        if (t < 384) { \
            int row = t >> 2, seg = t & 3; \
            int ke = k0_ + seg * 8; \
            int srcsz = (K - ke) * 2; \
            srcsz = srcsz < 0 ? 0 : (srcsz > 16 ? 16 : srcsz); \
            if (n0 + row >= N) srcsz = 0; \
            int grow = (n0 + row < N) ? (n0 + row) : 0; \
            const __half* g = Wt + (size_t)grow * K + (srcsz ? ke : 0); \
            uint32_t d = smem_to_u32(base_ + W_OFF + row * 80 + seg * 16); \
            CP_ASYNC(d, g, srcsz); \
        } \
    } \
    CP_COMMIT(); } while (0)

    float acc[2][6][4];
    #pragma unroll
    for (int i = 0; i < 2; i++)
        #pragma unroll
        for (int j = 0; j < 6; j++)
            #pragma unroll
            for (int q = 0; q < 4; q++) acc[i][j][q] = 0.f;

    ISSUE(0, 0);
    if (nch > 1) ISSUE(1, 1);
    if (nch > 2) ISSUE(2, 2);

    int sc = 0;
    for (int c = 0; c < nch; c++) {
        int rem = nch - 1 - c;
        if (rem >= 2)      asm volatile("cp.async.wait_group 2;" ::: "memory");
        else if (rem == 1) asm volatile("cp.async.wait_group 1;" ::: "memory");
        else               asm volatile("cp.async.wait_group 0;" ::: "memory");
        __syncthreads();
        char* base = smem + sc * STG_STRIDE;
        #pragma unroll
        for (int ks = 0; ks < 2; ks++) {
            uint32_t af[2][4], wf[3][4];
            #pragma unroll
            for (int mt = 0; mt < 2; mt++) {
                int row = wm + mt * 16 + (lane & 15);
                int colb = ks * 32 + ((lane >> 4) & 1) * 16;
                LDSM4(af[mt], smem_to_u32(base + row * 80 + colb));
            }
            #pragma unroll
            for (int np = 0; np < 3; np++) {
                int n = wn + np * 16 + (lane & 7) + ((lane >> 4) & 1) * 8;
                int colb = ks * 32 + ((lane >> 3) & 1) * 16;
                LDSM4(wf[np], smem_to_u32(base + W_OFF + n * 80 + colb));
            }
            #pragma unroll
            for (int mt = 0; mt < 2; mt++)
                #pragma unroll
                for (int nt = 0; nt < 6; nt++) {
                    int np = nt >> 1, h = (nt & 1) * 2;
                    MMA_F16(acc[mt][nt], af[mt], wf[np][h], wf[np][h+1]);
                }
        }
        if (c + 3 < nch) {
            int si = sc + 3; if (si >= NSTG) si -= NSTG;
            ISSUE(si, c + 3);
        }
        sc = (sc + 1 == NSTG) ? 0 : sc + 1;
    }

    // ---- epilogue ----
    #pragma unroll
    for (int mt = 0; mt < 2; mt++) {
        int r0 = m0 + wm + mt * 16 + (lane >> 2);
        #pragma unroll
        for (int nt = 0; nt < 6; nt++) {
            int col = n0 + wn + nt * 8 + (lane & 3) * 2;
            if (col < N) {
                float b0v = bias[col], b1v = bias[col + 1];
                #pragma unroll
                for (int rr = 0; rr < 2; rr++) {
                    int r = r0 + rr * 8;
                    float v0 = acc[mt][nt][rr*2+0] + b0v;
                    float v1 = acc[mt][nt][rr*2+1] + b1v;
                    if (EPI == 1 || EPI == 4) {
                        float2 rv = *(const float2*)(res + (size_t)r * N + col);
                        v0 += rv.x; v1 += rv.y;
                    }
                    if (EPI == 2) {
                        v0 = 0.5f * v0 * (1.f + erff(v0 * 0.70710678118654752f));
                        v1 = 0.5f * v1 * (1.f + erff(v1 * 0.70710678118654752f));
                    }
                    if (EPI == 3) {
                        v0 = (v0 >= 0.f) ? v0 : 0.2f * v0;
                        v1 = (v1 >= 0.f) ? v1 : 0.2f * v1;
                    }
                    if (EPI == 4) {
                        const float* sb = sgate + (r >> 16) * C_;
                        float2 yv = *(const float2*)(yy + (size_t)r * N + col);
                        v0 += yv.x * sb[col];
                        v1 += yv.y * sb[col + 1];
                    }
                    if (OUTP) {
                        *(uint32_t*)(out16 + (size_t)r * N + col) = pack_h2(v0, v1);
                    } else {
                        *(float2*)(out + (size_t)r * N + col) = make_float2(v0, v1);
                    }
                }
            }
        }
    }
#undef ISSUE
}

template<int EPI, int OUTP>
__global__ __launch_bounds__(256, 2) void gemm_cp(const __half* __restrict__ A16,
                                                  const __half* __restrict__ Wt,
                                                  const float* __restrict__ bias,
                                                  const float* __restrict__ res,
                                                  const float* __restrict__ yy,
                                                  const float* __restrict__ sgate,
                                                  float* __restrict__ out,
                                                  __half* __restrict__ out16,
                                                  int N, int K) {
    extern __shared__ char smem[];
    gemm_body<EPI, OUTP>(A16, Wt, bias, res, yy, sgate, out, out16, N, K, smem);
}

// ---------------- merged weight convert (6 tensors, one launch) ------------
#define S0 (3*C_*C_)
#define S1 (C_*C_)
#define S2 (HID_*C_)
#define S3 (C_*HID_)
#define S4 (RED_*C_)
#define S5 (C_*RED_)
#define STOT (S0+S1+S2+S3+S4+S5)
__global__ __launch_bounds__(256) void convert_all_kernel(
        const float* __restrict__ w0, const float* __restrict__ w1,
        const float* __restrict__ w2, const float* __restrict__ w3,
        const float* __restrict__ w4, const float* __restrict__ w5,
        __half* h0, __half* h1, __half* h2, __half* h3, __half* h4, __half* h5) {
    int i = blockIdx.x * 256 + threadIdx.x;
    const float* s; __half* h; int off;
    if      (i < S0)                { s = w0; h = h0; off = i; }
    else if (i < S0+S1)             { s = w1; h = h1; off = i - S0; }
    else if (i < S0+S1+S2)          { s = w2; h = h2; off = i - S0-S1; }
    else if (i < S0+S1+S2+S3)       { s = w3; h = h3; off = i - S0-S1-S2; }
    else if (i < S0+S1+S2+S3+S4)    { s = w4; h = h4; off = i - S0-S1-S2-S3; }
    else if (i < STOT)              { s = w5; h = h5; off = i - S0-S1-S2-S3-S4; }
    else return;
    h[off] = __float2half_rn(s[off]);
}

// ---------------- LayerNorm -> single fp16 plane ---------------------------
__global__ __launch_bounds__(256) void ln16_kernel(const float* __restrict__ x,
                                                   const float* __restrict__ g,
                                                   const float* __restrict__ b,
                                                   __half* __restrict__ o16) {
    int token = blockIdx.x * 8 + (threadIdx.x >> 5);
    int lane  = threadIdx.x & 31;
    const float* p = x + (size_t)token * C_;
    float v[6];
    float s = 0.f;
    #pragma unroll
    for (int j = 0; j < 6; j++) { v[j] = p[lane + 32*j]; s += v[j]; }
    #pragma unroll
    for (int o = 16; o > 0; o >>= 1) s += __shfl_xor_sync(0xffffffffu, s, o);
    float mean = s * (1.f / C_);
    float q = 0.f;
    #pragma unroll
    for (int j = 0; j < 6; j++) { float d = v[j] - mean; q += d * d; }
    #pragma unroll
    for (int o = 16; o > 0; o >>= 1) q += __shfl_xor_sync(0xffffffffu, q, o);
    float rstd = rsqrtf(q * (1.f / C_) + 1e-5f);
    #pragma unroll
    for (int j = 0; j < 6; j++) {
        int c = lane + 32*j;
        o16[(size_t)token * C_ + c] = __float2half_rn((v[j] - mean) * rstd * g[c] + b[c]);
    }
}

// ============ Windowed attention: tensor-core, double-buffered head pairs ==
// 8 warps: warps 0-3 = head h0, warps 4-7 = head h0+1. 3 head-pair iters.
// Dynamic smem: 2 buffers x 6 planes x (64 rows x 80B) = 61440 B.
#define ATTN_SMEM (2*6*5120)
__global__ __launch_bounds__(256, 2) void attn_mma_kernel(const __half* __restrict__ qkv16,
                                                          const float* __restrict__ rpb,
                                                          __half* __restrict__ ao16) {
    extern __shared__ char dsmem[];
    __shared__ float  srpb[225 * NH];        // 5400 B
    __shared__ int    gidx[64];
    __shared__ int    rid [64];

    const int tid  = threadIdx.x;
    const int lane = tid & 31;
    const int warp = tid >> 5;
    const int wid  = blockIdx.x;
    const int bb   = wid >> 10;
    const int wib  = wid & 1023;
    const int wh   = wib >> 5, ww = wib & 31;

    if (tid < 64) {
        int ih = tid >> 3, iw = tid & 7;
        int h = wh * 8 + ih, w = ww * 8 + iw;
        gidx[tid] = bb * L_ + ((h + SHIFT) & (H_ - 1)) * W_ + ((w + SHIFT) & (W_ - 1));
        int rh = (h < H_ - WS) ? 0 : ((h < H_ - SHIFT) ? 1 : 2);
        int rw = (w < W_ - WS) ? 0 : ((w < W_ - SHIFT) ? 1 : 2);
        rid[tid] = rh * 3 + rw;
    }
    for (int i = tid; i < 225 * NH; i += 256) srpb[i] = rpb[i];
    __syncthreads();   // gidx ready for load macro below

    const uint32_t pb = smem_to_u32(dsmem);
    const int hp   = warp >> 2;
    const int r0   = (warp & 3) * 16;
    const int i_lo = r0 + (lane >> 2);
    const int i_hi = i_lo + 8;
    const int ihlo = i_lo >> 3, iwlo = i_lo & 7;
    const int ihhi = i_hi >> 3, iwhi = i_hi & 7;
    const float SCALE = 0.17677669529663687f;

#define ATTN_LOAD(buf, h0v) do { \
    _Pragma("unroll") \
    for (int i = 0; i < 6; i++) { \
        int t   = tid + i * 256; \
        int rowid = t >> 2, seg = t & 3; \
        int p   = rowid >> 6, tok = rowid & 63; \
        int mat = p % 3, php = p / 3; \
        const __half* g = qkv16 + (size_t)gidx[tok] * (3*C_) + mat * C_ + ((h0v) + php) * HD + seg * 8; \
        uint32_t d = pb + (buf) * 30720 + p * 5120 + tok * 80 + seg * 16; \
        CP_ASYNC(d, g, 16); \
    } \
    CP_COMMIT(); } while (0)

    ATTN_LOAD(0, 0);

    for (int it = 0; it < 3; ++it) {
        const int buf = it & 1;
        const int h0 = it * 2;
        asm volatile("cp.async.wait_group 0;" ::: "memory");
        __syncthreads();   // current buffer ready; prior buffer reads done
        if (it + 1 < 3) ATTN_LOAD(buf ^ 1, h0 + 2);

        const uint32_t qbase = pb + buf * 30720 + hp * 15360;
        const uint32_t kbase = qbase + 5120;
        const uint32_t vbase = qbase + 10240;
        const int head = h0 + hp;

        float S[8][4];
        #pragma unroll
        for (int t = 0; t < 8; t++)
            #pragma unroll
            for (int q = 0; q < 4; q++) S[t][q] = 0.f;
        #pragma unroll
        for (int ks = 0; ks < 2; ks++) {
            uint32_t qf[4];
            LDSM4(qf, qbase + (r0 + (lane & 15)) * 80 + ks * 32 + ((lane >> 4) & 1) * 16);
            #pragma unroll
            for (int np = 0; np < 4; np++) {
                uint32_t kf[4];
                LDSM4(kf, kbase + ((lane & 7) + ((lane >> 4) & 1) * 8 + np * 16) * 80
                          + ks * 32 + ((lane >> 3) & 1) * 16);
                MMA_F16(S[np*2+0], qf, kf[0], kf[1]);
                MMA_F16(S[np*2+1], qf, kf[2], kf[3]);
            }
        }
        const int ridlo = rid[i_lo], ridhi = rid[i_hi];
        float mlo = -1e30f, mhi = -1e30f;
        #pragma unroll
        for (int t = 0; t < 8; t++) {
            int jc = (t >> 1) * 16 + (t & 1) * 8 + (lane & 3) * 2;
            #pragma unroll
            for (int e = 0; e < 2; e++) {
                int j = jc + e;
                int jh = j >> 3, jw = j & 7;
                float blo = srpb[((ihlo - jh + 7) * 15 + (iwlo - jw + 7)) * NH + head];
                float bhi = srpb[((ihhi - jh + 7) * 15 + (iwhi - jw + 7)) * NH + head];
                int rj = rid[j];
                float v0 = S[t][e]     * SCALE + blo + ((ridlo != rj) ? -100.f : 0.f);
                float v1 = S[t][e + 2] * SCALE + bhi + ((ridhi != rj) ? -100.f : 0.f);
                S[t][e] = v0; S[t][e + 2] = v1;
                mlo = fmaxf(mlo, v0); mhi = fmaxf(mhi, v1);
            }
        }
        mlo = fmaxf(mlo, __shfl_xor_sync(0xffffffffu, mlo, 1));
        mlo = fmaxf(mlo, __shfl_xor_sync(0xffffffffu, mlo, 2));
        mhi = fmaxf(mhi, __shfl_xor_sync(0xffffffffu, mhi, 1));
        mhi = fmaxf(mhi, __shfl_xor_sync(0xffffffffu, mhi, 2));
        float slo = 0.f, shi = 0.f;
        #pragma unroll
        for (int t = 0; t < 8; t++) {
            #pragma unroll
            for (int e = 0; e < 2; e++) {
                float v0 = __expf(S[t][e] - mlo);
                float v1 = __expf(S[t][e + 2] - mhi);
                S[t][e] = v0; S[t][e + 2] = v1;
                slo += v0; shi += v1;
            }
        }
        slo += __shfl_xor_sync(0xffffffffu, slo, 1);
        slo += __shfl_xor_sync(0xffffffffu, slo, 2);
        shi += __shfl_xor_sync(0xffffffffu, shi, 1);
        shi += __shfl_xor_sync(0xffffffffu, shi, 2);
        float ilo = 1.f / slo, ihi2 = 1.f / shi;
        uint32_t pa[4][4];
        #pragma unroll
        for (int kt = 0; kt < 4; kt++) {
            pa[kt][0] = pack_h2(S[kt*2][0] * ilo,  S[kt*2][1] * ilo);
            pa[kt][1] = pack_h2(S[kt*2][2] * ihi2, S[kt*2][3] * ihi2);
            pa[kt][2] = pack_h2(S[kt*2+1][0] * ilo,  S[kt*2+1][1] * ilo);
            pa[kt][3] = pack_h2(S[kt*2+1][2] * ihi2, S[kt*2+1][3] * ihi2);
        }
        float O[4][4];
        #pragma unroll
        for (int t = 0; t < 4; t++)
            #pragma unroll
            for (int q = 0; q < 4; q++) O[t][q] = 0.f;
        #pragma unroll
        for (int kt = 0; kt < 4; kt++) {
            #pragma unroll
            for (int nc = 0; nc < 2; nc++) {
                uint32_t vf[4];
                LDSM4T(vf, vbase + (kt * 16 + (lane & 7) + ((lane >> 3) & 1) * 8) * 80
                           + nc * 32 + ((lane >> 4) & 1) * 16);
                MMA_F16(O[nc*2+0], pa[kt], vf[0], vf[1]);
                MMA_F16(O[nc*2+1], pa[kt], vf[2], vf[3]);
            }
        }
        #pragma unroll
        for (int t = 0; t < 4; t++) {
            int col = t * 8 + (lane & 3) * 2;
            *(uint32_t*)(ao16 + (size_t)gidx[i_lo] * C_ + head * HD + col) = pack_h2(O[t][0], O[t][1]);
            *(uint32_t*)(ao16 + (size_t)gidx[i_hi] * C_ + head * HD + col) = pack_h2(O[t][2], O[t][3]);
        }
    }
#undef ATTN_LOAD
}

// ---------------- 3x3 conv on r=24 channels, NHWC, pad 1 -------------------
__global__ __launch_bounds__(64) void conv3_kernel(const float* __restrict__ yin,
                                                   const float* __restrict__ w,
                                                   const float* __restrict__ bias,
                                                   __half* __restrict__ y16) {
    __shared__ float patch[100][RED_];
    __shared__ float wts[RED_ * RED_ * 9];
    int tid = threadIdx.x;
    int b = blockIdx.z;
    int th0 = blockIdx.y * 8, tw0 = blockIdx.x * 8;

    for (int d = tid; d < RED_ * RED_ * 9; d += 64) {
        int oc = d % RED_;
        int t2 = d / RED_;
        int kk = t2 % 9;
        int ic = t2 / 9;
        wts[d] = w[(oc * RED_ + ic) * 9 + kk];
    }
    for (int d = tid; d < 100 * RED_; d += 64) {
        int ic = d % RED_;
        int pos = d / RED_;
        int ph = pos / 10, pw = pos % 10;
        int hh = th0 + ph - 1, ww = tw0 + pw - 1;
        float v = 0.f;
        if (hh >= 0 && hh < H_ && ww >= 0 && ww < W_)
            v = yin[((size_t)b * L_ + hh * W_ + ww) * RED_ + ic];
        patch[pos][ic] = v;
    }
    __syncthreads();

    int py = tid >> 3, px = tid & 7;
    float acc[RED_];
    #pragma unroll
    for (int oc = 0; oc < RED_; oc++) acc[oc] = __ldg(bias + oc);
    for (int ic = 0; ic < RED_; ic++) {
        #pragma unroll
        for (int kk = 0; kk < 9; kk++) {
            int kh = kk / 3, kw = kk % 3;
            float pv = patch[(py + kh) * 10 + (px + kw)][ic];
            const float4* wp = (const float4*)&wts[(ic * 9 + kk) * RED_];
            #pragma unroll
            for (int o4 = 0; o4 < 6; o4++) {
                float4 wv = wp[o4];
                acc[o4*4+0] += wv.x * pv; acc[o4*4+1] += wv.y * pv;
                acc[o4*4+2] += wv.z * pv; acc[o4*4+3] += wv.w * pv;
            }
        }
    }
    size_t off = ((size_t)b * L_ + (th0 + py) * W_ + (tw0 + px)) * RED_;
    #pragma unroll
    for (int oc = 0; oc < RED_; oc += 2)
        *(uint32_t*)(y16 + off + oc) = pack_h2(acc[oc], acc[oc + 1]);
}

// ---------------- pool / SE ------------------------------------------------
__global__ void zero_pool_kernel(float* pool) {
    if (threadIdx.x < B_ * C_) pool[threadIdx.x] = 0.f;
}

__global__ __launch_bounds__(192) void pool_kernel(const float* __restrict__ y,
                                                   float* __restrict__ pool) {
    int base = blockIdx.x * 128;
    int b = base >> 16;
    int c = threadIdx.x;
    float acc = 0.f;
    for (int i = 0; i < 128; i++)
        acc += y[(size_t)(base + i) * C_ + c];
    atomicAdd(&pool[b * C_ + c], acc);
}

__global__ __launch_bounds__(192) void se_kernel(const float* __restrict__ pool,
                                                 const float* __restrict__ fc1,
                                                 const float* __restrict__ fc2,
                                                 float* __restrict__ sbuf) {
    __shared__ float t[RED_];
    int tid = threadIdx.x;
    const float inv = 1.f / (float)L_;
    for (int b = 0; b < B_; b++) {
        if (tid < RED_) {
            float s = 0.f;
            for (int c = 0; c < C_; c++)
                s += pool[b * C_ + c] * inv * fc1[tid * C_ + c];
            t[tid] = fmaxf(s, 0.f);
        }
        __syncthreads();
        float s = 0.f;
        #pragma unroll
        for (int j = 0; j < RED_; j++) s += t[j] * fc2[tid * RED_ + j];
        sbuf[b * C_ + tid] = 1.f / (1.f + expf(-s));
        __syncthreads();
    }
}

// ---------------- launch ---------------------------------------------------
extern "C" void kernel_launch(void* const* d_in, const int* in_sizes, int n_in,
                              void* d_out, int out_size) {
    const float* x      = (const float*)d_in[0];
    const float* n1g    = (const float*)d_in[1];
    const float* n1b    = (const float*)d_in[2];
    const float* qkvw   = (const float*)d_in[3];
    const float* qkvb   = (const float*)d_in[4];
    const float* rpb    = (const float*)d_in[5];
    const float* projw  = (const float*)d_in[6];
    const float* projb  = (const float*)d_in[7];
    const float* n2g    = (const float*)d_in[8];
    const float* n2b    = (const float*)d_in[9];
    const float* fc1w   = (const float*)d_in[10];
    const float* fc1b   = (const float*)d_in[11];
    const float* fc2w   = (const float*)d_in[12];
    const float* fc2b   = (const float*)d_in[13];
    const float* c1w    = (const float*)d_in[14];
    const float* c1b    = (const float*)d_in[15];
    const float* c2w    = (const float*)d_in[16];
    const float* c2b    = (const float*)d_in[17];
    const float* c3w    = (const float*)d_in[18];
    const float* c3b    = (const float*)d_in[19];
    const float* sfc1   = (const float*)d_in[20];
    const float* sfc2   = (const float*)d_in[21];
    float* out = (float*)d_out;

    float *x1, *y1, *y, *pool, *sbuf;
    cudaGetSymbolAddress((void**)&x1,   g_x1);
    cudaGetSymbolAddress((void**)&y1,   g_y1);
    cudaGetSymbolAddress((void**)&y,    g_y);
    cudaGetSymbolAddress((void**)&pool, g_pool);
    cudaGetSymbolAddress((void**)&sbuf, g_s);
    __half *qkv16, *xn16, *ao16, *x1n16, *hb16, *y216;
    __half *wq, *wp, *w1, *w2, *wc1, *wc3;
    cudaGetSymbolAddress((void**)&qkv16, g_qkv16);
    cudaGetSymbolAddress((void**)&xn16,  g_xn16);
    cudaGetSymbolAddress((void**)&ao16,  g_ao16);
    cudaGetSymbolAddress((void**)&x1n16, g_x1n16);
    cudaGetSymbolAddress((void**)&hb16,  g_hb16);
    cudaGetSymbolAddress((void**)&y216,  g_y216);
    cudaGetSymbolAddress((void**)&wq,  g_wq);
    cudaGetSymbolAddress((void**)&wp,  g_wp);
    cudaGetSymbolAddress((void**)&w1,  g_w1);
    cudaGetSymbolAddress((void**)&w2,  g_w2);
    cudaGetSymbolAddress((void**)&wc1, g_wc1);
    cudaGetSymbolAddress((void**)&wc3, g_wc3);

    cudaFuncSetAttribute(gemm_cp<0,0>, cudaFuncAttributeMaxDynamicSharedMemorySize, GEMM_SMEM_SZ);
    cudaFuncSetAttribute(gemm_cp<0,1>, cudaFuncAttributeMaxDynamicSharedMemorySize, GEMM_SMEM_SZ);
    cudaFuncSetAttribute(gemm_cp<1,0>, cudaFuncAttributeMaxDynamicSharedMemorySize, GEMM_SMEM_SZ);
    cudaFuncSetAttribute(gemm_cp<2,1>, cudaFuncAttributeMaxDynamicSharedMemorySize, GEMM_SMEM_SZ);
    cudaFuncSetAttribute(gemm_cp<3,0>, cudaFuncAttributeMaxDynamicSharedMemorySize, GEMM_SMEM_SZ);
    cudaFuncSetAttribute(gemm_cp<4,0>, cudaFuncAttributeMaxDynamicSharedMemorySize, GEMM_SMEM_SZ);
    cudaFuncSetAttribute(attn_mma_kernel, cudaFuncAttributeMaxDynamicSharedMemorySize, ATTN_SMEM);

    // 1) weight convert (one launch)
    convert_all_kernel<<<(STOT+255)/256, 256>>>(qkvw, projw, fc1w, fc2w, c1w, c3w,
        wq, wp, w1, w2, wc1, wc3);
    // 2) LN1 -> fp16 plane
    ln16_kernel<<<M_/8, 256>>>(x, n1g, n1b, xn16);
    // 3) QKV GEMM -> fp16
    gemm_cp<0,1><<<dim3(6, M_/128), 256, GEMM_SMEM_SZ>>>(xn16, wq, qkvb, nullptr, nullptr, nullptr, nullptr, qkv16, 3*C_, C_);
    // 4) LCE conv1x1 C->24 -> y1 fp32
    gemm_cp<0,0><<<dim3(1, M_/128), 256, GEMM_SMEM_SZ>>>(xn16, wc1, c1b, nullptr, nullptr, nullptr, y1, nullptr, RED_, C_);
    // 5) attention (tensor-core, double-buffered) -> ao fp16
    attn_mma_kernel<<<NWIN, 256, ATTN_SMEM>>>(qkv16, rpb, ao16);
    // 6) proj + residual -> x1 fp32
    gemm_cp<1,0><<<dim3(2, M_/128), 256, GEMM_SMEM_SZ>>>(ao16, wp, projb, x, nullptr, nullptr, x1, nullptr, C_, C_);
    // 7) LN2 -> fp16 plane
    ln16_kernel<<<M_/8, 256>>>(x1, n2g, n2b, x1n16);
    // 8) fc1 + GELU -> hb fp16
    gemm_cp<2,1><<<dim3(8, M_/128), 256, GEMM_SMEM_SZ>>>(x1n16, w1, fc1b, nullptr, nullptr, nullptr, nullptr, hb16, HID_, C_);
    // 9) LCE conv3x3 -> y2 fp16
    conv3_kernel<<<dim3(W_/8, H_/8, B_), 64>>>(y1, c2w, c2b, y216);
    // 10) LCE conv1x1 24->192 + LeakyReLU -> y fp32
    gemm_cp<3,0><<<dim3(2, M_/128), 256, GEMM_SMEM_SZ>>>(y216, wc3, c3b, nullptr, nullptr, nullptr, y, nullptr, C_, RED_);
    // 11) global avg pool + SE gate
    zero_pool_kernel<<<1, 384>>>(pool);
    pool_kernel<<<M_/128, 192>>>(y, pool);
    se_kernel<<<1, 192>>>(pool, sfc1, sfc2, sbuf);
    // 12) fc2 + residual + SE-gated local context -> out
    gemm_cp<4,0><<<dim3(2, M_/128), 256, GEMM_SMEM_SZ>>>(hb16, w2, fc2b, x1, y, sbuf, out, nullptr, C_, HID_);
}

// round 14
// speedup vs baseline: 7.3167x; 1.0137x over previous
#include <cuda_runtime.h>
#include <cuda_fp16.h>
#include <math.h>
#include <stdint.h>

#define B_    2
#define H_    256
#define W_    256
#define C_    192
#define L_    (H_*W_)         // 65536
#define M_    (B_*L_)         // 131072
#define HID_  768
#define NH    6
#define HD    32
#define WS    8
#define SHIFT 4
#define NWIN  (B_*(H_/WS)*(W_/WS))  // 2048
#define RED_  24

// ---------------- scratch (device globals; no allocations) ----------------
__device__ float g_x1 [M_*C_];
__device__ float g_y1 [M_*RED_];
__device__ float g_y  [M_*C_];
__device__ float g_pool[B_*C_];
__device__ float g_s  [B_*C_];
// fp16 activation planes
__device__ __half g_qkv16[(size_t)M_*3*C_];
__device__ __half g_xn16 [M_*C_];
__device__ __half g_ao16 [M_*C_];
__device__ __half g_x1n16[M_*C_];
__device__ __half g_hb16 [(size_t)M_*HID_];
__device__ __half g_y216 [M_*RED_];
// fp16 weights (single plane)
__device__ __half g_wq [3*C_*C_];
__device__ __half g_wp [C_*C_];
__device__ __half g_w1 [HID_*C_];
__device__ __half g_w2 [C_*HID_];
__device__ __half g_wc1[RED_*C_];
__device__ __half g_wc3[C_*RED_];

// ======================= helpers ===========================================
__device__ __forceinline__ uint32_t smem_to_u32(const void* p) {
    uint32_t a;
    asm("{ .reg .u64 t; cvta.to.shared.u64 t, %1; cvt.u32.u64 %0, t; }" : "=r"(a) : "l"(p));
    return a;
}
__device__ __forceinline__ uint32_t pack_h2(float x, float y) {
    __half2 h = __floats2half2_rn(x, y);
    return *reinterpret_cast<uint32_t*>(&h);
}
#define LDSM4(r, addr) \
    asm volatile("ldmatrix.sync.aligned.m8n8.x4.shared.b16 {%0,%1,%2,%3}, [%4];" \
        : "=r"((r)[0]), "=r"((r)[1]), "=r"((r)[2]), "=r"((r)[3]) : "r"(addr))
#define LDSM4T(r, addr) \
    asm volatile("ldmatrix.sync.aligned.m8n8.x4.trans.shared.b16 {%0,%1,%2,%3}, [%4];" \
        : "=r"((r)[0]), "=r"((r)[1]), "=r"((r)[2]), "=r"((r)[3]) : "r"(addr))
#define MMA_F16(d, a, b0, b1) \
    asm volatile("mma.sync.aligned.m16n8k16.row.col.f32.f16.f16.f32 " \
        "{%0,%1,%2,%3},{%4,%5,%6,%7},{%8,%9},{%0,%1,%2,%3};" \
        : "+f"((d)[0]), "+f"((d)[1]), "+f"((d)[2]), "+f"((d)[3]) \
        : "r"((a)[0]), "r"((a)[1]), "r"((a)[2]), "r"((a)[3]), "r"(b0), "r"(b1))
#define CP_ASYNC(dst, src, sz) \
    asm volatile("cp.async.cg.shared.global [%0], [%1], 16, %2;" \
        :: "r"(dst), "l"(src), "r"(sz))
#define CP_ASYNC16(dst, src) \
    asm volatile("cp.async.cg.shared.global [%0], [%1], 16;" \
        :: "r"(dst), "l"(src))
#define CP_COMMIT() asm volatile("cp.async.commit_group;" ::: "memory")

// ======================= fp16 mma.sync GEMM (128x96 tile, 4-stage) =========
// out[M,N] = epi(A @ W^T + bias); A and W single fp16 planes [rows][K].
// CTA tile 128x96, BK=32. 8 warps = 4(M) x 2(N); warp tile 32x48.
// EPI: 0 none, 1 +res, 2 exact GELU, 3 LeakyReLU(0.2),
//      4 +res + gate (out = v + res + yy*s[b,col]). OUTP: 1 = write fp16 plane.
// CLEAN: 1 = K%32==0 && N%96==0 (no bounds checks; pointer-walk issue path).
#define STG_STRIDE 17920   // A 10240 | W 7680
#define W_OFF 10240
#define NSTG 4
#define GEMM_SMEM_SZ (NSTG*STG_STRIDE)   // 71680

template<int EPI, int OUTP, int CLEAN>
__device__ __forceinline__ void gemm_body(const __half* __restrict__ A16,
                                          const __half* __restrict__ Wt,
                                          const float* __restrict__ bias,
                                          const float* __restrict__ res,
                                          const float* __restrict__ yy,
                                          const float* __restrict__ sgate,
                                          float* __restrict__ out,
                                          __half* __restrict__ out16,
                                          int N, int K, char* smem) {
    const int tid  = threadIdx.x;
    const int lane = tid & 31;
    const int warp = tid >> 5;
    const int m0 = blockIdx.y * 128, n0 = blockIdx.x * 96;
    const int wm = (warp & 3) * 32, wn = (warp >> 2) * 48;
    const int nch = (K + 31) >> 5;
    const uint32_t sb = smem_to_u32(smem);

    // ---- clean-path issue state (pointer-walk, no per-chunk ALU) ----
    const __half* gA0 = nullptr; const __half* gA1 = nullptr;
    const __half* gW0 = nullptr; const __half* gW1 = nullptr;
    uint32_t dA0 = 0, dA1 = 0, dW0 = 0, dW1 = 0;
    if (CLEAN) {
        int row = tid >> 2, seg = tid & 3;
        gA0 = A16 + (size_t)(m0 + row) * K + seg * 8;
        gA1 = gA0 + (size_t)64 * K;
        gW0 = Wt + (size_t)(n0 + row) * K + seg * 8;
        gW1 = gW0 + (size_t)64 * K;
        dA0 = sb + row * 80 + seg * 16;
        dA1 = dA0 + 64 * 80;
        dW0 = dA0 + W_OFF;
        dW1 = dW0 + 64 * 80;
    }

#define ISSUE_C(stg) do { \
    uint32_t so_ = (uint32_t)(stg) * STG_STRIDE; \
    CP_ASYNC16(dA0 + so_, gA0); \
    CP_ASYNC16(dA1 + so_, gA1); \
    CP_ASYNC16(dW0 + so_, gW0); \
    if (tid < 128) CP_ASYNC16(dW1 + so_, gW1); \
    CP_COMMIT(); \
    gA0 += 32; gA1 += 32; gW0 += 32; gW1 += 32; } while (0)

#define ISSUE(stg, c) do { \
    char* base_ = smem + (stg) * STG_STRIDE; \
    int k0_ = (c) * 32; \
    _Pragma("unroll") \
    for (int i = 0; i < 2; i++) { \
        int t = tid + i * 256; \
        int row = t >> 2, seg = t & 3; \
        int ke = k0_ + seg * 8; \
        int srcsz = (K - ke) * 2; \
        srcsz = srcsz < 0 ? 0 : (srcsz > 16 ? 16 : srcsz); \
        const __half* g = A16 + (size_t)(m0 + row) * K + (srcsz ? ke : 0); \
        uint32_t d = smem_to_u32(base_ + row * 80 + seg * 16); \
        CP_ASYNC(d, g, srcsz); \
    } \
    _Pragma("unroll") \
    for (int i = 0; i < 2; i++) { \
        int t = tid + i * 256; \
        if (t < 384) { \
            int row = t >> 2, seg = t & 3; \
            int ke = k0_ + seg * 8; \
            int srcsz = (K - ke) * 2; \
            srcsz = srcsz < 0 ? 0 : (srcsz > 16 ? 16 : srcsz); \
            if (n0 + row >= N) srcsz = 0; \
            int grow = (n0 + row < N) ? (n0 + row) : 0; \
            const __half* g = Wt + (size_t)grow * K + (srcsz ? ke : 0); \
            uint32_t d = smem_to_u32(base_ + W_OFF + row * 80 + seg * 16); \
            CP_ASYNC(d, g, srcsz); \
        } \
    } \
    CP_COMMIT(); } while (0)

    float acc[2][6][4];
    #pragma unroll
    for (int i = 0; i < 2; i++)
        #pragma unroll
        for (int j = 0; j < 6; j++)
            #pragma unroll
            for (int q = 0; q < 4; q++) acc[i][j][q] = 0.f;

    if (CLEAN) {
        ISSUE_C(0);
        if (nch > 1) ISSUE_C(1);
        if (nch > 2) ISSUE_C(2);
    } else {
        ISSUE(0, 0);
        if (nch > 1) ISSUE(1, 1);
        if (nch > 2) ISSUE(2, 2);
    }

    int sc = 0;
    for (int c = 0; c < nch; c++) {
        int rem = nch - 1 - c;
        if (rem >= 2)      asm volatile("cp.async.wait_group 2;" ::: "memory");
        else if (rem == 1) asm volatile("cp.async.wait_group 1;" ::: "memory");
        else               asm volatile("cp.async.wait_group 0;" ::: "memory");
        __syncthreads();
        char* base = smem + sc * STG_STRIDE;
        #pragma unroll
        for (int ks = 0; ks < 2; ks++) {
            uint32_t af[2][4], wf[3][4];
            #pragma unroll
            for (int mt = 0; mt < 2; mt++) {
                int row = wm + mt * 16 + (lane & 15);
                int colb = ks * 32 + ((lane >> 4) & 1) * 16;
                LDSM4(af[mt], smem_to_u32(base + row * 80 + colb));
            }
            #pragma unroll
            for (int np = 0; np < 3; np++) {
                int n = wn + np * 16 + (lane & 7) + ((lane >> 4) & 1) * 8;
                int colb = ks * 32 + ((lane >> 3) & 1) * 16;
                LDSM4(wf[np], smem_to_u32(base + W_OFF + n * 80 + colb));
            }
            #pragma unroll
            for (int mt = 0; mt < 2; mt++)
                #pragma unroll
                for (int nt = 0; nt < 6; nt++) {
                    int np = nt >> 1, h = (nt & 1) * 2;
                    MMA_F16(acc[mt][nt], af[mt], wf[np][h], wf[np][h+1]);
                }
        }
        if (c + 3 < nch) {
            int si = sc + 3; if (si >= NSTG) si -= NSTG;
            if (CLEAN) ISSUE_C(si);
            else       ISSUE(si, c + 3);
        }
        sc = (sc + 1 == NSTG) ? 0 : sc + 1;
    }

    // ---- epilogue ----
    #pragma unroll
    for (int mt = 0; mt < 2; mt++) {
        int r0 = m0 + wm + mt * 16 + (lane >> 2);
        #pragma unroll
        for (int nt = 0; nt < 6; nt++) {
            int col = n0 + wn + nt * 8 + (lane & 3) * 2;
            if (col < N) {
                float b0v = bias[col], b1v = bias[col + 1];
                #pragma unroll
                for (int rr = 0; rr < 2; rr++) {
                    int r = r0 + rr * 8;
                    float v0 = acc[mt][nt][rr*2+0] + b0v;
                    float v1 = acc[mt][nt][rr*2+1] + b1v;
                    if (EPI == 1 || EPI == 4) {
                        float2 rv = *(const float2*)(res + (size_t)r * N + col);
                        v0 += rv.x; v1 += rv.y;
                    }
                    if (EPI == 2) {
                        v0 = 0.5f * v0 * (1.f + erff(v0 * 0.70710678118654752f));
                        v1 = 0.5f * v1 * (1.f + erff(v1 * 0.70710678118654752f));
                    }
                    if (EPI == 3) {
                        v0 = (v0 >= 0.f) ? v0 : 0.2f * v0;
                        v1 = (v1 >= 0.f) ? v1 : 0.2f * v1;
                    }
                    if (EPI == 4) {
                        const float* sb2 = sgate + (r >> 16) * C_;
                        float2 yv = *(const float2*)(yy + (size_t)r * N + col);
                        v0 += yv.x * sb2[col];
                        v1 += yv.y * sb2[col + 1];
                    }
                    if (OUTP) {
                        *(uint32_t*)(out16 + (size_t)r * N + col) = pack_h2(v0, v1);
                    } else {
                        *(float2*)(out + (size_t)r * N + col) = make_float2(v0, v1);
                    }
                }
            }
        }
    }
#undef ISSUE
#undef ISSUE_C
}

template<int EPI, int OUTP, int CLEAN>
__global__ __launch_bounds__(256, 2) void gemm_cp(const __half* __restrict__ A16,
                                                  const __half* __restrict__ Wt,
                                                  const float* __restrict__ bias,
                                                  const float* __restrict__ res,
                                                  const float* __restrict__ yy,
                                                  const float* __restrict__ sgate,
                                                  float* __restrict__ out,
                                                  __half* __restrict__ out16,
                                                  int N, int K) {
    extern __shared__ char smem[];
    gemm_body<EPI, OUTP, CLEAN>(A16, Wt, bias, res, yy, sgate, out, out16, N, K, smem);
}

// ---------------- merged weight convert (6 tensors, one launch) ------------
#define S0 (3*C_*C_)
#define S1 (C_*C_)
#define S2 (HID_*C_)
#define S3 (C_*HID_)
#define S4 (RED_*C_)
#define S5 (C_*RED_)
#define STOT (S0+S1+S2+S3+S4+S5)
__global__ __launch_bounds__(256) void convert_all_kernel(
        const float* __restrict__ w0, const float* __restrict__ w1,
        const float* __restrict__ w2, const float* __restrict__ w3,
        const float* __restrict__ w4, const float* __restrict__ w5,
        __half* h0, __half* h1, __half* h2, __half* h3, __half* h4, __half* h5) {
    int i = blockIdx.x * 256 + threadIdx.x;
    const float* s; __half* h; int off;
    if      (i < S0)                { s = w0; h = h0; off = i; }
    else if (i < S0+S1)             { s = w1; h = h1; off = i - S0; }
    else if (i < S0+S1+S2)          { s = w2; h = h2; off = i - S0-S1; }
    else if (i < S0+S1+S2+S3)       { s = w3; h = h3; off = i - S0-S1-S2; }
    else if (i < S0+S1+S2+S3+S4)    { s = w4; h = h4; off = i - S0-S1-S2-S3; }
    else if (i < STOT)              { s = w5; h = h5; off = i - S0-S1-S2-S3-S4; }
    else return;
    h[off] = __float2half_rn(s[off]);
}

// ---------------- LayerNorm -> single fp16 plane ---------------------------
__global__ __launch_bounds__(256) void ln16_kernel(const float* __restrict__ x,
                                                   const float* __restrict__ g,
                                                   const float* __restrict__ b,
                                                   __half* __restrict__ o16) {
    int token = blockIdx.x * 8 + (threadIdx.x >> 5);
    int lane  = threadIdx.x & 31;
    const float* p = x + (size_t)token * C_;
    float v[6];
    float s = 0.f;
    #pragma unroll
    for (int j = 0; j < 6; j++) { v[j] = p[lane + 32*j]; s += v[j]; }
    #pragma unroll
    for (int o = 16; o > 0; o >>= 1) s += __shfl_xor_sync(0xffffffffu, s, o);
    float mean = s * (1.f / C_);
    float q = 0.f;
    #pragma unroll
    for (int j = 0; j < 6; j++) { float d = v[j] - mean; q += d * d; }
    #pragma unroll
    for (int o = 16; o > 0; o >>= 1) q += __shfl_xor_sync(0xffffffffu, q, o);
    float rstd = rsqrtf(q * (1.f / C_) + 1e-5f);
    #pragma unroll
    for (int j = 0; j < 6; j++) {
        int c = lane + 32*j;
        o16[(size_t)token * C_ + c] = __float2half_rn((v[j] - mean) * rstd * g[c] + b[c]);
    }
}

// ============ Windowed attention: tensor-core, double-buffered head pairs ==
#define ATTN_SMEM (2*6*5120)
__global__ __launch_bounds__(256, 2) void attn_mma_kernel(const __half* __restrict__ qkv16,
                                                          const float* __restrict__ rpb,
                                                          __half* __restrict__ ao16) {
    extern __shared__ char dsmem[];
    __shared__ float  srpb[225 * NH];
    __shared__ int    gidx[64];
    __shared__ int    rid [64];

    const int tid  = threadIdx.x;
    const int lane = tid & 31;
    const int warp = tid >> 5;
    const int wid  = blockIdx.x;
    const int bb   = wid >> 10;
    const int wib  = wid & 1023;
    const int wh   = wib >> 5, ww = wib & 31;

    if (tid < 64) {
        int ih = tid >> 3, iw = tid & 7;
        int h = wh * 8 + ih, w = ww * 8 + iw;
        gidx[tid] = bb * L_ + ((h + SHIFT) & (H_ - 1)) * W_ + ((w + SHIFT) & (W_ - 1));
        int rh = (h < H_ - WS) ? 0 : ((h < H_ - SHIFT) ? 1 : 2);
        int rw = (w < W_ - WS) ? 0 : ((w < W_ - SHIFT) ? 1 : 2);
        rid[tid] = rh * 3 + rw;
    }
    for (int i = tid; i < 225 * NH; i += 256) srpb[i] = rpb[i];
    __syncthreads();

    const uint32_t pb = smem_to_u32(dsmem);
    const int hp   = warp >> 2;
    const int r0   = (warp & 3) * 16;
    const int i_lo = r0 + (lane >> 2);
    const int i_hi = i_lo + 8;
    const int ihlo = i_lo >> 3, iwlo = i_lo & 7;
    const int ihhi = i_hi >> 3, iwhi = i_hi & 7;
    const float SCALE = 0.17677669529663687f;

#define ATTN_LOAD(buf, h0v) do { \
    _Pragma("unroll") \
    for (int i = 0; i < 6; i++) { \
        int t   = tid + i * 256; \
        int rowid = t >> 2, seg = t & 3; \
        int p   = rowid >> 6, tok = rowid & 63; \
        int mat = p % 3, php = p / 3; \
        const __half* g = qkv16 + (size_t)gidx[tok] * (3*C_) + mat * C_ + ((h0v) + php) * HD + seg * 8; \
        uint32_t d = pb + (buf) * 30720 + p * 5120 + tok * 80 + seg * 16; \
        CP_ASYNC16(d, g); \
    } \
    CP_COMMIT(); } while (0)

    ATTN_LOAD(0, 0);

    for (int it = 0; it < 3; ++it) {
        const int buf = it & 1;
        const int h0 = it * 2;
        asm volatile("cp.async.wait_group 0;" ::: "memory");
        __syncthreads();
        if (it + 1 < 3) ATTN_LOAD(buf ^ 1, h0 + 2);

        const uint32_t qbase = pb + buf * 30720 + hp * 15360;
        const uint32_t kbase = qbase + 5120;
        const uint32_t vbase = qbase + 10240;
        const int head = h0 + hp;

        float S[8][4];
        #pragma unroll
        for (int t = 0; t < 8; t++)
            #pragma unroll
            for (int q = 0; q < 4; q++) S[t][q] = 0.f;
        #pragma unroll
        for (int ks = 0; ks < 2; ks++) {
            uint32_t qf[4];
            LDSM4(qf, qbase + (r0 + (lane & 15)) * 80 + ks * 32 + ((lane >> 4) & 1) * 16);
            #pragma unroll
            for (int np = 0; np < 4; np++) {
                uint32_t kf[4];
                LDSM4(kf, kbase + ((lane & 7) + ((lane >> 4) & 1) * 8 + np * 16) * 80
                          + ks * 32 + ((lane >> 3) & 1) * 16);
                MMA_F16(S[np*2+0], qf, kf[0], kf[1]);
                MMA_F16(S[np*2+1], qf, kf[2], kf[3]);
            }
        }
        const int ridlo = rid[i_lo], ridhi = rid[i_hi];
        float mlo = -1e30f, mhi = -1e30f;
        #pragma unroll
        for (int t = 0; t < 8; t++) {
            int jc = (t >> 1) * 16 + (t & 1) * 8 + (lane & 3) * 2;
            #pragma unroll
            for (int e = 0; e < 2; e++) {
                int j = jc + e;
                int jh = j >> 3, jw = j & 7;
                float blo = srpb[((ihlo - jh + 7) * 15 + (iwlo - jw + 7)) * NH + head];
                float bhi = srpb[((ihhi - jh + 7) * 15 + (iwhi - jw + 7)) * NH + head];
                int rj = rid[j];
                float v0 = S[t][e]     * SCALE + blo + ((ridlo != rj) ? -100.f : 0.f);
                float v1 = S[t][e + 2] * SCALE + bhi + ((ridhi != rj) ? -100.f : 0.f);
                S[t][e] = v0; S[t][e + 2] = v1;
                mlo = fmaxf(mlo, v0); mhi = fmaxf(mhi, v1);
            }
        }
        mlo = fmaxf(mlo, __shfl_xor_sync(0xffffffffu, mlo, 1));
        mlo = fmaxf(mlo, __shfl_xor_sync(0xffffffffu, mlo, 2));
        mhi = fmaxf(mhi, __shfl_xor_sync(0xffffffffu, mhi, 1));
        mhi = fmaxf(mhi, __shfl_xor_sync(0xffffffffu, mhi, 2));
        float slo = 0.f, shi = 0.f;
        #pragma unroll
        for (int t = 0; t < 8; t++) {
            #pragma unroll
            for (int e = 0; e < 2; e++) {
                float v0 = __expf(S[t][e] - mlo);
                float v1 = __expf(S[t][e + 2] - mhi);
                S[t][e] = v0; S[t][e + 2] = v1;
                slo += v0; shi += v1;
            }
        }
        slo += __shfl_xor_sync(0xffffffffu, slo, 1);
        slo += __shfl_xor_sync(0xffffffffu, slo, 2);
        shi += __shfl_xor_sync(0xffffffffu, shi, 1);
        shi += __shfl_xor_sync(0xffffffffu, shi, 2);
        float ilo = 1.f / slo, ihi2 = 1.f / shi;
        uint32_t pa[4][4];
        #pragma unroll
        for (int kt = 0; kt < 4; kt++) {
            pa[kt][0] = pack_h2(S[kt*2][0] * ilo,  S[kt*2][1] * ilo);
            pa[kt][1] = pack_h2(S[kt*2][2] * ihi2, S[kt*2][3] * ihi2);
            pa[kt][2] = pack_h2(S[kt*2+1][0] * ilo,  S[kt*2+1][1] * ilo);
            pa[kt][3] = pack_h2(S[kt*2+1][2] * ihi2, S[kt*2+1][3] * ihi2);
        }
        float O[4][4];
        #pragma unroll
        for (int t = 0; t < 4; t++)
            #pragma unroll
            for (int q = 0; q < 4; q++) O[t][q] = 0.f;
        #pragma unroll
        for (int kt = 0; kt < 4; kt++) {
            #pragma unroll
            for (int nc = 0; nc < 2; nc++) {
                uint32_t vf[4];
                LDSM4T(vf, vbase + (kt * 16 + (lane & 7) + ((lane >> 3) & 1) * 8) * 80
                           + nc * 32 + ((lane >> 4) & 1) * 16);
                MMA_F16(O[nc*2+0], pa[kt], vf[0], vf[1]);
                MMA_F16(O[nc*2+1], pa[kt], vf[2], vf[3]);
            }
        }
        #pragma unroll
        for (int t = 0; t < 4; t++) {
            int col = t * 8 + (lane & 3) * 2;
            *(uint32_t*)(ao16 + (size_t)gidx[i_lo] * C_ + head * HD + col) = pack_h2(O[t][0], O[t][1]);
            *(uint32_t*)(ao16 + (size_t)gidx[i_hi] * C_ + head * HD + col) = pack_h2(O[t][2], O[t][3]);
        }
    }
#undef ATTN_LOAD
}

// ---------------- 3x3 conv on r=24 channels, NHWC, pad 1 -------------------
__global__ __launch_bounds__(64) void conv3_kernel(const float* __restrict__ yin,
                                                   const float* __restrict__ w,
                                                   const float* __restrict__ bias,
                                                   __half* __restrict__ y16) {
    __shared__ float patch[100][RED_];
    __shared__ float wts[RED_ * RED_ * 9];
    int tid = threadIdx.x;
    int b = blockIdx.z;
    int th0 = blockIdx.y * 8, tw0 = blockIdx.x * 8;

    for (int d = tid; d < RED_ * RED_ * 9; d += 64) {
        int oc = d % RED_;
        int t2 = d / RED_;
        int kk = t2 % 9;
        int ic = t2 / 9;
        wts[d] = w[(oc * RED_ + ic) * 9 + kk];
    }
    for (int d = tid; d < 100 * RED_; d += 64) {
        int ic = d % RED_;
        int pos = d / RED_;
        int ph = pos / 10, pw = pos % 10;
        int hh = th0 + ph - 1, ww = tw0 + pw - 1;
        float v = 0.f;
        if (hh >= 0 && hh < H_ && ww >= 0 && ww < W_)
            v = yin[((size_t)b * L_ + hh * W_ + ww) * RED_ + ic];
        patch[pos][ic] = v;
    }
    __syncthreads();

    int py = tid >> 3, px = tid & 7;
    float acc[RED_];
    #pragma unroll
    for (int oc = 0; oc < RED_; oc++) acc[oc] = __ldg(bias + oc);
    for (int ic = 0; ic < RED_; ic++) {
        #pragma unroll
        for (int kk = 0; kk < 9; kk++) {
            int kh = kk / 3, kw = kk % 3;
            float pv = patch[(py + kh) * 10 + (px + kw)][ic];
            const float4* wp = (const float4*)&wts[(ic * 9 + kk) * RED_];
            #pragma unroll
            for (int o4 = 0; o4 < 6; o4++) {
                float4 wv = wp[o4];
                acc[o4*4+0] += wv.x * pv; acc[o4*4+1] += wv.y * pv;
                acc[o4*4+2] += wv.z * pv; acc[o4*4+3] += wv.w * pv;
            }
        }
    }
    size_t off = ((size_t)b * L_ + (th0 + py) * W_ + (tw0 + px)) * RED_;
    #pragma unroll
    for (int oc = 0; oc < RED_; oc += 2)
        *(uint32_t*)(y16 + off + oc) = pack_h2(acc[oc], acc[oc + 1]);
}

// ---------------- pool / SE ------------------------------------------------
__global__ void zero_pool_kernel(float* pool) {
    if (threadIdx.x < B_ * C_) pool[threadIdx.x] = 0.f;
}

__global__ __launch_bounds__(192) void pool_kernel(const float* __restrict__ y,
                                                   float* __restrict__ pool) {
    int base = blockIdx.x * 128;
    int b = base >> 16;
    int c = threadIdx.x;
    float acc = 0.f;
    for (int i = 0; i < 128; i++)
        acc += y[(size_t)(base + i) * C_ + c];
    atomicAdd(&pool[b * C_ + c], acc);
}

__global__ __launch_bounds__(192) void se_kernel(const float* __restrict__ pool,
                                                 const float* __restrict__ fc1,
                                                 const float* __restrict__ fc2,
                                                 float* __restrict__ sbuf) {
    __shared__ float t[RED_];
    int tid = threadIdx.x;
    const float inv = 1.f / (float)L_;
    for (int b = 0; b < B_; b++) {
        if (tid < RED_) {
            float s = 0.f;
            for (int c = 0; c < C_; c++)
                s += pool[b * C_ + c] * inv * fc1[tid * C_ + c];
            t[tid] = fmaxf(s, 0.f);
        }
        __syncthreads();
        float s = 0.f;
        #pragma unroll
        for (int j = 0; j < RED_; j++) s += t[j] * fc2[tid * RED_ + j];
        sbuf[b * C_ + tid] = 1.f / (1.f + expf(-s));
        __syncthreads();
    }
}

// ---------------- launch ---------------------------------------------------
extern "C" void kernel_launch(void* const* d_in, const int* in_sizes, int n_in,
                              void* d_out, int out_size) {
    const float* x      = (const float*)d_in[0];
    const float* n1g    = (const float*)d_in[1];
    const float* n1b    = (const float*)d_in[2];
    const float* qkvw   = (const float*)d_in[3];
    const float* qkvb   = (const float*)d_in[4];
    const float* rpb    = (const float*)d_in[5];
    const float* projw  = (const float*)d_in[6];
    const float* projb  = (const float*)d_in[7];
    const float* n2g    = (const float*)d_in[8];
    const float* n2b    = (const float*)d_in[9];
    const float* fc1w   = (const float*)d_in[10];
    const float* fc1b   = (const float*)d_in[11];
    const float* fc2w   = (const float*)d_in[12];
    const float* fc2b   = (const float*)d_in[13];
    const float* c1w    = (const float*)d_in[14];
    const float* c1b    = (const float*)d_in[15];
    const float* c2w    = (const float*)d_in[16];
    const float* c2b    = (const float*)d_in[17];
    const float* c3w    = (const float*)d_in[18];
    const float* c3b    = (const float*)d_in[19];
    const float* sfc1   = (const float*)d_in[20];
    const float* sfc2   = (const float*)d_in[21];
    float* out = (float*)d_out;

    float *x1, *y1, *y, *pool, *sbuf;
    cudaGetSymbolAddress((void**)&x1,   g_x1);
    cudaGetSymbolAddress((void**)&y1,   g_y1);
    cudaGetSymbolAddress((void**)&y,    g_y);
    cudaGetSymbolAddress((void**)&pool, g_pool);
    cudaGetSymbolAddress((void**)&sbuf, g_s);
    __half *qkv16, *xn16, *ao16, *x1n16, *hb16, *y216;
    __half *wq, *wp, *w1, *w2, *wc1, *wc3;
    cudaGetSymbolAddress((void**)&qkv16, g_qkv16);
    cudaGetSymbolAddress((void**)&xn16,  g_xn16);
    cudaGetSymbolAddress((void**)&ao16,  g_ao16);
    cudaGetSymbolAddress((void**)&x1n16, g_x1n16);
    cudaGetSymbolAddress((void**)&hb16,  g_hb16);
    cudaGetSymbolAddress((void**)&y216,  g_y216);
    cudaGetSymbolAddress((void**)&wq,  g_wq);
    cudaGetSymbolAddress((void**)&wp,  g_wp);
    cudaGetSymbolAddress((void**)&w1,  g_w1);
    cudaGetSymbolAddress((void**)&w2,  g_w2);
    cudaGetSymbolAddress((void**)&wc1, g_wc1);
    cudaGetSymbolAddress((void**)&wc3, g_wc3);

    cudaFuncSetAttribute(gemm_cp<0,0,0>, cudaFuncAttributeMaxDynamicSharedMemorySize, GEMM_SMEM_SZ);
    cudaFuncSetAttribute(gemm_cp<0,1,1>, cudaFuncAttributeMaxDynamicSharedMemorySize, GEMM_SMEM_SZ);
    cudaFuncSetAttribute(gemm_cp<1,0,1>, cudaFuncAttributeMaxDynamicSharedMemorySize, GEMM_SMEM_SZ);
    cudaFuncSetAttribute(gemm_cp<2,1,1>, cudaFuncAttributeMaxDynamicSharedMemorySize, GEMM_SMEM_SZ);
    cudaFuncSetAttribute(gemm_cp<3,0,0>, cudaFuncAttributeMaxDynamicSharedMemorySize, GEMM_SMEM_SZ);
    cudaFuncSetAttribute(gemm_cp<4,0,1>, cudaFuncAttributeMaxDynamicSharedMemorySize, GEMM_SMEM_SZ);
    cudaFuncSetAttribute(attn_mma_kernel, cudaFuncAttributeMaxDynamicSharedMemorySize, ATTN_SMEM);

    // 1) weight convert (one launch)
    convert_all_kernel<<<(STOT+255)/256, 256>>>(qkvw, projw, fc1w, fc2w, c1w, c3w,
        wq, wp, w1, w2, wc1, wc3);
    // 2) LN1 -> fp16 plane
    ln16_kernel<<<M_/8, 256>>>(x, n1g, n1b, xn16);
    // 3) QKV GEMM -> fp16 (clean: N=576, K=192)
    gemm_cp<0,1,1><<<dim3(6, M_/128), 256, GEMM_SMEM_SZ>>>(xn16, wq, qkvb, nullptr, nullptr, nullptr, nullptr, qkv16, 3*C_, C_);
    // 4) LCE conv1x1 C->24 -> y1 fp32 (checked: N=24)
    gemm_cp<0,0,0><<<dim3(1, M_/128), 256, GEMM_SMEM_SZ>>>(xn16, wc1, c1b, nullptr, nullptr, nullptr, y1, nullptr, RED_, C_);
    // 5) attention (tensor-core, double-buffered) -> ao fp16
    attn_mma_kernel<<<NWIN, 256, ATTN_SMEM>>>(qkv16, rpb, ao16);
    // 6) proj + residual -> x1 fp32 (clean: N=192, K=192)
    gemm_cp<1,0,1><<<dim3(2, M_/128), 256, GEMM_SMEM_SZ>>>(ao16, wp, projb, x, nullptr, nullptr, x1, nullptr, C_, C_);
    // 7) LN2 -> fp16 plane
    ln16_kernel<<<M_/8, 256>>>(x1, n2g, n2b, x1n16);
    // 8) fc1 + GELU -> hb fp16 (clean: N=768, K=192)
    gemm_cp<2,1,1><<<dim3(8, M_/128), 256, GEMM_SMEM_SZ>>>(x1n16, w1, fc1b, nullptr, nullptr, nullptr, nullptr, hb16, HID_, C_);
    // 9) LCE conv3x3 -> y2 fp16
    conv3_kernel<<<dim3(W_/8, H_/8, B_), 64>>>(y1, c2w, c2b, y216);
    // 10) LCE conv1x1 24->192 + LeakyReLU -> y fp32 (checked: K=24)
    gemm_cp<3,0,0><<<dim3(2, M_/128), 256, GEMM_SMEM_SZ>>>(y216, wc3, c3b, nullptr, nullptr, nullptr, y, nullptr, C_, RED_);
    // 11) global avg pool + SE gate
    zero_pool_kernel<<<1, 384>>>(pool);
    pool_kernel<<<M_/128, 192>>>(y, pool);
    se_kernel<<<1, 192>>>(pool, sfc1, sfc2, sbuf);
    // 12) fc2 + residual + SE-gated local context -> out (clean: N=192, K=768)
    gemm_cp<4,0,1><<<dim3(2, M_/128), 256, GEMM_SMEM_SZ>>>(hb16, w2, fc2b, x1, y, sbuf, out, nullptr, C_, HID_);
}

// round 15
// speedup vs baseline: 7.4021x; 1.0117x over previous
#include <cuda_runtime.h>
#include <cuda_fp16.h>
#include <math.h>
#include <stdint.h>

#define B_    2
#define H_    256
#define W_    256
#define C_    192
#define L_    (H_*W_)         // 65536
#define M_    (B_*L_)         // 131072
#define HID_  768
#define NH    6
#define HD    32
#define WS    8
#define SHIFT 4
#define NWIN  (B_*(H_/WS)*(W_/WS))  // 2048
#define RED_  24

// ---------------- scratch (device globals; no allocations) ----------------
__device__ float g_y1 [M_*RED_];
__device__ float g_pool[B_*C_];
__device__ float g_s  [B_*C_];
// fp16 activation planes
__device__ __half g_qkv16[(size_t)M_*3*C_];
__device__ __half g_xn16 [M_*C_];
__device__ __half g_ao16 [M_*C_];
__device__ __half g_x116 [M_*C_];
__device__ __half g_x1n16[M_*C_];
__device__ __half g_hb16 [(size_t)M_*HID_];
__device__ __half g_y216 [M_*RED_];
__device__ __half g_y16  [M_*C_];
// fp16 weights (single plane)
__device__ __half g_wq [3*C_*C_];
__device__ __half g_wp [C_*C_];
__device__ __half g_w1 [HID_*C_];
__device__ __half g_w2 [C_*HID_];
__device__ __half g_wc1[RED_*C_];
__device__ __half g_wc3[C_*RED_];

// ======================= helpers ===========================================
__device__ __forceinline__ uint32_t smem_to_u32(const void* p) {
    uint32_t a;
    asm("{ .reg .u64 t; cvta.to.shared.u64 t, %1; cvt.u32.u64 %0, t; }" : "=r"(a) : "l"(p));
    return a;
}
__device__ __forceinline__ uint32_t pack_h2(float x, float y) {
    __half2 h = __floats2half2_rn(x, y);
    return *reinterpret_cast<uint32_t*>(&h);
}
__device__ __forceinline__ float2 unpack_h2(uint32_t u) {
    __half2 h = *reinterpret_cast<__half2*>(&u);
    return __half22float2(h);
}
#define LDSM4(r, addr) \
    asm volatile("ldmatrix.sync.aligned.m8n8.x4.shared.b16 {%0,%1,%2,%3}, [%4];" \
        : "=r"((r)[0]), "=r"((r)[1]), "=r"((r)[2]), "=r"((r)[3]) : "r"(addr))
#define LDSM4T(r, addr) \
    asm volatile("ldmatrix.sync.aligned.m8n8.x4.trans.shared.b16 {%0,%1,%2,%3}, [%4];" \
        : "=r"((r)[0]), "=r"((r)[1]), "=r"((r)[2]), "=r"((r)[3]) : "r"(addr))
#define MMA_F16(d, a, b0, b1) \
    asm volatile("mma.sync.aligned.m16n8k16.row.col.f32.f16.f16.f32 " \
        "{%0,%1,%2,%3},{%4,%5,%6,%7},{%8,%9},{%0,%1,%2,%3};" \
        : "+f"((d)[0]), "+f"((d)[1]), "+f"((d)[2]), "+f"((d)[3]) \
        : "r"((a)[0]), "r"((a)[1]), "r"((a)[2]), "r"((a)[3]), "r"(b0), "r"(b1))
#define CP_ASYNC(dst, src, sz) \
    asm volatile("cp.async.cg.shared.global [%0], [%1], 16, %2;" \
        :: "r"(dst), "l"(src), "r"(sz))
#define CP_ASYNC16(dst, src) \
    asm volatile("cp.async.cg.shared.global [%0], [%1], 16;" \
        :: "r"(dst), "l"(src))
#define CP_COMMIT() asm volatile("cp.async.commit_group;" ::: "memory")

// ======================= fp16 mma.sync GEMM (128x96 tile, 4-stage) =========
// out[M,N] = epi(A @ W^T + bias); A and W single fp16 planes [rows][K].
// EPI: 0 none, 1 +res32, 2 exact GELU, 3 LeakyReLU(0.2),
//      4 +res16 + gate (out = v + res16 + yy16*s[b,col]). OUTP: 1 = fp16 out.
// CLEAN: 1 = K%32==0 && N%96==0.
#define STG_STRIDE 17920   // A 10240 | W 7680
#define W_OFF 10240
#define NSTG 4
#define GEMM_SMEM_SZ (NSTG*STG_STRIDE)   // 71680

template<int EPI, int OUTP, int CLEAN>
__device__ __forceinline__ void gemm_body(const __half* __restrict__ A16,
                                          const __half* __restrict__ Wt,
                                          const float* __restrict__ bias,
                                          const float* __restrict__ res32,
                                          const __half* __restrict__ res16,
                                          const __half* __restrict__ yy16,
                                          const float* __restrict__ sgate,
                                          float* __restrict__ out,
                                          __half* __restrict__ out16,
                                          int N, int K, char* smem) {
    const int tid  = threadIdx.x;
    const int lane = tid & 31;
    const int warp = tid >> 5;
    const int m0 = blockIdx.y * 128, n0 = blockIdx.x * 96;
    const int wm = (warp & 3) * 32, wn = (warp >> 2) * 48;
    const int nch = (K + 31) >> 5;
    const uint32_t sb = smem_to_u32(smem);

    const __half* gA0 = nullptr; const __half* gA1 = nullptr;
    const __half* gW0 = nullptr; const __half* gW1 = nullptr;
    uint32_t dA0 = 0, dA1 = 0, dW0 = 0, dW1 = 0;
    if (CLEAN) {
        int row = tid >> 2, seg = tid & 3;
        gA0 = A16 + (size_t)(m0 + row) * K + seg * 8;
        gA1 = gA0 + (size_t)64 * K;
        gW0 = Wt + (size_t)(n0 + row) * K + seg * 8;
        gW1 = gW0 + (size_t)64 * K;
        dA0 = sb + row * 80 + seg * 16;
        dA1 = dA0 + 64 * 80;
        dW0 = dA0 + W_OFF;
        dW1 = dW0 + 64 * 80;
    }

#define ISSUE_C(stg) do { \
    uint32_t so_ = (uint32_t)(stg) * STG_STRIDE; \
    CP_ASYNC16(dA0 + so_, gA0); \
    CP_ASYNC16(dA1 + so_, gA1); \
    CP_ASYNC16(dW0 + so_, gW0); \
    if (tid < 128) CP_ASYNC16(dW1 + so_, gW1); \
    CP_COMMIT(); \
    gA0 += 32; gA1 += 32; gW0 += 32; gW1 += 32; } while (0)

#define ISSUE(stg, c) do { \
    char* base_ = smem + (stg) * STG_STRIDE; \
    int k0_ = (c) * 32; \
    _Pragma("unroll") \
    for (int i = 0; i < 2; i++) { \
        int t = tid + i * 256; \
        int row = t >> 2, seg = t & 3; \
        int ke = k0_ + seg * 8; \
        int srcsz = (K - ke) * 2; \
        srcsz = srcsz < 0 ? 0 : (srcsz > 16 ? 16 : srcsz); \
        const __half* g = A16 + (size_t)(m0 + row) * K + (srcsz ? ke : 0); \
        uint32_t d = smem_to_u32(base_ + row * 80 + seg * 16); \
        CP_ASYNC(d, g, srcsz); \
    } \
    _Pragma("unroll") \
    for (int i = 0; i < 2; i++) { \
        int t = tid + i * 256; \
        if (t < 384) { \
            int row = t >> 2, seg = t & 3; \
            int ke = k0_ + seg * 8; \
            int srcsz = (K - ke) * 2; \
            srcsz = srcsz < 0 ? 0 : (srcsz > 16 ? 16 : srcsz); \
            if (n0 + row >= N) srcsz = 0; \
            int grow = (n0 + row < N) ? (n0 + row) : 0; \
            const __half* g = Wt + (size_t)grow * K + (srcsz ? ke : 0); \
            uint32_t d = smem_to_u32(base_ + W_OFF + row * 80 + seg * 16); \
            CP_ASYNC(d, g, srcsz); \
        } \
    } \
    CP_COMMIT(); } while (0)

    float acc[2][6][4];
    #pragma unroll
    for (int i = 0; i < 2; i++)
        #pragma unroll
        for (int j = 0; j < 6; j++)
            #pragma unroll
            for (int q = 0; q < 4; q++) acc[i][j][q] = 0.f;

    if (CLEAN) {
        ISSUE_C(0);
        if (nch > 1) ISSUE_C(1);
        if (nch > 2) ISSUE_C(2);
    } else {
        ISSUE(0, 0);
        if (nch > 1) ISSUE(1, 1);
        if (nch > 2) ISSUE(2, 2);
    }

    int sc = 0;
    for (int c = 0; c < nch; c++) {
        int rem = nch - 1 - c;
        if (rem >= 2)      asm volatile("cp.async.wait_group 2;" ::: "memory");
        else if (rem == 1) asm volatile("cp.async.wait_group 1;" ::: "memory");
        else               asm volatile("cp.async.wait_group 0;" ::: "memory");
        __syncthreads();
        char* base = smem + sc * STG_STRIDE;
        #pragma unroll
        for (int ks = 0; ks < 2; ks++) {
            uint32_t af[2][4], wf[3][4];
            #pragma unroll
            for (int mt = 0; mt < 2; mt++) {
                int row = wm + mt * 16 + (lane & 15);
                int colb = ks * 32 + ((lane >> 4) & 1) * 16;
                LDSM4(af[mt], smem_to_u32(base + row * 80 + colb));
            }
            #pragma unroll
            for (int np = 0; np < 3; np++) {
                int n = wn + np * 16 + (lane & 7) + ((lane >> 4) & 1) * 8;
                int colb = ks * 32 + ((lane >> 3) & 1) * 16;
                LDSM4(wf[np], smem_to_u32(base + W_OFF + n * 80 + colb));
            }
            #pragma unroll
            for (int mt = 0; mt < 2; mt++)
                #pragma unroll
                for (int nt = 0; nt < 6; nt++) {
                    int np = nt >> 1, h = (nt & 1) * 2;
                    MMA_F16(acc[mt][nt], af[mt], wf[np][h], wf[np][h+1]);
                }
        }
        if (c + 3 < nch) {
            int si = sc + 3; if (si >= NSTG) si -= NSTG;
            if (CLEAN) ISSUE_C(si);
            else       ISSUE(si, c + 3);
        }
        sc = (sc + 1 == NSTG) ? 0 : sc + 1;
    }

    // ---- epilogue ----
    #pragma unroll
    for (int mt = 0; mt < 2; mt++) {
        int r0 = m0 + wm + mt * 16 + (lane >> 2);
        #pragma unroll
        for (int nt = 0; nt < 6; nt++) {
            int col = n0 + wn + nt * 8 + (lane & 3) * 2;
            if (col < N) {
                float b0v = bias[col], b1v = bias[col + 1];
                #pragma unroll
                for (int rr = 0; rr < 2; rr++) {
                    int r = r0 + rr * 8;
                    float v0 = acc[mt][nt][rr*2+0] + b0v;
                    float v1 = acc[mt][nt][rr*2+1] + b1v;
                    if (EPI == 1) {
                        float2 rv = *(const float2*)(res32 + (size_t)r * N + col);
                        v0 += rv.x; v1 += rv.y;
                    }
                    if (EPI == 2) {
                        v0 = 0.5f * v0 * (1.f + erff(v0 * 0.70710678118654752f));
                        v1 = 0.5f * v1 * (1.f + erff(v1 * 0.70710678118654752f));
                    }
                    if (EPI == 3) {
                        v0 = (v0 >= 0.f) ? v0 : 0.2f * v0;
                        v1 = (v1 >= 0.f) ? v1 : 0.2f * v1;
                    }
                    if (EPI == 4) {
                        float2 rv = unpack_h2(*(const uint32_t*)(res16 + (size_t)r * N + col));
                        float2 yv = unpack_h2(*(const uint32_t*)(yy16 + (size_t)r * N + col));
                        const float* sb2 = sgate + (r >> 16) * C_;
                        v0 += rv.x + yv.x * sb2[col];
                        v1 += rv.y + yv.y * sb2[col + 1];
                    }
                    if (OUTP) {
                        *(uint32_t*)(out16 + (size_t)r * N + col) = pack_h2(v0, v1);
                    } else {
                        *(float2*)(out + (size_t)r * N + col) = make_float2(v0, v1);
                    }
                }
            }
        }
    }
#undef ISSUE
#undef ISSUE_C
}

template<int EPI, int OUTP, int CLEAN>
__global__ __launch_bounds__(256, 2) void gemm_cp(const __half* __restrict__ A16,
                                                  const __half* __restrict__ Wt,
                                                  const float* __restrict__ bias,
                                                  const float* __restrict__ res32,
                                                  const __half* __restrict__ res16,
                                                  const __half* __restrict__ yy16,
                                                  const float* __restrict__ sgate,
                                                  float* __restrict__ out,
                                                  __half* __restrict__ out16,
                                                  int N, int K) {
    extern __shared__ char smem[];
    gemm_body<EPI, OUTP, CLEAN>(A16, Wt, bias, res32, res16, yy16, sgate, out, out16, N, K, smem);
}

// ---------------- merged weight convert + pool zero ------------------------
#define S0 (3*C_*C_)
#define S1 (C_*C_)
#define S2 (HID_*C_)
#define S3 (C_*HID_)
#define S4 (RED_*C_)
#define S5 (C_*RED_)
#define STOT (S0+S1+S2+S3+S4+S5)
__global__ __launch_bounds__(256) void convert_all_kernel(
        const float* __restrict__ w0, const float* __restrict__ w1,
        const float* __restrict__ w2, const float* __restrict__ w3,
        const float* __restrict__ w4, const float* __restrict__ w5,
        __half* h0, __half* h1, __half* h2, __half* h3, __half* h4, __half* h5,
        float* pool) {
    int i = blockIdx.x * 256 + threadIdx.x;
    if (i < B_ * C_) pool[i] = 0.f;
    const float* s; __half* h; int off;
    if      (i < S0)                { s = w0; h = h0; off = i; }
    else if (i < S0+S1)             { s = w1; h = h1; off = i - S0; }
    else if (i < S0+S1+S2)          { s = w2; h = h2; off = i - S0-S1; }
    else if (i < S0+S1+S2+S3)       { s = w3; h = h3; off = i - S0-S1-S2; }
    else if (i < S0+S1+S2+S3+S4)    { s = w4; h = h4; off = i - S0-S1-S2-S3; }
    else if (i < STOT)              { s = w5; h = h5; off = i - S0-S1-S2-S3-S4; }
    else return;
    h[off] = __float2half_rn(s[off]);
}

// ---------------- LayerNorm fp32-in -> fp16 plane --------------------------
__global__ __launch_bounds__(256) void ln16_kernel(const float* __restrict__ x,
                                                   const float* __restrict__ g,
                                                   const float* __restrict__ b,
                                                   __half* __restrict__ o16) {
    int token = blockIdx.x * 8 + (threadIdx.x >> 5);
    int lane  = threadIdx.x & 31;
    const float* p = x + (size_t)token * C_;
    float v[6];
    float s = 0.f;
    #pragma unroll
    for (int j = 0; j < 6; j++) { v[j] = p[lane + 32*j]; s += v[j]; }
    #pragma unroll
    for (int o = 16; o > 0; o >>= 1) s += __shfl_xor_sync(0xffffffffu, s, o);
    float mean = s * (1.f / C_);
    float q = 0.f;
    #pragma unroll
    for (int j = 0; j < 6; j++) { float d = v[j] - mean; q += d * d; }
    #pragma unroll
    for (int o = 16; o > 0; o >>= 1) q += __shfl_xor_sync(0xffffffffu, q, o);
    float rstd = rsqrtf(q * (1.f / C_) + 1e-5f);
    #pragma unroll
    for (int j = 0; j < 6; j++) {
        int c = lane + 32*j;
        o16[(size_t)token * C_ + c] = __float2half_rn((v[j] - mean) * rstd * g[c] + b[c]);
    }
}

// ---------------- LayerNorm fp16-in -> fp16 plane --------------------------
__global__ __launch_bounds__(256) void ln16h_kernel(const __half* __restrict__ x,
                                                    const float* __restrict__ g,
                                                    const float* __restrict__ b,
                                                    __half* __restrict__ o16) {
    int token = blockIdx.x * 8 + (threadIdx.x >> 5);
    int lane  = threadIdx.x & 31;
    const __half* p = x + (size_t)token * C_;
    float v[6];
    float s = 0.f;
    #pragma unroll
    for (int j = 0; j < 6; j++) { v[j] = __half2float(p[lane + 32*j]); s += v[j]; }
    #pragma unroll
    for (int o = 16; o > 0; o >>= 1) s += __shfl_xor_sync(0xffffffffu, s, o);
    float mean = s * (1.f / C_);
    float q = 0.f;
    #pragma unroll
    for (int j = 0; j < 6; j++) { float d = v[j] - mean; q += d * d; }
    #pragma unroll
    for (int o = 16; o > 0; o >>= 1) q += __shfl_xor_sync(0xffffffffu, q, o);
    float rstd = rsqrtf(q * (1.f / C_) + 1e-5f);
    #pragma unroll
    for (int j = 0; j < 6; j++) {
        int c = lane + 32*j;
        o16[(size_t)token * C_ + c] = __float2half_rn((v[j] - mean) * rstd * g[c] + b[c]);
    }
}

// ============ Windowed attention: tensor-core, double-buffered head pairs ==
#define ATTN_SMEM (2*6*5120)
__global__ __launch_bounds__(256, 2) void attn_mma_kernel(const __half* __restrict__ qkv16,
                                                          const float* __restrict__ rpb,
                                                          __half* __restrict__ ao16) {
    extern __shared__ char dsmem[];
    __shared__ float  srpb[225 * NH];
    __shared__ int    gidx[64];
    __shared__ int    rid [64];

    const int tid  = threadIdx.x;
    const int lane = tid & 31;
    const int warp = tid >> 5;
    const int wid  = blockIdx.x;
    const int bb   = wid >> 10;
    const int wib  = wid & 1023;
    const int wh   = wib >> 5, ww = wib & 31;

    if (tid < 64) {
        int ih = tid >> 3, iw = tid & 7;
        int h = wh * 8 + ih, w = ww * 8 + iw;
        gidx[tid] = bb * L_ + ((h + SHIFT) & (H_ - 1)) * W_ + ((w + SHIFT) & (W_ - 1));
        int rh = (h < H_ - WS) ? 0 : ((h < H_ - SHIFT) ? 1 : 2);
        int rw = (w < W_ - WS) ? 0 : ((w < W_ - SHIFT) ? 1 : 2);
        rid[tid] = rh * 3 + rw;
    }
    for (int i = tid; i < 225 * NH; i += 256) srpb[i] = rpb[i];
    __syncthreads();

    const uint32_t pb = smem_to_u32(dsmem);
    const int hp   = warp >> 2;
    const int r0   = (warp & 3) * 16;
    const int i_lo = r0 + (lane >> 2);
    const int i_hi = i_lo + 8;
    const int ihlo = i_lo >> 3, iwlo = i_lo & 7;
    const int ihhi = i_hi >> 3, iwhi = i_hi & 7;
    const float SCALE = 0.17677669529663687f;

#define ATTN_LOAD(buf, h0v) do { \
    _Pragma("unroll") \
    for (int i = 0; i < 6; i++) { \
        int t   = tid + i * 256; \
        int rowid = t >> 2, seg = t & 3; \
        int p   = rowid >> 6, tok = rowid & 63; \
        int mat = p % 3, php = p / 3; \
        const __half* g = qkv16 + (size_t)gidx[tok] * (3*C_) + mat * C_ + ((h0v) + php) * HD + seg * 8; \
        uint32_t d = pb + (buf) * 30720 + p * 5120 + tok * 80 + seg * 16; \
        CP_ASYNC16(d, g); \
    } \
    CP_COMMIT(); } while (0)

    ATTN_LOAD(0, 0);

    for (int it = 0; it < 3; ++it) {
        const int buf = it & 1;
        const int h0 = it * 2;
        asm volatile("cp.async.wait_group 0;" ::: "memory");
        __syncthreads();
        if (it + 1 < 3) ATTN_LOAD(buf ^ 1, h0 + 2);

        const uint32_t qbase = pb + buf * 30720 + hp * 15360;
        const uint32_t kbase = qbase + 5120;
        const uint32_t vbase = qbase + 10240;
        const int head = h0 + hp;

        float S[8][4];
        #pragma unroll
        for (int t = 0; t < 8; t++)
            #pragma unroll
            for (int q = 0; q < 4; q++) S[t][q] = 0.f;
        #pragma unroll
        for (int ks = 0; ks < 2; ks++) {
            uint32_t qf[4];
            LDSM4(qf, qbase + (r0 + (lane & 15)) * 80 + ks * 32 + ((lane >> 4) & 1) * 16);
            #pragma unroll
            for (int np = 0; np < 4; np++) {
                uint32_t kf[4];
                LDSM4(kf, kbase + ((lane & 7) + ((lane >> 4) & 1) * 8 + np * 16) * 80
                          + ks * 32 + ((lane >> 3) & 1) * 16);
                MMA_F16(S[np*2+0], qf, kf[0], kf[1]);
                MMA_F16(S[np*2+1], qf, kf[2], kf[3]);
            }
        }
        const int ridlo = rid[i_lo], ridhi = rid[i_hi];
        float mlo = -1e30f, mhi = -1e30f;
        #pragma unroll
        for (int t = 0; t < 8; t++) {
            int jc = (t >> 1) * 16 + (t & 1) * 8 + (lane & 3) * 2;
            #pragma unroll
            for (int e = 0; e < 2; e++) {
                int j = jc + e;
                int jh = j >> 3, jw = j & 7;
                float blo = srpb[((ihlo - jh + 7) * 15 + (iwlo - jw + 7)) * NH + head];
                float bhi = srpb[((ihhi - jh + 7) * 15 + (iwhi - jw + 7)) * NH + head];
                int rj = rid[j];
                float v0 = S[t][e]     * SCALE + blo + ((ridlo != rj) ? -100.f : 0.f);
                float v1 = S[t][e + 2] * SCALE + bhi + ((ridhi != rj) ? -100.f : 0.f);
                S[t][e] = v0; S[t][e + 2] = v1;
                mlo = fmaxf(mlo, v0); mhi = fmaxf(mhi, v1);
            }
        }
        mlo = fmaxf(mlo, __shfl_xor_sync(0xffffffffu, mlo, 1));
        mlo = fmaxf(mlo, __shfl_xor_sync(0xffffffffu, mlo, 2));
        mhi = fmaxf(mhi, __shfl_xor_sync(0xffffffffu, mhi, 1));
        mhi = fmaxf(mhi, __shfl_xor_sync(0xffffffffu, mhi, 2));
        float slo = 0.f, shi = 0.f;
        #pragma unroll
        for (int t = 0; t < 8; t++) {
            #pragma unroll
            for (int e = 0; e < 2; e++) {
                float v0 = __expf(S[t][e] - mlo);
                float v1 = __expf(S[t][e + 2] - mhi);
                S[t][e] = v0; S[t][e + 2] = v1;
                slo += v0; shi += v1;
            }
        }
        slo += __shfl_xor_sync(0xffffffffu, slo, 1);
        slo += __shfl_xor_sync(0xffffffffu, slo, 2);
        shi += __shfl_xor_sync(0xffffffffu, shi, 1);
        shi += __shfl_xor_sync(0xffffffffu, shi, 2);
        float ilo = 1.f / slo, ihi2 = 1.f / shi;
        uint32_t pa[4][4];
        #pragma unroll
        for (int kt = 0; kt < 4; kt++) {
            pa[kt][0] = pack_h2(S[kt*2][0] * ilo,  S[kt*2][1] * ilo);
            pa[kt][1] = pack_h2(S[kt*2][2] * ihi2, S[kt*2][3] * ihi2);
            pa[kt][2] = pack_h2(S[kt*2+1][0] * ilo,  S[kt*2+1][1] * ilo);
            pa[kt][3] = pack_h2(S[kt*2+1][2] * ihi2, S[kt*2+1][3] * ihi2);
        }
        float O[4][4];
        #pragma unroll
        for (int t = 0; t < 4; t++)
            #pragma unroll
            for (int q = 0; q < 4; q++) O[t][q] = 0.f;
        #pragma unroll
        for (int kt = 0; kt < 4; kt++) {
            #pragma unroll
            for (int nc = 0; nc < 2; nc++) {
                uint32_t vf[4];
                LDSM4T(vf, vbase + (kt * 16 + (lane & 7) + ((lane >> 3) & 1) * 8) * 80
                           + nc * 32 + ((lane >> 4) & 1) * 16);
                MMA_F16(O[nc*2+0], pa[kt], vf[0], vf[1]);
                MMA_F16(O[nc*2+1], pa[kt], vf[2], vf[3]);
            }
        }
        #pragma unroll
        for (int t = 0; t < 4; t++) {
            int col = t * 8 + (lane & 3) * 2;
            *(uint32_t*)(ao16 + (size_t)gidx[i_lo] * C_ + head * HD + col) = pack_h2(O[t][0], O[t][1]);
            *(uint32_t*)(ao16 + (size_t)gidx[i_hi] * C_ + head * HD + col) = pack_h2(O[t][2], O[t][3]);
        }
    }
#undef ATTN_LOAD
}

// ---------------- 3x3 conv on r=24 channels, NHWC, pad 1 -------------------
__global__ __launch_bounds__(64) void conv3_kernel(const float* __restrict__ yin,
                                                   const float* __restrict__ w,
                                                   const float* __restrict__ bias,
                                                   __half* __restrict__ y16) {
    __shared__ float patch[100][RED_];
    __shared__ float wts[RED_ * RED_ * 9];
    int tid = threadIdx.x;
    int b = blockIdx.z;
    int th0 = blockIdx.y * 8, tw0 = blockIdx.x * 8;

    for (int d = tid; d < RED_ * RED_ * 9; d += 64) {
        int oc = d % RED_;
        int t2 = d / RED_;
        int kk = t2 % 9;
        int ic = t2 / 9;
        wts[d] = w[(oc * RED_ + ic) * 9 + kk];
    }
    for (int d = tid; d < 100 * RED_; d += 64) {
        int ic = d % RED_;
        int pos = d / RED_;
        int ph = pos / 10, pw = pos % 10;
        int hh = th0 + ph - 1, ww = tw0 + pw - 1;
        float v = 0.f;
        if (hh >= 0 && hh < H_ && ww >= 0 && ww < W_)
            v = yin[((size_t)b * L_ + hh * W_ + ww) * RED_ + ic];
        patch[pos][ic] = v;
    }
    __syncthreads();

    int py = tid >> 3, px = tid & 7;
    float acc[RED_];
    #pragma unroll
    for (int oc = 0; oc < RED_; oc++) acc[oc] = __ldg(bias + oc);
    for (int ic = 0; ic < RED_; ic++) {
        #pragma unroll
        for (int kk = 0; kk < 9; kk++) {
            int kh = kk / 3, kw = kk % 3;
            float pv = patch[(py + kh) * 10 + (px + kw)][ic];
            const float4* wp = (const float4*)&wts[(ic * 9 + kk) * RED_];
            #pragma unroll
            for (int o4 = 0; o4 < 6; o4++) {
                float4 wv = wp[o4];
                acc[o4*4+0] += wv.x * pv; acc[o4*4+1] += wv.y * pv;
                acc[o4*4+2] += wv.z * pv; acc[o4*4+3] += wv.w * pv;
            }
        }
    }
    size_t off = ((size_t)b * L_ + (th0 + py) * W_ + (tw0 + px)) * RED_;
    #pragma unroll
    for (int oc = 0; oc < RED_; oc += 2)
        *(uint32_t*)(y16 + off + oc) = pack_h2(acc[oc], acc[oc + 1]);
}

// ---------------- pool / SE ------------------------------------------------
__global__ __launch_bounds__(192) void pool_kernel(const __half* __restrict__ y16,
                                                   float* __restrict__ pool) {
    int base = blockIdx.x * 128;
    int b = base >> 16;
    int c = threadIdx.x;
    float acc = 0.f;
    for (int i = 0; i < 128; i++)
        acc += __half2float(y16[(size_t)(base + i) * C_ + c]);
    atomicAdd(&pool[b * C_ + c], acc);
}

__global__ __launch_bounds__(192) void se_kernel(const float* __restrict__ pool,
                                                 const float* __restrict__ fc1,
                                                 const float* __restrict__ fc2,
                                                 float* __restrict__ sbuf) {
    __shared__ float t[RED_];
    int tid = threadIdx.x;
    const float inv = 1.f / (float)L_;
    for (int b = 0; b < B_; b++) {
        if (tid < RED_) {
            float s = 0.f;
            for (int c = 0; c < C_; c++)
                s += pool[b * C_ + c] * inv * fc1[tid * C_ + c];
            t[tid] = fmaxf(s, 0.f);
        }
        __syncthreads();
        float s = 0.f;
        #pragma unroll
        for (int j = 0; j < RED_; j++) s += t[j] * fc2[tid * RED_ + j];
        sbuf[b * C_ + tid] = 1.f / (1.f + expf(-s));
        __syncthreads();
    }
}

// ---------------- launch ---------------------------------------------------
extern "C" void kernel_launch(void* const* d_in, const int* in_sizes, int n_in,
                              void* d_out, int out_size) {
    const float* x      = (const float*)d_in[0];
    const float* n1g    = (const float*)d_in[1];
    const float* n1b    = (const float*)d_in[2];
    const float* qkvw   = (const float*)d_in[3];
    const float* qkvb   = (const float*)d_in[4];
    const float* rpb    = (const float*)d_in[5];
    const float* projw  = (const float*)d_in[6];
    const float* projb  = (const float*)d_in[7];
    const float* n2g    = (const float*)d_in[8];
    const float* n2b    = (const float*)d_in[9];
    const float* fc1w   = (const float*)d_in[10];
    const float* fc1b   = (const float*)d_in[11];
    const float* fc2w   = (const float*)d_in[12];
    const float* fc2b   = (const float*)d_in[13];
    const float* c1w    = (const float*)d_in[14];
    const float* c1b    = (const float*)d_in[15];
    const float* c2w    = (const float*)d_in[16];
    const float* c2b    = (const float*)d_in[17];
    const float* c3w    = (const float*)d_in[18];
    const float* c3b    = (const float*)d_in[19];
    const float* sfc1   = (const float*)d_in[20];
    const float* sfc2   = (const float*)d_in[21];
    float* out = (float*)d_out;

    float *y1, *pool, *sbuf;
    cudaGetSymbolAddress((void**)&y1,   g_y1);
    cudaGetSymbolAddress((void**)&pool, g_pool);
    cudaGetSymbolAddress((void**)&sbuf, g_s);
    __half *qkv16, *xn16, *ao16, *x116, *x1n16, *hb16, *y216, *y16;
    __half *wq, *wp, *w1, *w2, *wc1, *wc3;
    cudaGetSymbolAddress((void**)&qkv16, g_qkv16);
    cudaGetSymbolAddress((void**)&xn16,  g_xn16);
    cudaGetSymbolAddress((void**)&ao16,  g_ao16);
    cudaGetSymbolAddress((void**)&x116,  g_x116);
    cudaGetSymbolAddress((void**)&x1n16, g_x1n16);
    cudaGetSymbolAddress((void**)&hb16,  g_hb16);
    cudaGetSymbolAddress((void**)&y216,  g_y216);
    cudaGetSymbolAddress((void**)&y16,   g_y16);
    cudaGetSymbolAddress((void**)&wq,  g_wq);
    cudaGetSymbolAddress((void**)&wp,  g_wp);
    cudaGetSymbolAddress((void**)&w1,  g_w1);
    cudaGetSymbolAddress((void**)&w2,  g_w2);
    cudaGetSymbolAddress((void**)&wc1, g_wc1);
    cudaGetSymbolAddress((void**)&wc3, g_wc3);

    cudaFuncSetAttribute(gemm_cp<0,0,0>, cudaFuncAttributeMaxDynamicSharedMemorySize, GEMM_SMEM_SZ);
    cudaFuncSetAttribute(gemm_cp<0,1,1>, cudaFuncAttributeMaxDynamicSharedMemorySize, GEMM_SMEM_SZ);
    cudaFuncSetAttribute(gemm_cp<1,1,1>, cudaFuncAttributeMaxDynamicSharedMemorySize, GEMM_SMEM_SZ);
    cudaFuncSetAttribute(gemm_cp<2,1,1>, cudaFuncAttributeMaxDynamicSharedMemorySize, GEMM_SMEM_SZ);
    cudaFuncSetAttribute(gemm_cp<3,1,0>, cudaFuncAttributeMaxDynamicSharedMemorySize, GEMM_SMEM_SZ);
    cudaFuncSetAttribute(gemm_cp<4,0,1>, cudaFuncAttributeMaxDynamicSharedMemorySize, GEMM_SMEM_SZ);
    cudaFuncSetAttribute(attn_mma_kernel, cudaFuncAttributeMaxDynamicSharedMemorySize, ATTN_SMEM);

    // 1) weight convert + pool zero (one launch)
    convert_all_kernel<<<(STOT+255)/256, 256>>>(qkvw, projw, fc1w, fc2w, c1w, c3w,
        wq, wp, w1, w2, wc1, wc3, pool);
    // 2) LN1 -> fp16 plane
    ln16_kernel<<<M_/8, 256>>>(x, n1g, n1b, xn16);
    // 3) QKV GEMM -> fp16 (clean)
    gemm_cp<0,1,1><<<dim3(6, M_/128), 256, GEMM_SMEM_SZ>>>(xn16, wq, qkvb, nullptr, nullptr, nullptr, nullptr, nullptr, qkv16, 3*C_, C_);
    // 4) LCE conv1x1 C->24 -> y1 fp32 (checked: N=24)
    gemm_cp<0,0,0><<<dim3(1, M_/128), 256, GEMM_SMEM_SZ>>>(xn16, wc1, c1b, nullptr, nullptr, nullptr, nullptr, y1, nullptr, RED_, C_);
    // 5) attention -> ao fp16
    attn_mma_kernel<<<NWIN, 256, ATTN_SMEM>>>(qkv16, rpb, ao16);
    // 6) proj + residual(x fp32) -> x1 fp16 (clean)
    gemm_cp<1,1,1><<<dim3(2, M_/128), 256, GEMM_SMEM_SZ>>>(ao16, wp, projb, x, nullptr, nullptr, nullptr, nullptr, x116, C_, C_);
    // 7) LN2 (fp16 in) -> fp16 plane
    ln16h_kernel<<<M_/8, 256>>>(x116, n2g, n2b, x1n16);
    // 8) fc1 + GELU -> hb fp16 (clean)
    gemm_cp<2,1,1><<<dim3(8, M_/128), 256, GEMM_SMEM_SZ>>>(x1n16, w1, fc1b, nullptr, nullptr, nullptr, nullptr, nullptr, hb16, HID_, C_);
    // 9) LCE conv3x3 -> y2 fp16
    conv3_kernel<<<dim3(W_/8, H_/8, B_), 64>>>(y1, c2w, c2b, y216);
    // 10) LCE conv1x1 24->192 + LeakyReLU -> y fp16 (checked: K=24)
    gemm_cp<3,1,0><<<dim3(2, M_/128), 256, GEMM_SMEM_SZ>>>(y216, wc3, c3b, nullptr, nullptr, nullptr, nullptr, nullptr, y16, C_, RED_);
    // 11) global avg pool (fp16 in) + SE gate
    pool_kernel<<<M_/128, 192>>>(y16, pool);
    se_kernel<<<1, 192>>>(pool, sfc1, sfc2, sbuf);
    // 12) fc2 + residual(x1 fp16) + SE-gated lc (y fp16) -> out fp32 (clean)
    gemm_cp<4,0,1><<<dim3(2, M_/128), 256, GEMM_SMEM_SZ>>>(hb16, w2, fc2b, nullptr, x116, y16, sbuf, out, nullptr, C_, HID_);
}

// round 16
// speedup vs baseline: 7.5598x; 1.0213x over previous
#include <cuda_runtime.h>
#include <cuda_fp16.h>
#include <math.h>
#include <stdint.h>

#define B_    2
#define H_    256
#define W_    256
#define C_    192
#define L_    (H_*W_)         // 65536
#define M_    (B_*L_)         // 131072
#define HID_  768
#define NH    6
#define HD    32
#define WS    8
#define SHIFT 4
#define NWIN  (B_*(H_/WS)*(W_/WS))  // 2048
#define RED_  24

// ---------------- scratch (device globals; no allocations) ----------------
__device__ float g_y1 [M_*RED_];
__device__ float g_pool[B_*C_];
__device__ float g_s  [B_*C_];
// fp16 activation planes
__device__ __half g_qkv16[(size_t)M_*3*C_];
__device__ __half g_xn16 [M_*C_];
__device__ __half g_ao16 [M_*C_];
__device__ __half g_x116 [M_*C_];
__device__ __half g_x1n16[M_*C_];
__device__ __half g_hb16 [(size_t)M_*HID_];
__device__ __half g_y216 [M_*RED_];
__device__ __half g_y16  [M_*C_];
// fp16 weights (single plane)
__device__ __half g_wq [3*C_*C_];
__device__ __half g_wp [C_*C_];
__device__ __half g_w1 [HID_*C_];
__device__ __half g_w2 [C_*HID_];
__device__ __half g_wc1[RED_*C_];
__device__ __half g_wc3[C_*RED_];

// ======================= helpers ===========================================
__device__ __forceinline__ uint32_t smem_to_u32(const void* p) {
    uint32_t a;
    asm("{ .reg .u64 t; cvta.to.shared.u64 t, %1; cvt.u32.u64 %0, t; }" : "=r"(a) : "l"(p));
    return a;
}
__device__ __forceinline__ uint32_t pack_h2(float x, float y) {
    __half2 h = __floats2half2_rn(x, y);
    return *reinterpret_cast<uint32_t*>(&h);
}
__device__ __forceinline__ float2 unpack_h2(uint32_t u) {
    __half2 h = *reinterpret_cast<__half2*>(&u);
    return __half22float2(h);
}
#define LDSM4(r, addr) \
    asm volatile("ldmatrix.sync.aligned.m8n8.x4.shared.b16 {%0,%1,%2,%3}, [%4];" \
        : "=r"((r)[0]), "=r"((r)[1]), "=r"((r)[2]), "=r"((r)[3]) : "r"(addr))
#define LDSM4T(r, addr) \
    asm volatile("ldmatrix.sync.aligned.m8n8.x4.trans.shared.b16 {%0,%1,%2,%3}, [%4];" \
        : "=r"((r)[0]), "=r"((r)[1]), "=r"((r)[2]), "=r"((r)[3]) : "r"(addr))
#define MMA_F16(d, a, b0, b1) \
    asm volatile("mma.sync.aligned.m16n8k16.row.col.f32.f16.f16.f32 " \
        "{%0,%1,%2,%3},{%4,%5,%6,%7},{%8,%9},{%0,%1,%2,%3};" \
        : "+f"((d)[0]), "+f"((d)[1]), "+f"((d)[2]), "+f"((d)[3]) \
        : "r"((a)[0]), "r"((a)[1]), "r"((a)[2]), "r"((a)[3]), "r"(b0), "r"(b1))
#define CP_ASYNC(dst, src, sz) \
    asm volatile("cp.async.cg.shared.global [%0], [%1], 16, %2;" \
        :: "r"(dst), "l"(src), "r"(sz))
#define CP_ASYNC16(dst, src) \
    asm volatile("cp.async.cg.shared.global [%0], [%1], 16;" \
        :: "r"(dst), "l"(src))
#define CP_COMMIT() asm volatile("cp.async.commit_group;" ::: "memory")

// ======================= fp16 mma.sync GEMM (128x96 tile, 4-stage) =========
// out[M,N] = epi(A @ W^T + bias); A and W single fp16 planes [rows][K].
// EPI: 0 none, 1 +res32, 2 exact GELU, 3 LeakyReLU(0.2),
//      4 +res16 + gate (out = v + res16 + yy16*s[b,col]). OUTP: 1 = fp16 out.
// CLEAN: 1 = K%32==0 && N%96==0.
#define STG_STRIDE 17920   // A 10240 | W 7680
#define W_OFF 10240
#define NSTG 4
#define GEMM_SMEM_SZ (NSTG*STG_STRIDE)   // 71680; 3 CTAs/SM = 210KB <= 228KB

template<int EPI, int OUTP, int CLEAN>
__device__ __forceinline__ void gemm_body(const __half* __restrict__ A16,
                                          const __half* __restrict__ Wt,
                                          const float* __restrict__ bias,
                                          const float* __restrict__ res32,
                                          const __half* __restrict__ res16,
                                          const __half* __restrict__ yy16,
                                          const float* __restrict__ sgate,
                                          float* __restrict__ out,
                                          __half* __restrict__ out16,
                                          int N, int K, char* smem) {
    const int tid  = threadIdx.x;
    const int lane = tid & 31;
    const int warp = tid >> 5;
    const int m0 = blockIdx.y * 128, n0 = blockIdx.x * 96;
    const int wm = (warp & 3) * 32, wn = (warp >> 2) * 48;
    const int nch = (K + 31) >> 5;
    const uint32_t sb = smem_to_u32(smem);

    const __half* gA0 = nullptr; const __half* gA1 = nullptr;
    const __half* gW0 = nullptr; const __half* gW1 = nullptr;
    uint32_t dA0 = 0, dA1 = 0, dW0 = 0, dW1 = 0;
    if (CLEAN) {
        int row = tid >> 2, seg = tid & 3;
        gA0 = A16 + (size_t)(m0 + row) * K + seg * 8;
        gA1 = gA0 + (size_t)64 * K;
        gW0 = Wt + (size_t)(n0 + row) * K + seg * 8;
        gW1 = gW0 + (size_t)64 * K;
        dA0 = sb + row * 80 + seg * 16;
        dA1 = dA0 + 64 * 80;
        dW0 = dA0 + W_OFF;
        dW1 = dW0 + 64 * 80;
    }

#define ISSUE_C(stg) do { \
    uint32_t so_ = (uint32_t)(stg) * STG_STRIDE; \
    CP_ASYNC16(dA0 + so_, gA0); \
    CP_ASYNC16(dA1 + so_, gA1); \
    CP_ASYNC16(dW0 + so_, gW0); \
    if (tid < 128) CP_ASYNC16(dW1 + so_, gW1); \
    CP_COMMIT(); \
    gA0 += 32; gA1 += 32; gW0 += 32; gW1 += 32; } while (0)

#define ISSUE(stg, c) do { \
    char* base_ = smem + (stg) * STG_STRIDE; \
    int k0_ = (c) * 32; \
    _Pragma("unroll") \
    for (int i = 0; i < 2; i++) { \
        int t = tid + i * 256; \
        int row = t >> 2, seg = t & 3; \
        int ke = k0_ + seg * 8; \
        int srcsz = (K - ke) * 2; \
        srcsz = srcsz < 0 ? 0 : (srcsz > 16 ? 16 : srcsz); \
        const __half* g = A16 + (size_t)(m0 + row) * K + (srcsz ? ke : 0); \
        uint32_t d = smem_to_u32(base_ + row * 80 + seg * 16); \
        CP_ASYNC(d, g, srcsz); \
    } \
    _Pragma("unroll") \
    for (int i = 0; i < 2; i++) { \
        int t = tid + i * 256; \
        if (t < 384) { \
            int row = t >> 2, seg = t & 3; \
            int ke = k0_ + seg * 8; \
            int srcsz = (K - ke) * 2; \
            srcsz = srcsz < 0 ? 0 : (srcsz > 16 ? 16 : srcsz); \
            if (n0 + row >= N) srcsz = 0; \
            int grow = (n0 + row < N) ? (n0 + row) : 0; \
            const __half* g = Wt + (size_t)grow * K + (srcsz ? ke : 0); \
            uint32_t d = smem_to_u32(base_ + W_OFF + row * 80 + seg * 16); \
            CP_ASYNC(d, g, srcsz); \
        } \
    } \
    CP_COMMIT(); } while (0)

    float acc[2][6][4];
    #pragma unroll
    for (int i = 0; i < 2; i++)
        #pragma unroll
        for (int j = 0; j < 6; j++)
            #pragma unroll
            for (int q = 0; q < 4; q++) acc[i][j][q] = 0.f;

    if (CLEAN) {
        ISSUE_C(0);
        if (nch > 1) ISSUE_C(1);
        if (nch > 2) ISSUE_C(2);
    } else {
        ISSUE(0, 0);
        if (nch > 1) ISSUE(1, 1);
        if (nch > 2) ISSUE(2, 2);
    }

    int sc = 0;
    for (int c = 0; c < nch; c++) {
        int rem = nch - 1 - c;
        if (rem >= 2)      asm volatile("cp.async.wait_group 2;" ::: "memory");
        else if (rem == 1) asm volatile("cp.async.wait_group 1;" ::: "memory");
        else               asm volatile("cp.async.wait_group 0;" ::: "memory");
        __syncthreads();
        char* base = smem + sc * STG_STRIDE;
        #pragma unroll
        for (int ks = 0; ks < 2; ks++) {
            uint32_t af[2][4], wf[3][4];
            #pragma unroll
            for (int mt = 0; mt < 2; mt++) {
                int row = wm + mt * 16 + (lane & 15);
                int colb = ks * 32 + ((lane >> 4) & 1) * 16;
                LDSM4(af[mt], smem_to_u32(base + row * 80 + colb));
            }
            #pragma unroll
            for (int np = 0; np < 3; np++) {
                int n = wn + np * 16 + (lane & 7) + ((lane >> 4) & 1) * 8;
                int colb = ks * 32 + ((lane >> 3) & 1) * 16;
                LDSM4(wf[np], smem_to_u32(base + W_OFF + n * 80 + colb));
            }
            #pragma unroll
            for (int mt = 0; mt < 2; mt++)
                #pragma unroll
                for (int nt = 0; nt < 6; nt++) {
                    int np = nt >> 1, h = (nt & 1) * 2;
                    MMA_F16(acc[mt][nt], af[mt], wf[np][h], wf[np][h+1]);
                }
        }
        if (c + 3 < nch) {
            int si = sc + 3; if (si >= NSTG) si -= NSTG;
            if (CLEAN) ISSUE_C(si);
            else       ISSUE(si, c + 3);
        }
        sc = (sc + 1 == NSTG) ? 0 : sc + 1;
    }

    // ---- epilogue ----
    #pragma unroll
    for (int mt = 0; mt < 2; mt++) {
        int r0 = m0 + wm + mt * 16 + (lane >> 2);
        #pragma unroll
        for (int nt = 0; nt < 6; nt++) {
            int col = n0 + wn + nt * 8 + (lane & 3) * 2;
            if (col < N) {
                float b0v = bias[col], b1v = bias[col + 1];
                #pragma unroll
                for (int rr = 0; rr < 2; rr++) {
                    int r = r0 + rr * 8;
                    float v0 = acc[mt][nt][rr*2+0] + b0v;
                    float v1 = acc[mt][nt][rr*2+1] + b1v;
                    if (EPI == 1) {
                        float2 rv = *(const float2*)(res32 + (size_t)r * N + col);
                        v0 += rv.x; v1 += rv.y;
                    }
                    if (EPI == 2) {
                        v0 = 0.5f * v0 * (1.f + erff(v0 * 0.70710678118654752f));
                        v1 = 0.5f * v1 * (1.f + erff(v1 * 0.70710678118654752f));
                    }
                    if (EPI == 3) {
                        v0 = (v0 >= 0.f) ? v0 : 0.2f * v0;
                        v1 = (v1 >= 0.f) ? v1 : 0.2f * v1;
                    }
                    if (EPI == 4) {
                        float2 rv = unpack_h2(*(const uint32_t*)(res16 + (size_t)r * N + col));
                        float2 yv = unpack_h2(*(const uint32_t*)(yy16 + (size_t)r * N + col));
                        const float* sb2 = sgate + (r >> 16) * C_;
                        v0 += rv.x + yv.x * sb2[col];
                        v1 += rv.y + yv.y * sb2[col + 1];
                    }
                    if (OUTP) {
                        *(uint32_t*)(out16 + (size_t)r * N + col) = pack_h2(v0, v1);
                    } else {
                        *(float2*)(out + (size_t)r * N + col) = make_float2(v0, v1);
                    }
                }
            }
        }
    }
#undef ISSUE
#undef ISSUE_C
}

template<int EPI, int OUTP, int CLEAN>
__global__ __launch_bounds__(256, 3) void gemm_cp(const __half* __restrict__ A16,
                                                  const __half* __restrict__ Wt,
                                                  const float* __restrict__ bias,
                                                  const float* __restrict__ res32,
                                                  const __half* __restrict__ res16,
                                                  const __half* __restrict__ yy16,
                                                  const float* __restrict__ sgate,
                                                  float* __restrict__ out,
                                                  __half* __restrict__ out16,
                                                  int N, int K) {
    extern __shared__ char smem[];
    gemm_body<EPI, OUTP, CLEAN>(A16, Wt, bias, res32, res16, yy16, sgate, out, out16, N, K, smem);
}

// ---------------- merged weight convert + pool zero ------------------------
#define S0 (3*C_*C_)
#define S1 (C_*C_)
#define S2 (HID_*C_)
#define S3 (C_*HID_)
#define S4 (RED_*C_)
#define S5 (C_*RED_)
#define STOT (S0+S1+S2+S3+S4+S5)
__global__ __launch_bounds__(256) void convert_all_kernel(
        const float* __restrict__ w0, const float* __restrict__ w1,
        const float* __restrict__ w2, const float* __restrict__ w3,
        const float* __restrict__ w4, const float* __restrict__ w5,
        __half* h0, __half* h1, __half* h2, __half* h3, __half* h4, __half* h5,
        float* pool) {
    int i = blockIdx.x * 256 + threadIdx.x;
    if (i < B_ * C_) pool[i] = 0.f;
    const float* s; __half* h; int off;
    if      (i < S0)                { s = w0; h = h0; off = i; }
    else if (i < S0+S1)             { s = w1; h = h1; off = i - S0; }
    else if (i < S0+S1+S2)          { s = w2; h = h2; off = i - S0-S1; }
    else if (i < S0+S1+S2+S3)       { s = w3; h = h3; off = i - S0-S1-S2; }
    else if (i < S0+S1+S2+S3+S4)    { s = w4; h = h4; off = i - S0-S1-S2-S3; }
    else if (i < STOT)              { s = w5; h = h5; off = i - S0-S1-S2-S3-S4; }
    else return;
    h[off] = __float2half_rn(s[off]);
}

// ---------------- LayerNorm fp32-in -> fp16 plane --------------------------
__global__ __launch_bounds__(256) void ln16_kernel(const float* __restrict__ x,
                                                   const float* __restrict__ g,
                                                   const float* __restrict__ b,
                                                   __half* __restrict__ o16) {
    int token = blockIdx.x * 8 + (threadIdx.x >> 5);
    int lane  = threadIdx.x & 31;
    const float* p = x + (size_t)token * C_;
    float v[6];
    float s = 0.f;
    #pragma unroll
    for (int j = 0; j < 6; j++) { v[j] = p[lane + 32*j]; s += v[j]; }
    #pragma unroll
    for (int o = 16; o > 0; o >>= 1) s += __shfl_xor_sync(0xffffffffu, s, o);
    float mean = s * (1.f / C_);
    float q = 0.f;
    #pragma unroll
    for (int j = 0; j < 6; j++) { float d = v[j] - mean; q += d * d; }
    #pragma unroll
    for (int o = 16; o > 0; o >>= 1) q += __shfl_xor_sync(0xffffffffu, q, o);
    float rstd = rsqrtf(q * (1.f / C_) + 1e-5f);
    #pragma unroll
    for (int j = 0; j < 6; j++) {
        int c = lane + 32*j;
        o16[(size_t)token * C_ + c] = __float2half_rn((v[j] - mean) * rstd * g[c] + b[c]);
    }
}

// ---------------- LayerNorm fp16-in -> fp16 plane --------------------------
__global__ __launch_bounds__(256) void ln16h_kernel(const __half* __restrict__ x,
                                                    const float* __restrict__ g,
                                                    const float* __restrict__ b,
                                                    __half* __restrict__ o16) {
    int token = blockIdx.x * 8 + (threadIdx.x >> 5);
    int lane  = threadIdx.x & 31;
    const __half* p = x + (size_t)token * C_;
    float v[6];
    float s = 0.f;
    #pragma unroll
    for (int j = 0; j < 6; j++) { v[j] = __half2float(p[lane + 32*j]); s += v[j]; }
    #pragma unroll
    for (int o = 16; o > 0; o >>= 1) s += __shfl_xor_sync(0xffffffffu, s, o);
    float mean = s * (1.f / C_);
    float q = 0.f;
    #pragma unroll
    for (int j = 0; j < 6; j++) { float d = v[j] - mean; q += d * d; }
    #pragma unroll
    for (int o = 16; o > 0; o >>= 1) q += __shfl_xor_sync(0xffffffffu, q, o);
    float rstd = rsqrtf(q * (1.f / C_) + 1e-5f);
    #pragma unroll
    for (int j = 0; j < 6; j++) {
        int c = lane + 32*j;
        o16[(size_t)token * C_ + c] = __float2half_rn((v[j] - mean) * rstd * g[c] + b[c]);
    }
}

// ============ Windowed attention: tensor-core, double-buffered head pairs ==
#define ATTN_SMEM (2*6*5120)    // 61440; 3 CTAs/SM = 180KB
__global__ __launch_bounds__(256, 3) void attn_mma_kernel(const __half* __restrict__ qkv16,
                                                          const float* __restrict__ rpb,
                                                          __half* __restrict__ ao16) {
    extern __shared__ char dsmem[];
    __shared__ float  srpb[225 * NH];
    __shared__ int    gidx[64];
    __shared__ int    rid [64];

    const int tid  = threadIdx.x;
    const int lane = tid & 31;
    const int warp = tid >> 5;
    const int wid  = blockIdx.x;
    const int bb   = wid >> 10;
    const int wib  = wid & 1023;
    const int wh   = wib >> 5, ww = wib & 31;

    if (tid < 64) {
        int ih = tid >> 3, iw = tid & 7;
        int h = wh * 8 + ih, w = ww * 8 + iw;
        gidx[tid] = bb * L_ + ((h + SHIFT) & (H_ - 1)) * W_ + ((w + SHIFT) & (W_ - 1));
        int rh = (h < H_ - WS) ? 0 : ((h < H_ - SHIFT) ? 1 : 2);
        int rw = (w < W_ - WS) ? 0 : ((w < W_ - SHIFT) ? 1 : 2);
        rid[tid] = rh * 3 + rw;
    }
    for (int i = tid; i < 225 * NH; i += 256) srpb[i] = rpb[i];
    __syncthreads();

    const uint32_t pb = smem_to_u32(dsmem);
    const int hp   = warp >> 2;
    const int r0   = (warp & 3) * 16;
    const int i_lo = r0 + (lane >> 2);
    const int i_hi = i_lo + 8;
    const int ihlo = i_lo >> 3, iwlo = i_lo & 7;
    const int ihhi = i_hi >> 3, iwhi = i_hi & 7;
    const float SCALE = 0.17677669529663687f;

#define ATTN_LOAD(buf, h0v) do { \
    _Pragma("unroll") \
    for (int i = 0; i < 6; i++) { \
        int t   = tid + i * 256; \
        int rowid = t >> 2, seg = t & 3; \
        int p   = rowid >> 6, tok = rowid & 63; \
        int mat = p % 3, php = p / 3; \
        const __half* g = qkv16 + (size_t)gidx[tok] * (3*C_) + mat * C_ + ((h0v) + php) * HD + seg * 8; \
        uint32_t d = pb + (buf) * 30720 + p * 5120 + tok * 80 + seg * 16; \
        CP_ASYNC16(d, g); \
    } \
    CP_COMMIT(); } while (0)

    ATTN_LOAD(0, 0);

    for (int it = 0; it < 3; ++it) {
        const int buf = it & 1;
        const int h0 = it * 2;
        asm volatile("cp.async.wait_group 0;" ::: "memory");
        __syncthreads();
        if (it + 1 < 3) ATTN_LOAD(buf ^ 1, h0 + 2);

        const uint32_t qbase = pb + buf * 30720 + hp * 15360;
        const uint32_t kbase = qbase + 5120;
        const uint32_t vbase = qbase + 10240;
        const int head = h0 + hp;

        float S[8][4];
        #pragma unroll
        for (int t = 0; t < 8; t++)
            #pragma unroll
            for (int q = 0; q < 4; q++) S[t][q] = 0.f;
        #pragma unroll
        for (int ks = 0; ks < 2; ks++) {
            uint32_t qf[4];
            LDSM4(qf, qbase + (r0 + (lane & 15)) * 80 + ks * 32 + ((lane >> 4) & 1) * 16);
            #pragma unroll
            for (int np = 0; np < 4; np++) {
                uint32_t kf[4];
                LDSM4(kf, kbase + ((lane & 7) + ((lane >> 4) & 1) * 8 + np * 16) * 80
                          + ks * 32 + ((lane >> 3) & 1) * 16);
                MMA_F16(S[np*2+0], qf, kf[0], kf[1]);
                MMA_F16(S[np*2+1], qf, kf[2], kf[3]);
            }
        }
        const int ridlo = rid[i_lo], ridhi = rid[i_hi];
        float mlo = -1e30f, mhi = -1e30f;
        #pragma unroll
        for (int t = 0; t < 8; t++) {
            int jc = (t >> 1) * 16 + (t & 1) * 8 + (lane & 3) * 2;
            #pragma unroll
            for (int e = 0; e < 2; e++) {
                int j = jc + e;
                int jh = j >> 3, jw = j & 7;
                float blo = srpb[((ihlo - jh + 7) * 15 + (iwlo - jw + 7)) * NH + head];
                float bhi = srpb[((ihhi - jh + 7) * 15 + (iwhi - jw + 7)) * NH + head];
                int rj = rid[j];
                float v0 = S[t][e]     * SCALE + blo + ((ridlo != rj) ? -100.f : 0.f);
                float v1 = S[t][e + 2] * SCALE + bhi + ((ridhi != rj) ? -100.f : 0.f);
                S[t][e] = v0; S[t][e + 2] = v1;
                mlo = fmaxf(mlo, v0); mhi = fmaxf(mhi, v1);
            }
        }
        mlo = fmaxf(mlo, __shfl_xor_sync(0xffffffffu, mlo, 1));
        mlo = fmaxf(mlo, __shfl_xor_sync(0xffffffffu, mlo, 2));
        mhi = fmaxf(mhi, __shfl_xor_sync(0xffffffffu, mhi, 1));
        mhi = fmaxf(mhi, __shfl_xor_sync(0xffffffffu, mhi, 2));
        float slo = 0.f, shi = 0.f;
        #pragma unroll
        for (int t = 0; t < 8; t++) {
            #pragma unroll
            for (int e = 0; e < 2; e++) {
                float v0 = __expf(S[t][e] - mlo);
                float v1 = __expf(S[t][e + 2] - mhi);
                S[t][e] = v0; S[t][e + 2] = v1;
                slo += v0; shi += v1;
            }
        }
        slo += __shfl_xor_sync(0xffffffffu, slo, 1);
        slo += __shfl_xor_sync(0xffffffffu, slo, 2);
        shi += __shfl_xor_sync(0xffffffffu, shi, 1);
        shi += __shfl_xor_sync(0xffffffffu, shi, 2);
        float ilo = 1.f / slo, ihi2 = 1.f / shi;
        uint32_t pa[4][4];
        #pragma unroll
        for (int kt = 0; kt < 4; kt++) {
            pa[kt][0] = pack_h2(S[kt*2][0] * ilo,  S[kt*2][1] * ilo);
            pa[kt][1] = pack_h2(S[kt*2][2] * ihi2, S[kt*2][3] * ihi2);
            pa[kt][2] = pack_h2(S[kt*2+1][0] * ilo,  S[kt*2+1][1] * ilo);
            pa[kt][3] = pack_h2(S[kt*2+1][2] * ihi2, S[kt*2+1][3] * ihi2);
        }
        float O[4][4];
        #pragma unroll
        for (int t = 0; t < 4; t++)
            #pragma unroll
            for (int q = 0; q < 4; q++) O[t][q] = 0.f;
        #pragma unroll
        for (int kt = 0; kt < 4; kt++) {
            #pragma unroll
            for (int nc = 0; nc < 2; nc++) {
                uint32_t vf[4];
                LDSM4T(vf, vbase + (kt * 16 + (lane & 7) + ((lane >> 3) & 1) * 8) * 80
                           + nc * 32 + ((lane >> 4) & 1) * 16);
                MMA_F16(O[nc*2+0], pa[kt], vf[0], vf[1]);
                MMA_F16(O[nc*2+1], pa[kt], vf[2], vf[3]);
            }
        }
        #pragma unroll
        for (int t = 0; t < 4; t++) {
            int col = t * 8 + (lane & 3) * 2;
            *(uint32_t*)(ao16 + (size_t)gidx[i_lo] * C_ + head * HD + col) = pack_h2(O[t][0], O[t][1]);
            *(uint32_t*)(ao16 + (size_t)gidx[i_hi] * C_ + head * HD + col) = pack_h2(O[t][2], O[t][3]);
        }
    }
#undef ATTN_LOAD
}

// ---------------- 3x3 conv on r=24 channels, NHWC, pad 1 -------------------
__global__ __launch_bounds__(64) void conv3_kernel(const float* __restrict__ yin,
                                                   const float* __restrict__ w,
                                                   const float* __restrict__ bias,
                                                   __half* __restrict__ y16) {
    __shared__ float patch[100][RED_];
    __shared__ float wts[RED_ * RED_ * 9];
    int tid = threadIdx.x;
    int b = blockIdx.z;
    int th0 = blockIdx.y * 8, tw0 = blockIdx.x * 8;

    for (int d = tid; d < RED_ * RED_ * 9; d += 64) {
        int oc = d % RED_;
        int t2 = d / RED_;
        int kk = t2 % 9;
        int ic = t2 / 9;
        wts[d] = w[(oc * RED_ + ic) * 9 + kk];
    }
    for (int d = tid; d < 100 * RED_; d += 64) {
        int ic = d % RED_;
        int pos = d / RED_;
        int ph = pos / 10, pw = pos % 10;
        int hh = th0 + ph - 1, ww = tw0 + pw - 1;
        float v = 0.f;
        if (hh >= 0 && hh < H_ && ww >= 0 && ww < W_)
            v = yin[((size_t)b * L_ + hh * W_ + ww) * RED_ + ic];
        patch[pos][ic] = v;
    }
    __syncthreads();

    int py = tid >> 3, px = tid & 7;
    float acc[RED_];
    #pragma unroll
    for (int oc = 0; oc < RED_; oc++) acc[oc] = __ldg(bias + oc);
    for (int ic = 0; ic < RED_; ic++) {
        #pragma unroll
        for (int kk = 0; kk < 9; kk++) {
            int kh = kk / 3, kw = kk % 3;
            float pv = patch[(py + kh) * 10 + (px + kw)][ic];
            const float4* wp = (const float4*)&wts[(ic * 9 + kk) * RED_];
            #pragma unroll
            for (int o4 = 0; o4 < 6; o4++) {
                float4 wv = wp[o4];
                acc[o4*4+0] += wv.x * pv; acc[o4*4+1] += wv.y * pv;
                acc[o4*4+2] += wv.z * pv; acc[o4*4+3] += wv.w * pv;
            }
        }
    }
    size_t off = ((size_t)b * L_ + (th0 + py) * W_ + (tw0 + px)) * RED_;
    #pragma unroll
    for (int oc = 0; oc < RED_; oc += 2)
        *(uint32_t*)(y16 + off + oc) = pack_h2(acc[oc], acc[oc + 1]);
}

// ---------------- pool / SE ------------------------------------------------
__global__ __launch_bounds__(192) void pool_kernel(const __half* __restrict__ y16,
                                                   float* __restrict__ pool) {
    int base = blockIdx.x * 128;
    int b = base >> 16;
    int c = threadIdx.x;
    float acc = 0.f;
    for (int i = 0; i < 128; i++)
        acc += __half2float(y16[(size_t)(base + i) * C_ + c]);
    atomicAdd(&pool[b * C_ + c], acc);
}

__global__ __launch_bounds__(192) void se_kernel(const float* __restrict__ pool,
                                                 const float* __restrict__ fc1,
                                                 const float* __restrict__ fc2,
                                                 float* __restrict__ sbuf) {
    __shared__ float t[RED_];
    int tid = threadIdx.x;
    const float inv = 1.f / (float)L_;
    for (int b = 0; b < B_; b++) {
        if (tid < RED_) {
            float s = 0.f;
            for (int c = 0; c < C_; c++)
                s += pool[b * C_ + c] * inv * fc1[tid * C_ + c];
            t[tid] = fmaxf(s, 0.f);
        }
        __syncthreads();
        float s = 0.f;
        #pragma unroll
        for (int j = 0; j < RED_; j++) s += t[j] * fc2[tid * RED_ + j];
        sbuf[b * C_ + tid] = 1.f / (1.f + expf(-s));
        __syncthreads();
    }
}

// ---------------- launch ---------------------------------------------------
extern "C" void kernel_launch(void* const* d_in, const int* in_sizes, int n_in,
                              void* d_out, int out_size) {
    const float* x      = (const float*)d_in[0];
    const float* n1g    = (const float*)d_in[1];
    const float* n1b    = (const float*)d_in[2];
    const float* qkvw   = (const float*)d_in[3];
    const float* qkvb   = (const float*)d_in[4];
    const float* rpb    = (const float*)d_in[5];
    const float* projw  = (const float*)d_in[6];
    const float* projb  = (const float*)d_in[7];
    const float* n2g    = (const float*)d_in[8];
    const float* n2b    = (const float*)d_in[9];
    const float* fc1w   = (const float*)d_in[10];
    const float* fc1b   = (const float*)d_in[11];
    const float* fc2w   = (const float*)d_in[12];
    const float* fc2b   = (const float*)d_in[13];
    const float* c1w    = (const float*)d_in[14];
    const float* c1b    = (const float*)d_in[15];
    const float* c2w    = (const float*)d_in[16];
    const float* c2b    = (const float*)d_in[17];
    const float* c3w    = (const float*)d_in[18];
    const float* c3b    = (const float*)d_in[19];
    const float* sfc1   = (const float*)d_in[20];
    const float* sfc2   = (const float*)d_in[21];
    float* out = (float*)d_out;

    float *y1, *pool, *sbuf;
    cudaGetSymbolAddress((void**)&y1,   g_y1);
    cudaGetSymbolAddress((void**)&pool, g_pool);
    cudaGetSymbolAddress((void**)&sbuf, g_s);
    __half *qkv16, *xn16, *ao16, *x116, *x1n16, *hb16, *y216, *y16;
    __half *wq, *wp, *w1, *w2, *wc1, *wc3;
    cudaGetSymbolAddress((void**)&qkv16, g_qkv16);
    cudaGetSymbolAddress((void**)&xn16,  g_xn16);
    cudaGetSymbolAddress((void**)&ao16,  g_ao16);
    cudaGetSymbolAddress((void**)&x116,  g_x116);
    cudaGetSymbolAddress((void**)&x1n16, g_x1n16);
    cudaGetSymbolAddress((void**)&hb16,  g_hb16);
    cudaGetSymbolAddress((void**)&y216,  g_y216);
    cudaGetSymbolAddress((void**)&y16,   g_y16);
    cudaGetSymbolAddress((void**)&wq,  g_wq);
    cudaGetSymbolAddress((void**)&wp,  g_wp);
    cudaGetSymbolAddress((void**)&w1,  g_w1);
    cudaGetSymbolAddress((void**)&w2,  g_w2);
    cudaGetSymbolAddress((void**)&wc1, g_wc1);
    cudaGetSymbolAddress((void**)&wc3, g_wc3);

    cudaFuncSetAttribute(gemm_cp<0,0,0>, cudaFuncAttributeMaxDynamicSharedMemorySize, GEMM_SMEM_SZ);
    cudaFuncSetAttribute(gemm_cp<0,1,1>, cudaFuncAttributeMaxDynamicSharedMemorySize, GEMM_SMEM_SZ);
    cudaFuncSetAttribute(gemm_cp<1,1,1>, cudaFuncAttributeMaxDynamicSharedMemorySize, GEMM_SMEM_SZ);
    cudaFuncSetAttribute(gemm_cp<2,1,1>, cudaFuncAttributeMaxDynamicSharedMemorySize, GEMM_SMEM_SZ);
    cudaFuncSetAttribute(gemm_cp<3,1,0>, cudaFuncAttributeMaxDynamicSharedMemorySize, GEMM_SMEM_SZ);
    cudaFuncSetAttribute(gemm_cp<4,0,1>, cudaFuncAttributeMaxDynamicSharedMemorySize, GEMM_SMEM_SZ);
    cudaFuncSetAttribute(attn_mma_kernel, cudaFuncAttributeMaxDynamicSharedMemorySize, ATTN_SMEM);

    // 1) weight convert + pool zero (one launch)
    convert_all_kernel<<<(STOT+255)/256, 256>>>(qkvw, projw, fc1w, fc2w, c1w, c3w,
        wq, wp, w1, w2, wc1, wc3, pool);
    // 2) LN1 -> fp16 plane
    ln16_kernel<<<M_/8, 256>>>(x, n1g, n1b, xn16);
    // 3) QKV GEMM -> fp16 (clean)
    gemm_cp<0,1,1><<<dim3(6, M_/128), 256, GEMM_SMEM_SZ>>>(xn16, wq, qkvb, nullptr, nullptr, nullptr, nullptr, nullptr, qkv16, 3*C_, C_);
    // 4) LCE conv1x1 C->24 -> y1 fp32 (checked: N=24)
    gemm_cp<0,0,0><<<dim3(1, M_/128), 256, GEMM_SMEM_SZ>>>(xn16, wc1, c1b, nullptr, nullptr, nullptr, nullptr, y1, nullptr, RED_, C_);
    // 5) attention -> ao fp16
    attn_mma_kernel<<<NWIN, 256, ATTN_SMEM>>>(qkv16, rpb, ao16);
    // 6) proj + residual(x fp32) -> x1 fp16 (clean)
    gemm_cp<1,1,1><<<dim3(2, M_/128), 256, GEMM_SMEM_SZ>>>(ao16, wp, projb, x, nullptr, nullptr, nullptr, nullptr, x116, C_, C_);
    // 7) LN2 (fp16 in) -> fp16 plane
    ln16h_kernel<<<M_/8, 256>>>(x116, n2g, n2b, x1n16);
    // 8) fc1 + GELU -> hb fp16 (clean)
    gemm_cp<2,1,1><<<dim3(8, M_/128), 256, GEMM_SMEM_SZ>>>(x1n16, w1, fc1b, nullptr, nullptr, nullptr, nullptr, nullptr, hb16, HID_, C_);
    // 9) LCE conv3x3 -> y2 fp16
    conv3_kernel<<<dim3(W_/8, H_/8, B_), 64>>>(y1, c2w, c2b, y216);
    // 10) LCE conv1x1 24->192 + LeakyReLU -> y fp16 (checked: K=24)
    gemm_cp<3,1,0><<<dim3(2, M_/128), 256, GEMM_SMEM_SZ>>>(y216, wc3, c3b, nullptr, nullptr, nullptr, nullptr, nullptr, y16, C_, RED_);
    // 11) global avg pool (fp16 in) + SE gate
    pool_kernel<<<M_/128, 192>>>(y16, pool);
    se_kernel<<<1, 192>>>(pool, sfc1, sfc2, sbuf);
    // 12) fc2 + residual(x1 fp16) + SE-gated lc (y fp16) -> out fp32 (clean)
    gemm_cp<4,0,1><<<dim3(2, M_/128), 256, GEMM_SMEM_SZ>>>(hb16, w2, fc2b, nullptr, x116, y16, sbuf, out, nullptr, C_, HID_);
}

// round 17
// speedup vs baseline: 8.0840x; 1.0693x over previous
#include <cuda_runtime.h>
#include <cuda_fp16.h>
#include <math.h>
#include <stdint.h>

#define B_    2
#define H_    256
#define W_    256
#define C_    192
#define L_    (H_*W_)         // 65536
#define M_    (B_*L_)         // 131072
#define HID_  768
#define NH    6
#define HD    32
#define WS    8
#define SHIFT 4
#define NWIN  (B_*(H_/WS)*(W_/WS))  // 2048
#define RED_  24

// ---------------- scratch (device globals; no allocations) ----------------
__device__ float g_y1 [M_*RED_];
__device__ float g_pool[B_*C_];
__device__ float g_s  [B_*C_];
// fp16 activation planes
__device__ __half g_qkv16[(size_t)M_*3*C_];
__device__ __half g_xn16 [M_*C_];
__device__ __half g_ao16 [M_*C_];
__device__ __half g_x116 [M_*C_];
__device__ __half g_x1n16[M_*C_];
__device__ __half g_hb16 [(size_t)M_*HID_];
__device__ __half g_y216 [M_*RED_];
__device__ __half g_y16  [M_*C_];
// fp16 weights (single plane)
__device__ __half g_wq [3*C_*C_];
__device__ __half g_wp [C_*C_];
__device__ __half g_w1 [HID_*C_];
__device__ __half g_w2 [C_*HID_];
__device__ __half g_wc1[RED_*C_];
__device__ __half g_wc3[C_*RED_];

// ======================= helpers ===========================================
__device__ __forceinline__ uint32_t smem_to_u32(const void* p) {
    uint32_t a;
    asm("{ .reg .u64 t; cvta.to.shared.u64 t, %1; cvt.u32.u64 %0, t; }" : "=r"(a) : "l"(p));
    return a;
}
__device__ __forceinline__ uint32_t pack_h2(float x, float y) {
    __half2 h = __floats2half2_rn(x, y);
    return *reinterpret_cast<uint32_t*>(&h);
}
__device__ __forceinline__ float2 unpack_h2(uint32_t u) {
    __half2 h = *reinterpret_cast<__half2*>(&u);
    return __half22float2(h);
}
#define LDSM4(r, addr) \
    asm volatile("ldmatrix.sync.aligned.m8n8.x4.shared.b16 {%0,%1,%2,%3}, [%4];" \
        : "=r"((r)[0]), "=r"((r)[1]), "=r"((r)[2]), "=r"((r)[3]) : "r"(addr))
#define LDSM4T(r, addr) \
    asm volatile("ldmatrix.sync.aligned.m8n8.x4.trans.shared.b16 {%0,%1,%2,%3}, [%4];" \
        : "=r"((r)[0]), "=r"((r)[1]), "=r"((r)[2]), "=r"((r)[3]) : "r"(addr))
#define MMA_F16(d, a, b0, b1) \
    asm volatile("mma.sync.aligned.m16n8k16.row.col.f32.f16.f16.f32 " \
        "{%0,%1,%2,%3},{%4,%5,%6,%7},{%8,%9},{%0,%1,%2,%3};" \
        : "+f"((d)[0]), "+f"((d)[1]), "+f"((d)[2]), "+f"((d)[3]) \
        : "r"((a)[0]), "r"((a)[1]), "r"((a)[2]), "r"((a)[3]), "r"(b0), "r"(b1))
#define CP_ASYNC(dst, src, sz) \
    asm volatile("cp.async.cg.shared.global [%0], [%1], 16, %2;" \
        :: "r"(dst), "l"(src), "r"(sz))
#define CP_ASYNC16(dst, src) \
    asm volatile("cp.async.cg.shared.global [%0], [%1], 16;" \
        :: "r"(dst), "l"(src))
#define CP_COMMIT() asm volatile("cp.async.commit_group;" ::: "memory")

// ======================= fp16 mma.sync GEMM (128x96 tile, 4-stage) =========
// out[M,N] = epi(A @ W^T + bias); A and W single fp16 planes [rows][K].
// EPI: 0 none, 1 +res32, 2 exact GELU, 3 LeakyReLU(0.2),
//      4 +res16 + gate (out = v + res16 + yy16*s[b,col]). OUTP: 1 = fp16 out.
// CLEAN: 1 = K%32==0 && N%96==0.
#define STG_STRIDE 17920   // A 10240 | W 7680
#define W_OFF 10240
#define NSTG 4
#define GEMM_SMEM_SZ (NSTG*STG_STRIDE)   // 71680; 3 CTAs/SM = 210KB <= 228KB

template<int EPI, int OUTP, int CLEAN>
__device__ __forceinline__ void gemm_body(const __half* __restrict__ A16,
                                          const __half* __restrict__ Wt,
                                          const float* __restrict__ bias,
                                          const float* __restrict__ res32,
                                          const __half* __restrict__ res16,
                                          const __half* __restrict__ yy16,
                                          const float* __restrict__ sgate,
                                          float* __restrict__ out,
                                          __half* __restrict__ out16,
                                          int N, int K, char* smem) {
    const int tid  = threadIdx.x;
    const int lane = tid & 31;
    const int warp = tid >> 5;
    const int m0 = blockIdx.y * 128, n0 = blockIdx.x * 96;
    const int wm = (warp & 3) * 32, wn = (warp >> 2) * 48;
    const int nch = (K + 31) >> 5;
    const uint32_t sb = smem_to_u32(smem);

    const __half* gA0 = nullptr; const __half* gA1 = nullptr;
    const __half* gW0 = nullptr; const __half* gW1 = nullptr;
    uint32_t dA0 = 0, dA1 = 0, dW0 = 0, dW1 = 0;
    if (CLEAN) {
        int row = tid >> 2, seg = tid & 3;
        gA0 = A16 + (size_t)(m0 + row) * K + seg * 8;
        gA1 = gA0 + (size_t)64 * K;
        gW0 = Wt + (size_t)(n0 + row) * K + seg * 8;
        gW1 = gW0 + (size_t)64 * K;
        dA0 = sb + row * 80 + seg * 16;
        dA1 = dA0 + 64 * 80;
        dW0 = dA0 + W_OFF;
        dW1 = dW0 + 64 * 80;
    }

#define ISSUE_C(stg) do { \
    uint32_t so_ = (uint32_t)(stg) * STG_STRIDE; \
    CP_ASYNC16(dA0 + so_, gA0); \
    CP_ASYNC16(dA1 + so_, gA1); \
    CP_ASYNC16(dW0 + so_, gW0); \
    if (tid < 128) CP_ASYNC16(dW1 + so_, gW1); \
    CP_COMMIT(); \
    gA0 += 32; gA1 += 32; gW0 += 32; gW1 += 32; } while (0)

#define ISSUE(stg, c) do { \
    char* base_ = smem + (stg) * STG_STRIDE; \
    int k0_ = (c) * 32; \
    _Pragma("unroll") \
    for (int i = 0; i < 2; i++) { \
        int t = tid + i * 256; \
        int row = t >> 2, seg = t & 3; \
        int ke = k0_ + seg * 8; \
        int srcsz = (K - ke) * 2; \
        srcsz = srcsz < 0 ? 0 : (srcsz > 16 ? 16 : srcsz); \
        const __half* g = A16 + (size_t)(m0 + row) * K + (srcsz ? ke : 0); \
        uint32_t d = smem_to_u32(base_ + row * 80 + seg * 16); \
        CP_ASYNC(d, g, srcsz); \
    } \
    _Pragma("unroll") \
    for (int i = 0; i < 2; i++) { \
        int t = tid + i * 256; \
        if (t < 384) { \
            int row = t >> 2, seg = t & 3; \
            int ke = k0_ + seg * 8; \
            int srcsz = (K - ke) * 2; \
            srcsz = srcsz < 0 ? 0 : (srcsz > 16 ? 16 : srcsz); \
            if (n0 + row >= N) srcsz = 0; \
            int grow = (n0 + row < N) ? (n0 + row) : 0; \
            const __half* g = Wt + (size_t)grow * K + (srcsz ? ke : 0); \
            uint32_t d = smem_to_u32(base_ + W_OFF + row * 80 + seg * 16); \
            CP_ASYNC(d, g, srcsz); \
        } \
    } \
    CP_COMMIT(); } while (0)

    float acc[2][6][4];
    #pragma unroll
    for (int i = 0; i < 2; i++)
        #pragma unroll
        for (int j = 0; j < 6; j++)
            #pragma unroll
            for (int q = 0; q < 4; q++) acc[i][j][q] = 0.f;

    if (CLEAN) {
        ISSUE_C(0);
        if (nch > 1) ISSUE_C(1);
        if (nch > 2) ISSUE_C(2);
    } else {
        ISSUE(0, 0);
        if (nch > 1) ISSUE(1, 1);
        if (nch > 2) ISSUE(2, 2);
    }

    int sc = 0;
    for (int c = 0; c < nch; c++) {
        int rem = nch - 1 - c;
        if (rem >= 2)      asm volatile("cp.async.wait_group 2;" ::: "memory");
        else if (rem == 1) asm volatile("cp.async.wait_group 1;" ::: "memory");
        else               asm volatile("cp.async.wait_group 0;" ::: "memory");
        __syncthreads();
        char* base = smem + sc * STG_STRIDE;
        #pragma unroll
        for (int ks = 0; ks < 2; ks++) {
            uint32_t af[2][4], wf[3][4];
            #pragma unroll
            for (int mt = 0; mt < 2; mt++) {
                int row = wm + mt * 16 + (lane & 15);
                int colb = ks * 32 + ((lane >> 4) & 1) * 16;
                LDSM4(af[mt], smem_to_u32(base + row * 80 + colb));
            }
            #pragma unroll
            for (int np = 0; np < 3; np++) {
                int n = wn + np * 16 + (lane & 7) + ((lane >> 4) & 1) * 8;
                int colb = ks * 32 + ((lane >> 3) & 1) * 16;
                LDSM4(wf[np], smem_to_u32(base + W_OFF + n * 80 + colb));
            }
            #pragma unroll
            for (int mt = 0; mt < 2; mt++)
                #pragma unroll
                for (int nt = 0; nt < 6; nt++) {
                    int np = nt >> 1, h = (nt & 1) * 2;
                    MMA_F16(acc[mt][nt], af[mt], wf[np][h], wf[np][h+1]);
                }
        }
        if (c + 3 < nch) {
            int si = sc + 3; if (si >= NSTG) si -= NSTG;
            if (CLEAN) ISSUE_C(si);
            else       ISSUE(si, c + 3);
        }
        sc = (sc + 1 == NSTG) ? 0 : sc + 1;
    }

    // ---- epilogue ----
    #pragma unroll
    for (int mt = 0; mt < 2; mt++) {
        int r0 = m0 + wm + mt * 16 + (lane >> 2);
        #pragma unroll
        for (int nt = 0; nt < 6; nt++) {
            int col = n0 + wn + nt * 8 + (lane & 3) * 2;
            if (col < N) {
                float b0v = bias[col], b1v = bias[col + 1];
                #pragma unroll
                for (int rr = 0; rr < 2; rr++) {
                    int r = r0 + rr * 8;
                    float v0 = acc[mt][nt][rr*2+0] + b0v;
                    float v1 = acc[mt][nt][rr*2+1] + b1v;
                    if (EPI == 1) {
                        float2 rv = *(const float2*)(res32 + (size_t)r * N + col);
                        v0 += rv.x; v1 += rv.y;
                    }
                    if (EPI == 2) {
                        v0 = 0.5f * v0 * (1.f + erff(v0 * 0.70710678118654752f));
                        v1 = 0.5f * v1 * (1.f + erff(v1 * 0.70710678118654752f));
                    }
                    if (EPI == 3) {
                        v0 = (v0 >= 0.f) ? v0 : 0.2f * v0;
                        v1 = (v1 >= 0.f) ? v1 : 0.2f * v1;
                    }
                    if (EPI == 4) {
                        float2 rv = unpack_h2(*(const uint32_t*)(res16 + (size_t)r * N + col));
                        float2 yv = unpack_h2(*(const uint32_t*)(yy16 + (size_t)r * N + col));
                        const float* sb2 = sgate + (r >> 16) * C_;
                        v0 += rv.x + yv.x * sb2[col];
                        v1 += rv.y + yv.y * sb2[col + 1];
                    }
                    if (OUTP) {
                        *(uint32_t*)(out16 + (size_t)r * N + col) = pack_h2(v0, v1);
                    } else {
                        *(float2*)(out + (size_t)r * N + col) = make_float2(v0, v1);
                    }
                }
            }
        }
    }
#undef ISSUE
#undef ISSUE_C
}

template<int EPI, int OUTP, int CLEAN>
__global__ __launch_bounds__(256, 3) void gemm_cp(const __half* __restrict__ A16,
                                                  const __half* __restrict__ Wt,
                                                  const float* __restrict__ bias,
                                                  const float* __restrict__ res32,
                                                  const __half* __restrict__ res16,
                                                  const __half* __restrict__ yy16,
                                                  const float* __restrict__ sgate,
                                                  float* __restrict__ out,
                                                  __half* __restrict__ out16,
                                                  int N, int K) {
    extern __shared__ char smem[];
    gemm_body<EPI, OUTP, CLEAN>(A16, Wt, bias, res32, res16, yy16, sgate, out, out16, N, K, smem);
}

// ---------------- merged weight convert + pool zero ------------------------
#define S0 (3*C_*C_)
#define S1 (C_*C_)
#define S2 (HID_*C_)
#define S3 (C_*HID_)
#define S4 (RED_*C_)
#define S5 (C_*RED_)
#define STOT (S0+S1+S2+S3+S4+S5)
__global__ __launch_bounds__(256) void convert_all_kernel(
        const float* __restrict__ w0, const float* __restrict__ w1,
        const float* __restrict__ w2, const float* __restrict__ w3,
        const float* __restrict__ w4, const float* __restrict__ w5,
        __half* h0, __half* h1, __half* h2, __half* h3, __half* h4, __half* h5,
        float* pool) {
    int i = blockIdx.x * 256 + threadIdx.x;
    if (i < B_ * C_) pool[i] = 0.f;
    const float* s; __half* h; int off;
    if      (i < S0)                { s = w0; h = h0; off = i; }
    else if (i < S0+S1)             { s = w1; h = h1; off = i - S0; }
    else if (i < S0+S1+S2)          { s = w2; h = h2; off = i - S0-S1; }
    else if (i < S0+S1+S2+S3)       { s = w3; h = h3; off = i - S0-S1-S2; }
    else if (i < S0+S1+S2+S3+S4)    { s = w4; h = h4; off = i - S0-S1-S2-S3; }
    else if (i < STOT)              { s = w5; h = h5; off = i - S0-S1-S2-S3-S4; }
    else return;
    h[off] = __float2half_rn(s[off]);
}

// ---------------- LayerNorm fp32-in -> fp16 plane --------------------------
__global__ __launch_bounds__(256) void ln16_kernel(const float* __restrict__ x,
                                                   const float* __restrict__ g,
                                                   const float* __restrict__ b,
                                                   __half* __restrict__ o16) {
    int token = blockIdx.x * 8 + (threadIdx.x >> 5);
    int lane  = threadIdx.x & 31;
    const float* p = x + (size_t)token * C_;
    float v[6];
    float s = 0.f;
    #pragma unroll
    for (int j = 0; j < 6; j++) { v[j] = p[lane + 32*j]; s += v[j]; }
    #pragma unroll
    for (int o = 16; o > 0; o >>= 1) s += __shfl_xor_sync(0xffffffffu, s, o);
    float mean = s * (1.f / C_);
    float q = 0.f;
    #pragma unroll
    for (int j = 0; j < 6; j++) { float d = v[j] - mean; q += d * d; }
    #pragma unroll
    for (int o = 16; o > 0; o >>= 1) q += __shfl_xor_sync(0xffffffffu, q, o);
    float rstd = rsqrtf(q * (1.f / C_) + 1e-5f);
    #pragma unroll
    for (int j = 0; j < 6; j++) {
        int c = lane + 32*j;
        o16[(size_t)token * C_ + c] = __float2half_rn((v[j] - mean) * rstd * g[c] + b[c]);
    }
}

// ---------------- LayerNorm fp16-in -> fp16 plane --------------------------
__global__ __launch_bounds__(256) void ln16h_kernel(const __half* __restrict__ x,
                                                    const float* __restrict__ g,
                                                    const float* __restrict__ b,
                                                    __half* __restrict__ o16) {
    int token = blockIdx.x * 8 + (threadIdx.x >> 5);
    int lane  = threadIdx.x & 31;
    const __half* p = x + (size_t)token * C_;
    float v[6];
    float s = 0.f;
    #pragma unroll
    for (int j = 0; j < 6; j++) { v[j] = __half2float(p[lane + 32*j]); s += v[j]; }
    #pragma unroll
    for (int o = 16; o > 0; o >>= 1) s += __shfl_xor_sync(0xffffffffu, s, o);
    float mean = s * (1.f / C_);
    float q = 0.f;
    #pragma unroll
    for (int j = 0; j < 6; j++) { float d = v[j] - mean; q += d * d; }
    #pragma unroll
    for (int o = 16; o > 0; o >>= 1) q += __shfl_xor_sync(0xffffffffu, q, o);
    float rstd = rsqrtf(q * (1.f / C_) + 1e-5f);
    #pragma unroll
    for (int j = 0; j < 6; j++) {
        int c = lane + 32*j;
        o16[(size_t)token * C_ + c] = __float2half_rn((v[j] - mean) * rstd * g[c] + b[c]);
    }
}

// ============ Windowed attention: tensor-core, double-buffered head pairs ==
#define ATTN_SMEM (2*6*5120)    // 61440; 3 CTAs/SM = 180KB
__global__ __launch_bounds__(256, 3) void attn_mma_kernel(const __half* __restrict__ qkv16,
                                                          const float* __restrict__ rpb,
                                                          __half* __restrict__ ao16) {
    extern __shared__ char dsmem[];
    __shared__ float  srpb[225 * NH];
    __shared__ int    gidx[64];
    __shared__ int    rid [64];

    const int tid  = threadIdx.x;
    const int lane = tid & 31;
    const int warp = tid >> 5;
    const int wid  = blockIdx.x;
    const int bb   = wid >> 10;
    const int wib  = wid & 1023;
    const int wh   = wib >> 5, ww = wib & 31;

    if (tid < 64) {
        int ih = tid >> 3, iw = tid & 7;
        int h = wh * 8 + ih, w = ww * 8 + iw;
        gidx[tid] = bb * L_ + ((h + SHIFT) & (H_ - 1)) * W_ + ((w + SHIFT) & (W_ - 1));
        int rh = (h < H_ - WS) ? 0 : ((h < H_ - SHIFT) ? 1 : 2);
        int rw = (w < W_ - WS) ? 0 : ((w < W_ - SHIFT) ? 1 : 2);
        rid[tid] = rh * 3 + rw;
    }
    for (int i = tid; i < 225 * NH; i += 256) srpb[i] = rpb[i];
    __syncthreads();

    const uint32_t pb = smem_to_u32(dsmem);
    const int hp   = warp >> 2;
    const int r0   = (warp & 3) * 16;
    const int i_lo = r0 + (lane >> 2);
    const int i_hi = i_lo + 8;
    const int ihlo = i_lo >> 3, iwlo = i_lo & 7;
    const int ihhi = i_hi >> 3, iwhi = i_hi & 7;
    const float SCALE = 0.17677669529663687f;

#define ATTN_LOAD(buf, h0v) do { \
    _Pragma("unroll") \
    for (int i = 0; i < 6; i++) { \
        int t   = tid + i * 256; \
        int rowid = t >> 2, seg = t & 3; \
        int p   = rowid >> 6, tok = rowid & 63; \
        int mat = p % 3, php = p / 3; \
        const __half* g = qkv16 + (size_t)gidx[tok] * (3*C_) + mat * C_ + ((h0v) + php) * HD + seg * 8; \
        uint32_t d = pb + (buf) * 30720 + p * 5120 + tok * 80 + seg * 16; \
        CP_ASYNC16(d, g); \
    } \
    CP_COMMIT(); } while (0)

    ATTN_LOAD(0, 0);

    for (int it = 0; it < 3; ++it) {
        const int buf = it & 1;
        const int h0 = it * 2;
        asm volatile("cp.async.wait_group 0;" ::: "memory");
        __syncthreads();
        if (it + 1 < 3) ATTN_LOAD(buf ^ 1, h0 + 2);

        const uint32_t qbase = pb + buf * 30720 + hp * 15360;
        const uint32_t kbase = qbase + 5120;
        const uint32_t vbase = qbase + 10240;
        const int head = h0 + hp;

        float S[8][4];
        #pragma unroll
        for (int t = 0; t < 8; t++)
            #pragma unroll
            for (int q = 0; q < 4; q++) S[t][q] = 0.f;
        #pragma unroll
        for (int ks = 0; ks < 2; ks++) {
            uint32_t qf[4];
            LDSM4(qf, qbase + (r0 + (lane & 15)) * 80 + ks * 32 + ((lane >> 4) & 1) * 16);
            #pragma unroll
            for (int np = 0; np < 4; np++) {
                uint32_t kf[4];
                LDSM4(kf, kbase + ((lane & 7) + ((lane >> 4) & 1) * 8 + np * 16) * 80
                          + ks * 32 + ((lane >> 3) & 1) * 16);
                MMA_F16(S[np*2+0], qf, kf[0], kf[1]);
                MMA_F16(S[np*2+1], qf, kf[2], kf[3]);
            }
        }
        const int ridlo = rid[i_lo], ridhi = rid[i_hi];
        float mlo = -1e30f, mhi = -1e30f;
        #pragma unroll
        for (int t = 0; t < 8; t++) {
            int jc = (t >> 1) * 16 + (t & 1) * 8 + (lane & 3) * 2;
            #pragma unroll
            for (int e = 0; e < 2; e++) {
                int j = jc + e;
                int jh = j >> 3, jw = j & 7;
                float blo = srpb[((ihlo - jh + 7) * 15 + (iwlo - jw + 7)) * NH + head];
                float bhi = srpb[((ihhi - jh + 7) * 15 + (iwhi - jw + 7)) * NH + head];
                int rj = rid[j];
                float v0 = S[t][e]     * SCALE + blo + ((ridlo != rj) ? -100.f : 0.f);
                float v1 = S[t][e + 2] * SCALE + bhi + ((ridhi != rj) ? -100.f : 0.f);
                S[t][e] = v0; S[t][e + 2] = v1;
                mlo = fmaxf(mlo, v0); mhi = fmaxf(mhi, v1);
            }
        }
        mlo = fmaxf(mlo, __shfl_xor_sync(0xffffffffu, mlo, 1));
        mlo = fmaxf(mlo, __shfl_xor_sync(0xffffffffu, mlo, 2));
        mhi = fmaxf(mhi, __shfl_xor_sync(0xffffffffu, mhi, 1));
        mhi = fmaxf(mhi, __shfl_xor_sync(0xffffffffu, mhi, 2));
        float slo = 0.f, shi = 0.f;
        #pragma unroll
        for (int t = 0; t < 8; t++) {
            #pragma unroll
            for (int e = 0; e < 2; e++) {
                float v0 = __expf(S[t][e] - mlo);
                float v1 = __expf(S[t][e + 2] - mhi);
                S[t][e] = v0; S[t][e + 2] = v1;
                slo += v0; shi += v1;
            }
        }
        slo += __shfl_xor_sync(0xffffffffu, slo, 1);
        slo += __shfl_xor_sync(0xffffffffu, slo, 2);
        shi += __shfl_xor_sync(0xffffffffu, shi, 1);
        shi += __shfl_xor_sync(0xffffffffu, shi, 2);
        float ilo = 1.f / slo, ihi2 = 1.f / shi;
        uint32_t pa[4][4];
        #pragma unroll
        for (int kt = 0; kt < 4; kt++) {
            pa[kt][0] = pack_h2(S[kt*2][0] * ilo,  S[kt*2][1] * ilo);
            pa[kt][1] = pack_h2(S[kt*2][2] * ihi2, S[kt*2][3] * ihi2);
            pa[kt][2] = pack_h2(S[kt*2+1][0] * ilo,  S[kt*2+1][1] * ilo);
            pa[kt][3] = pack_h2(S[kt*2+1][2] * ihi2, S[kt*2+1][3] * ihi2);
        }
        float O[4][4];
        #pragma unroll
        for (int t = 0; t < 4; t++)
            #pragma unroll
            for (int q = 0; q < 4; q++) O[t][q] = 0.f;
        #pragma unroll
        for (int kt = 0; kt < 4; kt++) {
            #pragma unroll
            for (int nc = 0; nc < 2; nc++) {
                uint32_t vf[4];
                LDSM4T(vf, vbase + (kt * 16 + (lane & 7) + ((lane >> 3) & 1) * 8) * 80
                           + nc * 32 + ((lane >> 4) & 1) * 16);
                MMA_F16(O[nc*2+0], pa[kt], vf[0], vf[1]);
                MMA_F16(O[nc*2+1], pa[kt], vf[2], vf[3]);
            }
        }
        #pragma unroll
        for (int t = 0; t < 4; t++) {
            int col = t * 8 + (lane & 3) * 2;
            *(uint32_t*)(ao16 + (size_t)gidx[i_lo] * C_ + head * HD + col) = pack_h2(O[t][0], O[t][1]);
            *(uint32_t*)(ao16 + (size_t)gidx[i_hi] * C_ + head * HD + col) = pack_h2(O[t][2], O[t][3]);
        }
    }
#undef ATTN_LOAD
}

// ---------------- 3x3 conv on r=24 channels, NHWC, pad 1 -------------------
__global__ __launch_bounds__(64) void conv3_kernel(const float* __restrict__ yin,
                                                   const float* __restrict__ w,
                                                   const float* __restrict__ bias,
                                                   __half* __restrict__ y16) {
    __shared__ float patch[100][RED_];
    __shared__ float wts[RED_ * RED_ * 9];
    int tid = threadIdx.x;
    int b = blockIdx.z;
    int th0 = blockIdx.y * 8, tw0 = blockIdx.x * 8;

    for (int d = tid; d < RED_ * RED_ * 9; d += 64) {
        int oc = d % RED_;
        int t2 = d / RED_;
        int kk = t2 % 9;
        int ic = t2 / 9;
        wts[d] = w[(oc * RED_ + ic) * 9 + kk];
    }
    for (int d = tid; d < 100 * RED_; d += 64) {
        int ic = d % RED_;
        int pos = d / RED_;
        int ph = pos / 10, pw = pos % 10;
        int hh = th0 + ph - 1, ww = tw0 + pw - 1;
        float v = 0.f;
        if (hh >= 0 && hh < H_ && ww >= 0 && ww < W_)
            v = yin[((size_t)b * L_ + hh * W_ + ww) * RED_ + ic];
        patch[pos][ic] = v;
    }
    __syncthreads();

    int py = tid >> 3, px = tid & 7;
    float acc[RED_];
    #pragma unroll
    for (int oc = 0; oc < RED_; oc++) acc[oc] = __ldg(bias + oc);
    for (int ic = 0; ic < RED_; ic++) {
        #pragma unroll
        for (int kk = 0; kk < 9; kk++) {
            int kh = kk / 3, kw = kk % 3;
            float pv = patch[(py + kh) * 10 + (px + kw)][ic];
            const float4* wp = (const float4*)&wts[(ic * 9 + kk) * RED_];
            #pragma unroll
            for (int o4 = 0; o4 < 6; o4++) {
                float4 wv = wp[o4];
                acc[o4*4+0] += wv.x * pv; acc[o4*4+1] += wv.y * pv;
                acc[o4*4+2] += wv.z * pv; acc[o4*4+3] += wv.w * pv;
            }
        }
    }
    size_t off = ((size_t)b * L_ + (th0 + py) * W_ + (tw0 + px)) * RED_;
    #pragma unroll
    for (int oc = 0; oc < RED_; oc += 2)
        *(uint32_t*)(y16 + off + oc) = pack_h2(acc[oc], acc[oc + 1]);
}

// ---------------- pool / SE ------------------------------------------------
__global__ __launch_bounds__(192) void pool_kernel(const __half* __restrict__ y16,
                                                   float* __restrict__ pool) {
    int base = blockIdx.x * 128;
    int b = base >> 16;
    int c = threadIdx.x;
    float acc = 0.f;
    for (int i = 0; i < 128; i++)
        acc += __half2float(y16[(size_t)(base + i) * C_ + c]);
    atomicAdd(&pool[b * C_ + c], acc);
}

__global__ __launch_bounds__(192) void se_kernel(const float* __restrict__ pool,
                                                 const float* __restrict__ fc1,
                                                 const float* __restrict__ fc2,
                                                 float* __restrict__ sbuf) {
    __shared__ float t[RED_];
    int tid = threadIdx.x;
    const float inv = 1.f / (float)L_;
    for (int b = 0; b < B_; b++) {
        if (tid < RED_) {
            float s = 0.f;
            for (int c = 0; c < C_; c++)
                s += pool[b * C_ + c] * inv * fc1[tid * C_ + c];
            t[tid] = fmaxf(s, 0.f);
        }
        __syncthreads();
        float s = 0.f;
        #pragma unroll
        for (int j = 0; j < RED_; j++) s += t[j] * fc2[tid * RED_ + j];
        sbuf[b * C_ + tid] = 1.f / (1.f + expf(-s));
        __syncthreads();
    }
}

// ---------------- launch ---------------------------------------------------
extern "C" void kernel_launch(void* const* d_in, const int* in_sizes, int n_in,
                              void* d_out, int out_size) {
    const float* x      = (const float*)d_in[0];
    const float* n1g    = (const float*)d_in[1];
    const float* n1b    = (const float*)d_in[2];
    const float* qkvw   = (const float*)d_in[3];
    const float* qkvb   = (const float*)d_in[4];
    const float* rpb    = (const float*)d_in[5];
    const float* projw  = (const float*)d_in[6];
    const float* projb  = (const float*)d_in[7];
    const float* n2g    = (const float*)d_in[8];
    const float* n2b    = (const float*)d_in[9];
    const float* fc1w   = (const float*)d_in[10];
    const float* fc1b   = (const float*)d_in[11];
    const float* fc2w   = (const float*)d_in[12];
    const float* fc2b   = (const float*)d_in[13];
    const float* c1w    = (const float*)d_in[14];
    const float* c1b    = (const float*)d_in[15];
    const float* c2w    = (const float*)d_in[16];
    const float* c2b    = (const float*)d_in[17];
    const float* c3w    = (const float*)d_in[18];
    const float* c3b    = (const float*)d_in[19];
    const float* sfc1   = (const float*)d_in[20];
    const float* sfc2   = (const float*)d_in[21];
    float* out = (float*)d_out;

    float *y1, *pool, *sbuf;
    cudaGetSymbolAddress((void**)&y1,   g_y1);
    cudaGetSymbolAddress((void**)&pool, g_pool);
    cudaGetSymbolAddress((void**)&sbuf, g_s);
    __half *qkv16, *xn16, *ao16, *x116, *x1n16, *hb16, *y216, *y16;
    __half *wq, *wp, *w1, *w2, *wc1, *wc3;
    cudaGetSymbolAddress((void**)&qkv16, g_qkv16);
    cudaGetSymbolAddress((void**)&xn16,  g_xn16);
    cudaGetSymbolAddress((void**)&ao16,  g_ao16);
    cudaGetSymbolAddress((void**)&x116,  g_x116);
    cudaGetSymbolAddress((void**)&x1n16, g_x1n16);
    cudaGetSymbolAddress((void**)&hb16,  g_hb16);
    cudaGetSymbolAddress((void**)&y216,  g_y216);
    cudaGetSymbolAddress((void**)&y16,   g_y16);
    cudaGetSymbolAddress((void**)&wq,  g_wq);
    cudaGetSymbolAddress((void**)&wp,  g_wp);
    cudaGetSymbolAddress((void**)&w1,  g_w1);
    cudaGetSymbolAddress((void**)&w2,  g_w2);
    cudaGetSymbolAddress((void**)&wc1, g_wc1);
    cudaGetSymbolAddress((void**)&wc3, g_wc3);

    cudaFuncSetAttribute(gemm_cp<0,0,0>, cudaFuncAttributeMaxDynamicSharedMemorySize, GEMM_SMEM_SZ);
    cudaFuncSetAttribute(gemm_cp<0,1,1>, cudaFuncAttributeMaxDynamicSharedMemorySize, GEMM_SMEM_SZ);
    cudaFuncSetAttribute(gemm_cp<1,1,1>, cudaFuncAttributeMaxDynamicSharedMemorySize, GEMM_SMEM_SZ);
    cudaFuncSetAttribute(gemm_cp<2,1,1>, cudaFuncAttributeMaxDynamicSharedMemorySize, GEMM_SMEM_SZ);
    cudaFuncSetAttribute(gemm_cp<3,1,0>, cudaFuncAttributeMaxDynamicSharedMemorySize, GEMM_SMEM_SZ);
    cudaFuncSetAttribute(gemm_cp<4,0,1>, cudaFuncAttributeMaxDynamicSharedMemorySize, GEMM_SMEM_SZ);
    cudaFuncSetAttribute(attn_mma_kernel, cudaFuncAttributeMaxDynamicSharedMemorySize, ATTN_SMEM);

    // Fresh fork/join stream + events per call (leaked intentionally; called
    // only for correctness + capture, never per-replay; no device memory).
    cudaStream_t s_lce;
    cudaEvent_t ev_fork, ev_join;
    cudaStreamCreateWithFlags(&s_lce, cudaStreamNonBlocking);
    cudaEventCreateWithFlags(&ev_fork, cudaEventDisableTiming);
    cudaEventCreateWithFlags(&ev_join, cudaEventDisableTiming);

    // ---- main stream (0): trunk ----
    convert_all_kernel<<<(STOT+255)/256, 256>>>(qkvw, projw, fc1w, fc2w, c1w, c3w,
        wq, wp, w1, w2, wc1, wc3, pool);
    ln16_kernel<<<M_/8, 256>>>(x, n1g, n1b, xn16);
    cudaEventRecord(ev_fork, 0);

    // ---- LCE branch on s_lce (independent until fc2) ----
    cudaStreamWaitEvent(s_lce, ev_fork, 0);
    gemm_cp<0,0,0><<<dim3(1, M_/128), 256, GEMM_SMEM_SZ, s_lce>>>(xn16, wc1, c1b, nullptr, nullptr, nullptr, nullptr, y1, nullptr, RED_, C_);
    conv3_kernel<<<dim3(W_/8, H_/8, B_), 64, 0, s_lce>>>(y1, c2w, c2b, y216);
    gemm_cp<3,1,0><<<dim3(2, M_/128), 256, GEMM_SMEM_SZ, s_lce>>>(y216, wc3, c3b, nullptr, nullptr, nullptr, nullptr, nullptr, y16, C_, RED_);
    pool_kernel<<<M_/128, 192, 0, s_lce>>>(y16, pool);
    se_kernel<<<1, 192, 0, s_lce>>>(pool, sfc1, sfc2, sbuf);
    cudaEventRecord(ev_join, s_lce);

    // ---- trunk continues on stream 0 ----
    gemm_cp<0,1,1><<<dim3(6, M_/128), 256, GEMM_SMEM_SZ>>>(xn16, wq, qkvb, nullptr, nullptr, nullptr, nullptr, nullptr, qkv16, 3*C_, C_);
    attn_mma_kernel<<<NWIN, 256, ATTN_SMEM>>>(qkv16, rpb, ao16);
    gemm_cp<1,1,1><<<dim3(2, M_/128), 256, GEMM_SMEM_SZ>>>(ao16, wp, projb, x, nullptr, nullptr, nullptr, nullptr, x116, C_, C_);
    ln16h_kernel<<<M_/8, 256>>>(x116, n2g, n2b, x1n16);
    gemm_cp<2,1,1><<<dim3(8, M_/128), 256, GEMM_SMEM_SZ>>>(x1n16, w1, fc1b, nullptr, nullptr, nullptr, nullptr, nullptr, hb16, HID_, C_);

    // ---- join: fc2 needs hb (trunk) + x1 (trunk) + y16/sbuf (LCE) ----
    cudaStreamWaitEvent(0, ev_join, 0);
    gemm_cp<4,0,1><<<dim3(2, M_/128), 256, GEMM_SMEM_SZ>>>(hb16, w2, fc2b, nullptr, x116, y16, sbuf, out, nullptr, C_, HID_);
}